// round 6
// baseline (speedup 1.0000x reference)
#include <cuda_runtime.h>
#include <math.h>

#define BATCH 16384
#define NINP  768
#define NHID  360
#define NBLK  6
#define BSZ   60

// ---------------- scratch ----------------
__device__ float g_kv[BATCH*496];      // [b][0:256]=Kproj (4 heads x64), [256:496]=Vproj (4 heads x60)
__device__ float g_alpha[BATCH*24];    // [b][k*4+h] = sigma(score)
__device__ float g_mask[BATCH*6];      // 0/1
__device__ float g_hxn[BATCH*360];     // LSTM hx_new (pre comm-attn)
__device__ float g_qkvc[BATCH*2304];   // [b][k*384 + {0:q,128:k,256:v}]
__device__ float g_raw[BATCH*768];     // [b][i*128 + h*32 + c]

__device__ __forceinline__ float sigf(float x){ return 1.f/(1.f+expf(-x)); }

__device__ __forceinline__ float to_tf32(float x){
    unsigned t;
    asm("cvt.rna.tf32.f32 %0, %1;" : "=r"(t) : "f"(x));
    return __uint_as_float(t);
}

#define LOAD_FRAG(f, p) do { \
    *(float4*)&f[0] = *(const float4*)(p); \
    *(float4*)&f[4] = *(const float4*)((p)+4); } while(0)

#define FMA8x8(acc, af, bf) do { \
  _Pragma("unroll") for (int i_ = 0; i_ < 8; i_++) \
    _Pragma("unroll") for (int j_ = 0; j_ < 8; j_++) \
      acc[i_*8+j_] = fmaf(af[i_], bf[j_], acc[i_*8+j_]); } while(0)

// ---------------- K1: KV projection  [B,768] @ [768,496] ----------------
__global__ __launch_bounds__(256, 1) void k1_kvproj(const float* __restrict__ inp,
                          const float* __restrict__ Wk1,
                          const float* __restrict__ Wv1)
{
    __shared__ __align__(16) float As[32*132];
    __shared__ __align__(16) float Bs[32*132];
    int tid = threadIdx.x;
    int tx = tid & 15, ty = tid >> 4;
    int m0 = blockIdx.y * 128;
    int n0 = blockIdx.x * 128;
    float acc[64];
#pragma unroll
    for (int i = 0; i < 64; i++) acc[i] = 0.f;

    for (int k0 = 0; k0 < 768; k0 += 32) {
        for (int e = tid; e < 128*32; e += 256) {
            int m = e >> 5, d = e & 31;
            As[d*132 + m] = inp[(size_t)(m0+m)*768 + k0 + d];
        }
        for (int e = tid; e < 32*128; e += 256) {
            int d = e >> 7, n = e & 127;
            int ng = n0 + n;
            float v = 0.f;
            if (ng < 256)       v = Wk1[(size_t)(k0+d)*256 + ng];
            else if (ng < 496)  v = Wv1[(size_t)(k0+d)*240 + (ng-256)];
            Bs[d*132 + n] = v;
        }
        __syncthreads();
#pragma unroll
        for (int kk = 0; kk < 32; kk++) {
            float af[8], bf[8];
            LOAD_FRAG(af, &As[kk*132 + ty*8]);
            LOAD_FRAG(bf, &Bs[kk*132 + tx*8]);
            FMA8x8(acc, af, bf);
        }
        __syncthreads();
    }
#pragma unroll
    for (int i = 0; i < 8; i++) {
        int m = m0 + ty*8 + i;
#pragma unroll
        for (int j = 0; j < 8; j++) {
            int n = n0 + tx*8 + j;
            if (n < 496) g_kv[(size_t)m*496 + n] = acc[i*8+j];
        }
    }
}

// ---------------- K2: Q projection (all 4 heads) + fused score -> alpha ----------------
__global__ __launch_bounds__(256, 1) void k2_qalpha(const float* __restrict__ hx,
                          const float* __restrict__ Wq)
{
    __shared__ __align__(16) float Xs[20*68];
    __shared__ __align__(16) float Ws[20*260];
    int tid = threadIdx.x;            // 256
    int tx = tid & 31, ty = tid >> 5; // ty 0..7 (rows), tx 0..31 (cols)
    int m0 = blockIdx.x * 64;
    int k  = blockIdx.y;

    float acc[64];
#pragma unroll
    for (int i = 0; i < 64; i++) acc[i] = 0.f;

    for (int d0 = 0; d0 < 60; d0 += 20) {
        for (int e = tid; e < 64*20; e += 256) {
            int m = e / 20, dd = e % 20;
            Xs[dd*68 + m] = hx[(size_t)(m0+m)*360 + k*60 + d0 + dd];
        }
        for (int e = tid; e < 20*256; e += 256) {
            int dd = e >> 8, n = e & 255;
            Ws[dd*260 + n] = Wq[(size_t)k*15360 + (d0+dd)*256 + n];
        }
        __syncthreads();
#pragma unroll
        for (int kk = 0; kk < 20; kk++) {
            float af[8], bf[8];
            LOAD_FRAG(af, &Xs[kk*68 + ty*8]);
            LOAD_FRAG(bf, &Ws[kk*260 + tx*8]);
            FMA8x8(acc, af, bf);
        }
        __syncthreads();
    }
    int h = tx >> 3, lane8 = tx & 7;
#pragma unroll
    for (int i = 0; i < 8; i++) {
        int gm = m0 + ty*8 + i;
        const float* kp = &g_kv[(size_t)gm*496 + h*64 + lane8*8];
        float s = 0.f;
#pragma unroll
        for (int j = 0; j < 8; j++) s += acc[i*8+j] * kp[j];
        s += __shfl_xor_sync(0xffffffffu, s, 1);
        s += __shfl_xor_sync(0xffffffffu, s, 2);
        s += __shfl_xor_sync(0xffffffffu, s, 4);
        if (lane8 == 0) g_alpha[(size_t)gm*24 + k*4 + h] = sigf(0.125f*s);
    }
}

// ---------------- K3: top-2 null mask ----------------
__global__ void k3_mask()
{
    int b = blockIdx.x*256 + threadIdx.x;
    float4 a0 = *(const float4*)&g_alpha[(size_t)b*24 + 0];
    float4 a1 = *(const float4*)&g_alpha[(size_t)b*24 + 4];
    float4 a2 = *(const float4*)&g_alpha[(size_t)b*24 + 8];
    float4 a3 = *(const float4*)&g_alpha[(size_t)b*24 + 12];
    float4 a4 = *(const float4*)&g_alpha[(size_t)b*24 + 16];
    float4 a5 = *(const float4*)&g_alpha[(size_t)b*24 + 20];
    float nul[6];
    nul[0] = 1.f - 0.25f*(a0.x+a0.y+a0.z+a0.w);
    nul[1] = 1.f - 0.25f*(a1.x+a1.y+a1.z+a1.w);
    nul[2] = 1.f - 0.25f*(a2.x+a2.y+a2.z+a2.w);
    nul[3] = 1.f - 0.25f*(a3.x+a3.y+a3.z+a3.w);
    nul[4] = 1.f - 0.25f*(a4.x+a4.y+a4.z+a4.w);
    nul[5] = 1.f - 0.25f*(a5.x+a5.y+a5.z+a5.w);
    int i1 = 0; float m1 = nul[0];
#pragma unroll
    for (int k = 1; k < 6; k++) if (nul[k] > m1) { m1 = nul[k]; i1 = k; }
    int i2 = -1; float m2 = -1e30f;
#pragma unroll
    for (int k = 0; k < 6; k++) if (k != i1 && nul[k] > m2) { m2 = nul[k]; i2 = k; }
#pragma unroll
    for (int k = 0; k < 6; k++)
        g_mask[(size_t)b*6 + k] = (k == i1 || k == i2) ? 0.f : 1.f;
}

// ---------------- K4: tf32 mma gates GEMM + LSTM pointwise + cx_out ----------------
// CTA: 256 thr (8 warps, 2M x 4N). Tile M=64, N=256 (c = r*4+g, cols>=240 pad), K=304.
// Warp tile 32x64 (Mf=2, Nf=8). Epilogue: shfl.xor(1) assembles gate quads.
__global__ __launch_bounds__(256, 2) void k4_gates_lstm(const float* __restrict__ hx,
                              const float* __restrict__ cx,
                              const float* __restrict__ W_ih,
                              const float* __restrict__ W_hh,
                              const float* __restrict__ b_ih,
                              const float* __restrict__ b_hh,
                              float* __restrict__ out_cx)
{
    __shared__ __align__(16) float As[64*20];     // [m][d] stride 20
    __shared__ __align__(16) float Bs[16*264];    // [d][c] stride 264
    __shared__ float sbias[240];
    __shared__ float s_alpha[256];
    int tid = threadIdx.x;            // 256
    int lane = tid & 31, warp = tid >> 5;
    int warp_m = warp >> 2, warp_n = warp & 3;
    int group = lane >> 2, tcol = lane & 3;
    int m0 = blockIdx.x * 64;
    int k  = blockIdx.y;

    if (tid < 240) {
        int c = tid, r = c >> 2, g = c & 3;
        int rowW = g*360 + k*60 + r;
        sbias[c] = b_ih[rowW] + b_hh[rowW];
    }
    { // 256 alpha entries, 1 per thread
        int e = tid;
        s_alpha[e] = g_alpha[(size_t)(m0 + (e >> 2))*24 + k*4 + (e & 3)];
    }

    float c_acc[2][8][4];
#pragma unroll
    for (int a = 0; a < 2; a++)
#pragma unroll
        for (int b = 0; b < 8; b++)
#pragma unroll
            for (int d = 0; d < 4; d++) c_acc[a][b][d] = 0.f;

    for (int ch = 0; ch < 19; ch++) {
        int d0 = ch*16;
        __syncthreads();
        // A tile: 64x16, 4 elems/thread
#pragma unroll
        for (int e = tid; e < 64*16; e += 256) {
            int m = e >> 4, dd = e & 15;
            int d = d0 + dd;
            float v;
            if (d < 240)      v = s_alpha[m*4 + d/60] * g_kv[(size_t)(m0+m)*496 + 256 + d];
            else if (d < 300) v = hx[(size_t)(m0+m)*360 + k*60 + (d-240)];
            else              v = 0.f;
            As[m*20 + dd] = to_tf32(v);
        }
        // B tile: 16x256, 16 elems/thread
#pragma unroll
        for (int e = tid; e < 16*256; e += 256) {
            int dd = e >> 8, cc = e & 255;
            int d = d0 + dd;
            float v = 0.f;
            int r = cc >> 2, g = cc & 3;
            if (r < 60) {
                int rowW = g*360 + k*60 + r;
                if (d < 240)      v = W_ih[(size_t)rowW*1440 + k*240 + d];
                else if (d < 300) v = W_hh[(size_t)rowW*360 + k*60 + (d-240)];
            }
            Bs[dd*264 + cc] = to_tf32(v);
        }
        __syncthreads();
#pragma unroll
        for (int ks = 0; ks < 2; ks++) {
            int kb = ks*8;
            unsigned a_frag[2][4];
#pragma unroll
            for (int mf = 0; mf < 2; mf++) {
                int row0 = warp_m*32 + mf*16 + group;
                a_frag[mf][0] = __float_as_uint(As[row0*20 + kb + tcol]);
                a_frag[mf][1] = __float_as_uint(As[(row0+8)*20 + kb + tcol]);
                a_frag[mf][2] = __float_as_uint(As[row0*20 + kb + tcol + 4]);
                a_frag[mf][3] = __float_as_uint(As[(row0+8)*20 + kb + tcol + 4]);
            }
#pragma unroll
            for (int nf = 0; nf < 8; nf++) {
                int coln = warp_n*64 + nf*8 + group;
                unsigned b0 = __float_as_uint(Bs[(kb + tcol)*264 + coln]);
                unsigned b1 = __float_as_uint(Bs[(kb + tcol + 4)*264 + coln]);
#pragma unroll
                for (int mf = 0; mf < 2; mf++) {
                    asm volatile(
                        "mma.sync.aligned.m16n8k8.row.col.f32.tf32.tf32.f32 "
                        "{%0,%1,%2,%3}, {%4,%5,%6,%7}, {%8,%9}, {%0,%1,%2,%3};"
                        : "+f"(c_acc[mf][nf][0]), "+f"(c_acc[mf][nf][1]),
                          "+f"(c_acc[mf][nf][2]), "+f"(c_acc[mf][nf][3])
                        : "r"(a_frag[mf][0]), "r"(a_frag[mf][1]),
                          "r"(a_frag[mf][2]), "r"(a_frag[mf][3]),
                          "r"(b0), "r"(b1));
                }
            }
        }
    }
    // epilogue: shfl.xor(1) pairs lanes holding gates {0,1} and {2,3} of same r
#pragma unroll
    for (int mf = 0; mf < 2; mf++) {
#pragma unroll
        for (int nf = 0; nf < 8; nf++) {
            float x0 = c_acc[mf][nf][0], x1 = c_acc[mf][nf][1];
            float x2 = c_acc[mf][nf][2], x3 = c_acc[mf][nf][3];
            float y0 = __shfl_xor_sync(0xffffffffu, x0, 1);
            float y1 = __shfl_xor_sync(0xffffffffu, x1, 1);
            float y2 = __shfl_xor_sync(0xffffffffu, x2, 1);
            float y3 = __shfl_xor_sync(0xffffffffu, x3, 1);
            int r = warp_n*16 + nf*2 + (tcol >> 1);
            if (r >= 60) continue;
            float gi, gf, gg, go; int rowloc;
            if ((tcol & 1) == 0) {
                gi = x0; gf = x1; gg = y0; go = y1;
                rowloc = warp_m*32 + mf*16 + group;
            } else {
                gi = y2; gf = y3; gg = x2; go = x3;
                rowloc = warp_m*32 + mf*16 + group + 8;
            }
            gi += sbias[r*4 + 0];
            gf += sbias[r*4 + 1];
            gg += sbias[r*4 + 2];
            go += sbias[r*4 + 3];
            int b = m0 + rowloc;
            float msk = g_mask[(size_t)b*6 + k];
            size_t idx = (size_t)b*360 + k*60 + r;
            float c_old = cx[idx];
            float cn = sigf(gf)*c_old + sigf(gi)*tanhf(gg);
            float hn = sigf(go)*tanhf(cn);
            g_hxn[idx] = hn;
            out_cx[idx] = msk*cn + (1.f - msk)*c_old;
        }
    }
}

// ---------------- K6: comm QKV per block  [B,60] @ [60,384], 128x128 tiles ----------------
__global__ __launch_bounds__(256, 1) void k6_commqkv(const float* __restrict__ Wq_c,
                           const float* __restrict__ Wk_c,
                           const float* __restrict__ Wv_c)
{
    __shared__ __align__(16) float Xs[20*132];
    __shared__ __align__(16) float Ws[20*132];
    int tid = threadIdx.x;           // 256
    int tx = tid & 15, ty = tid >> 4;
    int m0 = blockIdx.x * 128;
    int k  = blockIdx.y;
    int bz = blockIdx.z;             // 0..2
    const float* Wsel = (bz == 0) ? Wq_c : (bz == 1) ? Wk_c : Wv_c;
    int ng0 = bz * 128;

    float acc[64];
#pragma unroll
    for (int i = 0; i < 64; i++) acc[i] = 0.f;

    for (int d0 = 0; d0 < 60; d0 += 20) {
        for (int e = tid; e < 128*20; e += 256) {
            int m = e / 20, dd = e % 20;
            Xs[dd*132 + m] = g_hxn[(size_t)(m0+m)*360 + k*60 + d0 + dd];
        }
        for (int e = tid; e < 20*128; e += 256) {
            int dd = e >> 7, n = e & 127;
            Ws[dd*132 + n] = Wsel[(size_t)k*7680 + (d0+dd)*128 + n];
        }
        __syncthreads();
#pragma unroll
        for (int kk = 0; kk < 20; kk++) {
            float af[8], bf[8];
            LOAD_FRAG(af, &Xs[kk*132 + ty*8]);
            LOAD_FRAG(bf, &Ws[kk*132 + tx*8]);
            FMA8x8(acc, af, bf);
        }
        __syncthreads();
    }
#pragma unroll
    for (int i = 0; i < 8; i++) {
        int m = m0 + ty*8 + i;
#pragma unroll
        for (int j = 0; j < 8; j++)
            g_qkvc[(size_t)m*2304 + k*384 + ng0 + tx*8 + j] = acc[i*8+j];
    }
}

// ---------------- K7: communication attention (6 tokens, 4 heads x 32) ----------------
__global__ void k7_commattn()
{
    __shared__ float sq[4][2304];
    __shared__ float ss[4][144];
    int w = threadIdx.x >> 5, lane = threadIdx.x & 31;
    int b = blockIdx.x * 4 + w;
    const float4* src = (const float4*)(g_qkvc + (size_t)b*2304);
    float4* dst = (float4*)&sq[w][0];
    for (int t = lane; t < 576; t += 32) dst[t] = src[t];
    __syncwarp();

    const float inv = 0.17677669529663687f;  // 1/sqrt(32)
    for (int p = lane; p < 144; p += 32) {
        int h = p / 36, rem = p % 36, i = rem / 6, j = rem % 6;
        const float* qv = &sq[w][i*384 + h*32];
        const float* kv = &sq[w][j*384 + 128 + h*32];
        float s = 0.f;
#pragma unroll
        for (int c = 0; c < 32; c++) s += qv[c]*kv[c];
        ss[w][p] = s * inv;
    }
    __syncwarp();
    if (lane < 24) {
        float* row = &ss[w][lane*6];
        float mx = row[0];
#pragma unroll
        for (int j = 1; j < 6; j++) mx = fmaxf(mx, row[j]);
        float ev[6]; float sum = 0.f;
#pragma unroll
        for (int j = 0; j < 6; j++) { ev[j] = expf(row[j]-mx); sum += ev[j]; }
        float is = 1.f/sum;
#pragma unroll
        for (int j = 0; j < 6; j++) row[j] = ev[j]*is;
    }
    __syncwarp();
    for (int o = lane; o < 768; o += 32) {
        int i = o >> 7, rem = o & 127, h = rem >> 5, c = rem & 31;
        const float* att = &ss[w][h*36 + i*6];
        float acc = 0.f;
#pragma unroll
        for (int j = 0; j < 6; j++) acc += att[j]*sq[w][j*384 + 256 + h*32 + c];
        g_raw[(size_t)b*768 + o] = acc;
    }
}

// ---------------- K8: fc/gate GEMM (interleaved cols) + final hx_out ----------------
__global__ __launch_bounds__(240, 1) void k8_fcgate_out(const float* __restrict__ fc_w, const float* __restrict__ fc_b,
                              const float* __restrict__ gate_w, const float* __restrict__ gate_b,
                              const float* __restrict__ hx, float* __restrict__ out_hx)
{
    __shared__ __align__(16) float Xs[32*132];
    __shared__ __align__(16) float Ws[32*124];
    int tid = threadIdx.x;            // 240
    int tx = tid % 15, ty = tid / 15; // ty 0..15 rows, tx 0..14 cols
    int m0 = blockIdx.x * 128;

    float acc[64];
#pragma unroll
    for (int i = 0; i < 64; i++) acc[i] = 0.f;

    for (int k0 = 0; k0 < 128; k0 += 32) {
        for (int e = tid; e < 128*32; e += 240) {
            int m = e >> 5, dd = e & 31;
            Xs[dd*132 + m] = g_raw[(size_t)(m0+m)*128 + k0 + dd];
        }
        for (int e = tid; e < 32*120; e += 240) {
            int c = e / 32, dd = e % 32;
            int r = c >> 1;
            const float* Wp = (c & 1) ? gate_w : fc_w;
            Ws[dd*124 + c] = Wp[(size_t)r*128 + k0 + dd];
        }
        __syncthreads();
#pragma unroll
        for (int kk = 0; kk < 32; kk++) {
            float af[8], bf[8];
            LOAD_FRAG(af, &Xs[kk*132 + ty*8]);
            LOAD_FRAG(bf, &Ws[kk*124 + tx*8]);
            FMA8x8(acc, af, bf);
        }
        __syncthreads();
    }
#pragma unroll
    for (int i = 0; i < 8; i++) {
        int m = m0 + ty*8 + i;
        int b = m / 6, kb = m % 6;
        float msk = g_mask[m];
#pragma unroll
        for (int jr = 0; jr < 4; jr++) {
            int r = tx*4 + jr;
            float fc = acc[i*8 + jr*2]     + fc_b[r];
            float gt = acc[i*8 + jr*2 + 1] + gate_b[r];
            float att = sigf(gt) * tanhf(fc);
            size_t idx = (size_t)b*360 + kb*60 + r;
            float hn = g_hxn[idx];
            float ho = hx[idx];
            out_hx[idx] = msk*(hn + att) + (1.f - msk)*ho;
        }
    }
}

// ---------------- launch ----------------
extern "C" void kernel_launch(void* const* d_in, const int* in_sizes, int n_in,
                              void* d_out, int out_size)
{
    const float* inp    = (const float*)d_in[0];
    const float* hx     = (const float*)d_in[1];
    const float* cx     = (const float*)d_in[2];
    const float* Wq_inp = (const float*)d_in[3];
    const float* Wk_inp = (const float*)d_in[4];
    const float* Wv_inp = (const float*)d_in[5];
    const float* Wq_c   = (const float*)d_in[6];
    const float* Wk_c   = (const float*)d_in[7];
    const float* Wv_c   = (const float*)d_in[8];
    const float* fc_w   = (const float*)d_in[9];
    const float* fc_b   = (const float*)d_in[10];
    const float* gate_w = (const float*)d_in[11];
    const float* gate_b = (const float*)d_in[12];
    const float* W_ih   = (const float*)d_in[13];
    const float* W_hh   = (const float*)d_in[14];
    const float* b_ih   = (const float*)d_in[15];
    const float* b_hh   = (const float*)d_in[16];

    float* out_hx = (float*)d_out;
    float* out_cx = (float*)d_out + (size_t)BATCH*360;

    k1_kvproj<<<dim3(4, 128), 256>>>(inp, Wk_inp + 768*256, Wv_inp + 768*240);
    k2_qalpha<<<dim3(256, 6), 256>>>(hx, Wq_inp);
    k3_mask<<<64, 256>>>();
    k4_gates_lstm<<<dim3(256, 6), 256>>>(hx, cx, W_ih, W_hh, b_ih, b_hh, out_cx);
    k6_commqkv<<<dim3(128, 6, 3), 256>>>(Wq_c, Wk_c, Wv_c);
    k7_commattn<<<BATCH/4, 128>>>();
    k8_fcgate_out<<<768, 240>>>(fc_w, fc_b, gate_w, gate_b, hx, out_hx);
}

// round 7
// speedup vs baseline: 1.1505x; 1.1505x over previous
#include <cuda_runtime.h>
#include <math.h>

#define BATCH 16384
#define NINP  768
#define NHID  360
#define NBLK  6
#define BSZ   60

// ---------------- scratch ----------------
__device__ float g_kv[BATCH*496];      // [b][0:256]=Kproj (4 heads x64), [256:496]=Vproj (4 heads x60)
__device__ float g_alpha[BATCH*24];    // [b][k*4+h] = sigma(score)
__device__ float g_mask[BATCH*6];      // 0/1
__device__ float g_hxn[BATCH*360];     // LSTM hx_new (pre comm-attn)
__device__ float g_qkvc[BATCH*2304];   // [b][k*384 + {0:q,128:k,256:v}]
__device__ float g_raw[BATCH*768];     // [b][i*128 + h*32 + c]
__device__ float g_w4[6*304*256];      // pre-interleaved LSTM weights [k][d][c], c=r*4+g

__device__ __forceinline__ float sigf(float x){ return 1.f/(1.f+expf(-x)); }

#define LOAD_FRAG(f, p) do { \
    *(float4*)&f[0] = *(const float4*)(p); \
    *(float4*)&f[4] = *(const float4*)((p)+4); } while(0)

#define FMA8x8(acc, af, bf) do { \
  _Pragma("unroll") for (int i_ = 0; i_ < 8; i_++) \
    _Pragma("unroll") for (int j_ = 0; j_ < 8; j_++) \
      acc[i_*8+j_] = fmaf(af[i_], bf[j_], acc[i_*8+j_]); } while(0)

// ---------------- prep: interleave LSTM weights into g_w4 ----------------
__global__ void prep_w4(const float* __restrict__ W_ih, const float* __restrict__ W_hh)
{
    int i = blockIdx.x*256 + threadIdx.x;        // < 6*304*256 = 466944
    if (i >= 6*304*256) return;
    int k = i / (304*256); int rem = i % (304*256);
    int d = rem >> 8; int c = rem & 255;
    int r = c >> 2, g = c & 3;
    float v = 0.f;
    if (r < 60) {
        int rowW = g*360 + k*60 + r;
        if (d < 240)      v = W_ih[(size_t)rowW*1440 + k*240 + d];
        else if (d < 300) v = W_hh[(size_t)rowW*360 + k*60 + (d-240)];
    }
    g_w4[i] = v;
}

// ---------------- K1: KV projection  [B,768] @ [768,496]  (fp32 — feeds the mask) ----------------
__global__ __launch_bounds__(256, 1) void k1_kvproj(const float* __restrict__ inp,
                          const float* __restrict__ Wk1,
                          const float* __restrict__ Wv1)
{
    __shared__ __align__(16) float As[32*132];
    __shared__ __align__(16) float Bs[32*132];
    int tid = threadIdx.x;
    int tx = tid & 15, ty = tid >> 4;
    int m0 = blockIdx.y * 128;
    int n0 = blockIdx.x * 128;
    float acc[64];
#pragma unroll
    for (int i = 0; i < 64; i++) acc[i] = 0.f;

    for (int k0 = 0; k0 < 768; k0 += 32) {
        for (int e = tid; e < 128*32; e += 256) {
            int m = e >> 5, d = e & 31;
            As[d*132 + m] = inp[(size_t)(m0+m)*768 + k0 + d];
        }
        for (int e = tid; e < 32*128; e += 256) {
            int d = e >> 7, n = e & 127;
            int ng = n0 + n;
            float v = 0.f;
            if (ng < 256)       v = Wk1[(size_t)(k0+d)*256 + ng];
            else if (ng < 496)  v = Wv1[(size_t)(k0+d)*240 + (ng-256)];
            Bs[d*132 + n] = v;
        }
        __syncthreads();
#pragma unroll
        for (int kk = 0; kk < 32; kk++) {
            float af[8], bf[8];
            LOAD_FRAG(af, &As[kk*132 + ty*8]);
            LOAD_FRAG(bf, &Bs[kk*132 + tx*8]);
            FMA8x8(acc, af, bf);
        }
        __syncthreads();
    }
#pragma unroll
    for (int i = 0; i < 8; i++) {
        int m = m0 + ty*8 + i;
#pragma unroll
        for (int j = 0; j < 8; j++) {
            int n = n0 + tx*8 + j;
            if (n < 496) g_kv[(size_t)m*496 + n] = acc[i*8+j];
        }
    }
}

// ---------------- K2: Q projection (all 4 heads) + fused score -> alpha (fp32) ----------------
__global__ __launch_bounds__(256, 1) void k2_qalpha(const float* __restrict__ hx,
                          const float* __restrict__ Wq)
{
    __shared__ __align__(16) float Xs[20*68];
    __shared__ __align__(16) float Ws[20*260];
    int tid = threadIdx.x;            // 256
    int tx = tid & 31, ty = tid >> 5; // ty 0..7 (rows), tx 0..31 (cols)
    int m0 = blockIdx.x * 64;
    int k  = blockIdx.y;

    float acc[64];
#pragma unroll
    for (int i = 0; i < 64; i++) acc[i] = 0.f;

    for (int d0 = 0; d0 < 60; d0 += 20) {
        for (int e = tid; e < 64*20; e += 256) {
            int m = e / 20, dd = e % 20;
            Xs[dd*68 + m] = hx[(size_t)(m0+m)*360 + k*60 + d0 + dd];
        }
        for (int e = tid; e < 20*256; e += 256) {
            int dd = e >> 8, n = e & 255;
            Ws[dd*260 + n] = Wq[(size_t)k*15360 + (d0+dd)*256 + n];
        }
        __syncthreads();
#pragma unroll
        for (int kk = 0; kk < 20; kk++) {
            float af[8], bf[8];
            LOAD_FRAG(af, &Xs[kk*68 + ty*8]);
            LOAD_FRAG(bf, &Ws[kk*260 + tx*8]);
            FMA8x8(acc, af, bf);
        }
        __syncthreads();
    }
    int h = tx >> 3, lane8 = tx & 7;
#pragma unroll
    for (int i = 0; i < 8; i++) {
        int gm = m0 + ty*8 + i;
        const float* kp = &g_kv[(size_t)gm*496 + h*64 + lane8*8];
        float s = 0.f;
#pragma unroll
        for (int j = 0; j < 8; j++) s += acc[i*8+j] * kp[j];
        s += __shfl_xor_sync(0xffffffffu, s, 1);
        s += __shfl_xor_sync(0xffffffffu, s, 2);
        s += __shfl_xor_sync(0xffffffffu, s, 4);
        if (lane8 == 0) g_alpha[(size_t)gm*24 + k*4 + h] = sigf(0.125f*s);
    }
}

// ---------------- K3: top-2 null mask ----------------
__global__ void k3_mask()
{
    int b = blockIdx.x*256 + threadIdx.x;
    float4 a0 = *(const float4*)&g_alpha[(size_t)b*24 + 0];
    float4 a1 = *(const float4*)&g_alpha[(size_t)b*24 + 4];
    float4 a2 = *(const float4*)&g_alpha[(size_t)b*24 + 8];
    float4 a3 = *(const float4*)&g_alpha[(size_t)b*24 + 12];
    float4 a4 = *(const float4*)&g_alpha[(size_t)b*24 + 16];
    float4 a5 = *(const float4*)&g_alpha[(size_t)b*24 + 20];
    float nul[6];
    nul[0] = 1.f - 0.25f*(a0.x+a0.y+a0.z+a0.w);
    nul[1] = 1.f - 0.25f*(a1.x+a1.y+a1.z+a1.w);
    nul[2] = 1.f - 0.25f*(a2.x+a2.y+a2.z+a2.w);
    nul[3] = 1.f - 0.25f*(a3.x+a3.y+a3.z+a3.w);
    nul[4] = 1.f - 0.25f*(a4.x+a4.y+a4.z+a4.w);
    nul[5] = 1.f - 0.25f*(a5.x+a5.y+a5.z+a5.w);
    int i1 = 0; float m1 = nul[0];
#pragma unroll
    for (int k = 1; k < 6; k++) if (nul[k] > m1) { m1 = nul[k]; i1 = k; }
    int i2 = -1; float m2 = -1e30f;
#pragma unroll
    for (int k = 0; k < 6; k++) if (k != i1 && nul[k] > m2) { m2 = nul[k]; i2 = k; }
#pragma unroll
    for (int k = 0; k < 6; k++)
        g_mask[(size_t)b*6 + k] = (k == i1 || k == i2) ? 0.f : 1.f;
}

// ---------------- K4: pipelined tf32 mma gates GEMM + LSTM pointwise + cx_out ----------------
// CTA 256 thr (8 warps, 2M x 4N). Tile M=64, N=256 (c=r*4+g), K=304 (19 chunks of 16).
// 2-stage pipeline: cp.async B (from pre-interleaved g_w4) + LDG/STS A.
__global__ __launch_bounds__(256, 1) void k4_gates_lstm(const float* __restrict__ hx,
                              const float* __restrict__ cx,
                              const float* __restrict__ b_ih,
                              const float* __restrict__ b_hh,
                              float* __restrict__ out_cx)
{
    __shared__ __align__(16) float As[2][64*20];     // [m][d] stride 20
    __shared__ __align__(16) float Bs[2][16*264];    // [d][c] stride 264
    __shared__ float sbias[240];
    __shared__ float s_alpha[256];
    int tid = threadIdx.x;            // 256
    int lane = tid & 31, warp = tid >> 5;
    int warp_m = warp >> 2, warp_n = warp & 3;
    int group = lane >> 2, tcol = lane & 3;
    int m0 = blockIdx.x * 64;
    int k  = blockIdx.y;

    if (tid < 240) {
        int c = tid, r = c >> 2, g = c & 3;
        int rowW = g*360 + k*60 + r;
        sbias[c] = b_ih[rowW] + b_hh[rowW];
    }
    s_alpha[tid] = g_alpha[(size_t)(m0 + (tid >> 2))*24 + k*4 + (tid & 3)];
    __syncthreads();   // s_alpha ready before any A prefetch

    const float* w4k = g_w4 + (size_t)k*(304*256);

#define PREFETCH_A(CH, S) do { \
    _Pragma("unroll") \
    for (int i_ = 0; i_ < 4; i_++) { \
        int e_ = tid + i_*256; \
        int m_ = e_ >> 4, dd_ = e_ & 15; \
        int d_ = (CH)*16 + dd_; \
        float v_; \
        if (d_ < 240)      v_ = s_alpha[m_*4 + d_/60] * g_kv[(size_t)(m0+m_)*496 + 256 + d_]; \
        else if (d_ < 300) v_ = hx[(size_t)(m0+m_)*360 + k*60 + (d_-240)]; \
        else               v_ = 0.f; \
        As[S][m_*20 + dd_] = v_; \
    } } while(0)

#define PREFETCH_B(CH, S) do { \
    const float* src_ = w4k + (CH)*16*256; \
    _Pragma("unroll") \
    for (int i_ = 0; i_ < 4; i_++) { \
        int e_ = tid + i_*256; \
        int dd_ = e_ >> 6, c4_ = (e_ & 63)*4; \
        unsigned dst_ = (unsigned)__cvta_generic_to_shared(&Bs[S][dd_*264 + c4_]); \
        asm volatile("cp.async.ca.shared.global [%0], [%1], 16;" :: "r"(dst_), "l"(src_ + dd_*256 + c4_)); \
    } } while(0)

    float c_acc[2][8][4];
#pragma unroll
    for (int a = 0; a < 2; a++)
#pragma unroll
        for (int b = 0; b < 8; b++)
#pragma unroll
            for (int d = 0; d < 4; d++) c_acc[a][b][d] = 0.f;

    PREFETCH_B(0, 0);
    PREFETCH_A(0, 0);
    asm volatile("cp.async.commit_group;");

    for (int ch = 0; ch < 19; ch++) {
        int cur = ch & 1;
        asm volatile("cp.async.wait_group 0;");
        __syncthreads();
        if (ch < 18) {
            PREFETCH_B(ch+1, cur^1);
            PREFETCH_A(ch+1, cur^1);
            asm volatile("cp.async.commit_group;");
        }
#pragma unroll
        for (int ks = 0; ks < 2; ks++) {
            int kb = ks*8;
            unsigned a_frag[2][4];
#pragma unroll
            for (int mf = 0; mf < 2; mf++) {
                int row0 = warp_m*32 + mf*16 + group;
                a_frag[mf][0] = __float_as_uint(As[cur][row0*20 + kb + tcol]);
                a_frag[mf][1] = __float_as_uint(As[cur][(row0+8)*20 + kb + tcol]);
                a_frag[mf][2] = __float_as_uint(As[cur][row0*20 + kb + tcol + 4]);
                a_frag[mf][3] = __float_as_uint(As[cur][(row0+8)*20 + kb + tcol + 4]);
            }
#pragma unroll
            for (int nf = 0; nf < 8; nf++) {
                int coln = warp_n*64 + nf*8 + group;
                unsigned b0 = __float_as_uint(Bs[cur][(kb + tcol)*264 + coln]);
                unsigned b1 = __float_as_uint(Bs[cur][(kb + tcol + 4)*264 + coln]);
#pragma unroll
                for (int mf = 0; mf < 2; mf++) {
                    asm volatile(
                        "mma.sync.aligned.m16n8k8.row.col.f32.tf32.tf32.f32 "
                        "{%0,%1,%2,%3}, {%4,%5,%6,%7}, {%8,%9}, {%0,%1,%2,%3};"
                        : "+f"(c_acc[mf][nf][0]), "+f"(c_acc[mf][nf][1]),
                          "+f"(c_acc[mf][nf][2]), "+f"(c_acc[mf][nf][3])
                        : "r"(a_frag[mf][0]), "r"(a_frag[mf][1]),
                          "r"(a_frag[mf][2]), "r"(a_frag[mf][3]),
                          "r"(b0), "r"(b1));
                }
            }
        }
    }
    // epilogue: shfl.xor(1) pairs lanes holding gates {0,1} and {2,3} of same r
#pragma unroll
    for (int mf = 0; mf < 2; mf++) {
#pragma unroll
        for (int nf = 0; nf < 8; nf++) {
            float x0 = c_acc[mf][nf][0], x1 = c_acc[mf][nf][1];
            float x2 = c_acc[mf][nf][2], x3 = c_acc[mf][nf][3];
            float y0 = __shfl_xor_sync(0xffffffffu, x0, 1);
            float y1 = __shfl_xor_sync(0xffffffffu, x1, 1);
            float y2 = __shfl_xor_sync(0xffffffffu, x2, 1);
            float y3 = __shfl_xor_sync(0xffffffffu, x3, 1);
            int r = warp_n*16 + nf*2 + (tcol >> 1);
            if (r >= 60) continue;
            float gi, gf, gg, go; int rowloc;
            if ((tcol & 1) == 0) {
                gi = x0; gf = x1; gg = y0; go = y1;
                rowloc = warp_m*32 + mf*16 + group;
            } else {
                gi = y2; gf = y3; gg = x2; go = x3;
                rowloc = warp_m*32 + mf*16 + group + 8;
            }
            gi += sbias[r*4 + 0];
            gf += sbias[r*4 + 1];
            gg += sbias[r*4 + 2];
            go += sbias[r*4 + 3];
            int b = m0 + rowloc;
            float msk = g_mask[(size_t)b*6 + k];
            size_t idx = (size_t)b*360 + k*60 + r;
            float c_old = cx[idx];
            float cn = sigf(gf)*c_old + sigf(gi)*tanhf(gg);
            float hn = sigf(go)*tanhf(cn);
            g_hxn[idx] = hn;
            out_cx[idx] = msk*cn + (1.f - msk)*c_old;
        }
    }
#undef PREFETCH_A
#undef PREFETCH_B
}

// ---------------- K6: comm QKV per block  [B,60] @ [60,384], 128x128 tiles ----------------
__global__ __launch_bounds__(256, 1) void k6_commqkv(const float* __restrict__ Wq_c,
                           const float* __restrict__ Wk_c,
                           const float* __restrict__ Wv_c)
{
    __shared__ __align__(16) float Xs[20*132];
    __shared__ __align__(16) float Ws[20*132];
    int tid = threadIdx.x;           // 256
    int tx = tid & 15, ty = tid >> 4;
    int m0 = blockIdx.x * 128;
    int k  = blockIdx.y;
    int bz = blockIdx.z;             // 0..2
    const float* Wsel = (bz == 0) ? Wq_c : (bz == 1) ? Wk_c : Wv_c;
    int ng0 = bz * 128;

    float acc[64];
#pragma unroll
    for (int i = 0; i < 64; i++) acc[i] = 0.f;

    for (int d0 = 0; d0 < 60; d0 += 20) {
        for (int e = tid; e < 128*20; e += 256) {
            int m = e / 20, dd = e % 20;
            Xs[dd*132 + m] = g_hxn[(size_t)(m0+m)*360 + k*60 + d0 + dd];
        }
        for (int e = tid; e < 20*128; e += 256) {
            int dd = e >> 7, n = e & 127;
            Ws[dd*132 + n] = Wsel[(size_t)k*7680 + (d0+dd)*128 + n];
        }
        __syncthreads();
#pragma unroll
        for (int kk = 0; kk < 20; kk++) {
            float af[8], bf[8];
            LOAD_FRAG(af, &Xs[kk*132 + ty*8]);
            LOAD_FRAG(bf, &Ws[kk*132 + tx*8]);
            FMA8x8(acc, af, bf);
        }
        __syncthreads();
    }
#pragma unroll
    for (int i = 0; i < 8; i++) {
        int m = m0 + ty*8 + i;
#pragma unroll
        for (int j = 0; j < 8; j++)
            g_qkvc[(size_t)m*2304 + k*384 + ng0 + tx*8 + j] = acc[i*8+j];
    }
}

// ---------------- K7: communication attention (6 tokens, 4 heads x 32) ----------------
__global__ void k7_commattn()
{
    __shared__ float sq[4][2304];
    __shared__ float ss[4][144];
    int w = threadIdx.x >> 5, lane = threadIdx.x & 31;
    int b = blockIdx.x * 4 + w;
    const float4* src = (const float4*)(g_qkvc + (size_t)b*2304);
    float4* dst = (float4*)&sq[w][0];
    for (int t = lane; t < 576; t += 32) dst[t] = src[t];
    __syncwarp();

    const float inv = 0.17677669529663687f;  // 1/sqrt(32)
    for (int p = lane; p < 144; p += 32) {
        int h = p / 36, rem = p % 36, i = rem / 6, j = rem % 6;
        const float* qv = &sq[w][i*384 + h*32];
        const float* kv = &sq[w][j*384 + 128 + h*32];
        float s = 0.f;
#pragma unroll
        for (int c = 0; c < 32; c++) s += qv[c]*kv[c];
        ss[w][p] = s * inv;
    }
    __syncwarp();
    if (lane < 24) {
        float* row = &ss[w][lane*6];
        float mx = row[0];
#pragma unroll
        for (int j = 1; j < 6; j++) mx = fmaxf(mx, row[j]);
        float ev[6]; float sum = 0.f;
#pragma unroll
        for (int j = 0; j < 6; j++) { ev[j] = expf(row[j]-mx); sum += ev[j]; }
        float is = 1.f/sum;
#pragma unroll
        for (int j = 0; j < 6; j++) row[j] = ev[j]*is;
    }
    __syncwarp();
    for (int o = lane; o < 768; o += 32) {
        int i = o >> 7, rem = o & 127, h = rem >> 5, c = rem & 31;
        const float* att = &ss[w][h*36 + i*6];
        float acc = 0.f;
#pragma unroll
        for (int j = 0; j < 6; j++) acc += att[j]*sq[w][j*384 + 256 + h*32 + c];
        g_raw[(size_t)b*768 + o] = acc;
    }
}

// ---------------- K8: fc/gate GEMM (interleaved cols) + final hx_out ----------------
__global__ __launch_bounds__(240, 1) void k8_fcgate_out(const float* __restrict__ fc_w, const float* __restrict__ fc_b,
                              const float* __restrict__ gate_w, const float* __restrict__ gate_b,
                              const float* __restrict__ hx, float* __restrict__ out_hx)
{
    __shared__ __align__(16) float Xs[32*132];
    __shared__ __align__(16) float Ws[32*124];
    int tid = threadIdx.x;            // 240
    int tx = tid % 15, ty = tid / 15; // ty 0..15 rows, tx 0..14 cols
    int m0 = blockIdx.x * 128;

    float acc[64];
#pragma unroll
    for (int i = 0; i < 64; i++) acc[i] = 0.f;

    for (int k0 = 0; k0 < 128; k0 += 32) {
        for (int e = tid; e < 128*32; e += 240) {
            int m = e >> 5, dd = e & 31;
            Xs[dd*132 + m] = g_raw[(size_t)(m0+m)*128 + k0 + dd];
        }
        for (int e = tid; e < 32*120; e += 240) {
            int c = e / 32, dd = e % 32;
            int r = c >> 1;
            const float* Wp = (c & 1) ? gate_w : fc_w;
            Ws[dd*124 + c] = Wp[(size_t)r*128 + k0 + dd];
        }
        __syncthreads();
#pragma unroll
        for (int kk = 0; kk < 32; kk++) {
            float af[8], bf[8];
            LOAD_FRAG(af, &Xs[kk*132 + ty*8]);
            LOAD_FRAG(bf, &Ws[kk*124 + tx*8]);
            FMA8x8(acc, af, bf);
        }
        __syncthreads();
    }
#pragma unroll
    for (int i = 0; i < 8; i++) {
        int m = m0 + ty*8 + i;
        int b = m / 6, kb = m % 6;
        float msk = g_mask[m];
#pragma unroll
        for (int jr = 0; jr < 4; jr++) {
            int r = tx*4 + jr;
            float fc = acc[i*8 + jr*2]     + fc_b[r];
            float gt = acc[i*8 + jr*2 + 1] + gate_b[r];
            float att = sigf(gt) * tanhf(fc);
            size_t idx = (size_t)b*360 + kb*60 + r;
            float hn = g_hxn[idx];
            float ho = hx[idx];
            out_hx[idx] = msk*(hn + att) + (1.f - msk)*ho;
        }
    }
}

// ---------------- launch ----------------
extern "C" void kernel_launch(void* const* d_in, const int* in_sizes, int n_in,
                              void* d_out, int out_size)
{
    const float* inp    = (const float*)d_in[0];
    const float* hx     = (const float*)d_in[1];
    const float* cx     = (const float*)d_in[2];
    const float* Wq_inp = (const float*)d_in[3];
    const float* Wk_inp = (const float*)d_in[4];
    const float* Wv_inp = (const float*)d_in[5];
    const float* Wq_c   = (const float*)d_in[6];
    const float* Wk_c   = (const float*)d_in[7];
    const float* Wv_c   = (const float*)d_in[8];
    const float* fc_w   = (const float*)d_in[9];
    const float* fc_b   = (const float*)d_in[10];
    const float* gate_w = (const float*)d_in[11];
    const float* gate_b = (const float*)d_in[12];
    const float* W_ih   = (const float*)d_in[13];
    const float* W_hh   = (const float*)d_in[14];
    const float* b_ih   = (const float*)d_in[15];
    const float* b_hh   = (const float*)d_in[16];

    float* out_hx = (float*)d_out;
    float* out_cx = (float*)d_out + (size_t)BATCH*360;

    prep_w4<<<1824, 256>>>(W_ih, W_hh);
    k1_kvproj<<<dim3(4, 128), 256>>>(inp, Wk_inp + 768*256, Wv_inp + 768*240);
    k2_qalpha<<<dim3(256, 6), 256>>>(hx, Wq_inp);
    k3_mask<<<64, 256>>>();
    k4_gates_lstm<<<dim3(256, 6), 256>>>(hx, cx, b_ih, b_hh, out_cx);
    k6_commqkv<<<dim3(128, 6, 3), 256>>>(Wq_c, Wk_c, Wv_c);
    k7_commattn<<<BATCH/4, 128>>>();
    k8_fcgate_out<<<768, 240>>>(fc_w, fc_b, gate_w, gate_b, hx, out_hx);
}

// round 11
// speedup vs baseline: 1.7201x; 1.4951x over previous
#include <cuda_runtime.h>
#include <math.h>

#define BATCH 16384
#define NINP  768
#define NHID  360
#define NBLK  6
#define BSZ   60

// ---------------- scratch ----------------
__device__ float g_kv[BATCH*496];      // [b][0:256]=Kproj (4 heads x64), [256:496]=Vproj (4 heads x60)
__device__ float g_alpha[BATCH*24];    // [b][k*4+h] = sigma(score)
__device__ float g_mask[BATCH*6];      // 0/1
__device__ float g_hxn[BATCH*360];     // LSTM hx_new (pre comm-attn)
__device__ float g_qkvc[BATCH*2304];   // [b][k*384 + {0:q,128:k,256:v}]
__device__ float g_raw[BATCH*768];     // [b][i*128 + h*32 + c]
__device__ float g_w4[6*304*256];      // LSTM weights [k][d][c], c=r*4+g
__device__ float g_wc[6*64*384];       // comm QKV weights [k][d][n], n={q|k|v}, d padded to 64
__device__ float g_w8[128*128];        // fc/gate weights [d][c], c=r*2+s (s=0 fc, 1 gate), c padded 128

__device__ __forceinline__ float sigf(float x){ return 1.f/(1.f+expf(-x)); }

#define LOAD_FRAG(f, p) do { \
    *(float4*)&f[0] = *(const float4*)(p); \
    *(float4*)&f[4] = *(const float4*)((p)+4); } while(0)

#define FMA8x8(acc, af, bf) do { \
  _Pragma("unroll") for (int i_ = 0; i_ < 8; i_++) \
    _Pragma("unroll") for (int j_ = 0; j_ < 8; j_++) \
      acc[i_*8+j_] = fmaf(af[i_], bf[j_], acc[i_*8+j_]); } while(0)

#define CP_ASYNC16(dst, src) \
    asm volatile("cp.async.ca.shared.global [%0], [%1], 16;" :: "r"(dst), "l"(src))
#define CP_COMMIT() asm volatile("cp.async.commit_group;")
#define CP_WAIT0()  asm volatile("cp.async.wait_group 0;")

#define MMA_TF32(c0,c1,c2,c3, a0,a1,a2,a3, b0,b1) \
    asm volatile( \
        "mma.sync.aligned.m16n8k8.row.col.f32.tf32.tf32.f32 " \
        "{%0,%1,%2,%3}, {%4,%5,%6,%7}, {%8,%9}, {%0,%1,%2,%3};" \
        : "+f"(c0), "+f"(c1), "+f"(c2), "+f"(c3) \
        : "r"(a0), "r"(a1), "r"(a2), "r"(a3), "r"(b0), "r"(b1))

// ---------------- prep kernels ----------------
__global__ void prep_w4(const float* __restrict__ W_ih, const float* __restrict__ W_hh)
{
    int i = blockIdx.x*256 + threadIdx.x;        // < 6*304*256
    if (i >= 6*304*256) return;
    int k = i / (304*256); int rem = i % (304*256);
    int d = rem >> 8; int c = rem & 255;
    int r = c >> 2, g = c & 3;
    float v = 0.f;
    if (r < 60) {
        int rowW = g*360 + k*60 + r;
        if (d < 240)      v = W_ih[(size_t)rowW*1440 + k*240 + d];
        else if (d < 300) v = W_hh[(size_t)rowW*360 + k*60 + (d-240)];
    }
    g_w4[i] = v;
}

__global__ void prep_wc(const float* __restrict__ Wq_c,
                        const float* __restrict__ Wk_c,
                        const float* __restrict__ Wv_c)
{
    int i = blockIdx.x*256 + threadIdx.x;        // < 6*64*384 = 147456
    if (i >= 6*64*384) return;
    int k = i / (64*384); int rem = i % (64*384);
    int d = rem / 384; int n = rem % 384;
    float v = 0.f;
    if (d < 60) {
        const float* W = (n < 128) ? Wq_c : (n < 256) ? Wk_c : Wv_c;
        v = W[(size_t)k*7680 + d*128 + (n & 127)];
    }
    g_wc[i] = v;
}

__global__ void prep_w8(const float* __restrict__ fc_w, const float* __restrict__ gate_w)
{
    int i = blockIdx.x*256 + threadIdx.x;        // < 128*128
    if (i >= 128*128) return;
    int d = i >> 7, c = i & 127;
    int r = c >> 1, s = c & 1;
    float v = 0.f;
    if (r < 60) v = s ? gate_w[(size_t)r*128 + d] : fc_w[(size_t)r*128 + d];
    g_w8[i] = v;
}

// ---------------- K1a: Kproj  [B,768] @ [768,256]  (fp32 — feeds the mask) ----------------
__global__ __launch_bounds__(256, 1) void k1a_kproj(const float* __restrict__ inp,
                          const float* __restrict__ Wk1)
{
    __shared__ __align__(16) float As[32*132];
    __shared__ __align__(16) float Bs[32*132];
    int tid = threadIdx.x;
    int tx = tid & 15, ty = tid >> 4;
    int m0 = blockIdx.y * 128;
    int n0 = blockIdx.x * 128;
    float acc[64];
#pragma unroll
    for (int i = 0; i < 64; i++) acc[i] = 0.f;

    for (int k0 = 0; k0 < 768; k0 += 32) {
        for (int e = tid; e < 128*32; e += 256) {
            int m = e >> 5, d = e & 31;
            As[d*132 + m] = inp[(size_t)(m0+m)*768 + k0 + d];
        }
        for (int e = tid; e < 32*128; e += 256) {
            int d = e >> 7, n = e & 127;
            Bs[d*132 + n] = Wk1[(size_t)(k0+d)*256 + n0 + n];
        }
        __syncthreads();
#pragma unroll
        for (int kk = 0; kk < 32; kk++) {
            float af[8], bf[8];
            LOAD_FRAG(af, &As[kk*132 + ty*8]);
            LOAD_FRAG(bf, &Bs[kk*132 + tx*8]);
            FMA8x8(acc, af, bf);
        }
        __syncthreads();
    }
#pragma unroll
    for (int i = 0; i < 8; i++) {
        int m = m0 + ty*8 + i;
#pragma unroll
        for (int j = 0; j < 8; j++)
            g_kv[(size_t)m*496 + n0 + tx*8 + j] = acc[i*8+j];
    }
}

// ---------------- K1b: Vproj  [B,768] @ [768,240]  (tf32 mma, pipelined) ----------------
// M=64, N=256 (240 pad), K=768 = 48 chunks of 16. 8 warps 2Mx4N, warp 32x64.
__global__ __launch_bounds__(256, 1) void k1b_vproj(const float* __restrict__ inp,
                          const float* __restrict__ Wv1)
{
    __shared__ __align__(16) float As[2][64*20];
    __shared__ __align__(16) float Bs[2][16*264];
    int tid = threadIdx.x;
    int lane = tid & 31, warp = tid >> 5;
    int warp_m = warp >> 2, warp_n = warp & 3;
    int group = lane >> 2, tcol = lane & 3;
    int m0 = blockIdx.x * 64;

    // zero pad cols 240..263 (never overwritten by cp.async)
    for (int s = 0; s < 2; s++)
        for (int e = tid; e < 16*24; e += 256) {
            int dd = e / 24, c = 240 + e % 24;
            Bs[s][dd*264 + c] = 0.f;
        }

    float c_acc[2][8][4];
#pragma unroll
    for (int a = 0; a < 2; a++)
#pragma unroll
        for (int b = 0; b < 8; b++)
#pragma unroll
            for (int d = 0; d < 4; d++) c_acc[a][b][d] = 0.f;

// A: 64 rows x 16 floats = 1024 floats = 256 x 4-float copies (1/thread).
// B: 16 rows x 240 floats = 3840 floats = 960 x 4-float copies (4 strided iters, guard e<960).
#define K1B_PF(CH, S) do { \
    { int m_ = tid >> 2, seg_ = tid & 3; \
      unsigned dA_ = (unsigned)__cvta_generic_to_shared(&As[S][m_*20 + seg_*4]); \
      CP_ASYNC16(dA_, inp + (size_t)(m0+m_)*768 + (CH)*16 + seg_*4); } \
    _Pragma("unroll") \
    for (int i_ = 0; i_ < 4; i_++) { \
        int e_ = tid + i_*256; \
        if (e_ < 960) { \
            int dd_ = e_ / 60, c4_ = (e_ % 60)*4; \
            unsigned dB_ = (unsigned)__cvta_generic_to_shared(&Bs[S][dd_*264 + c4_]); \
            CP_ASYNC16(dB_, Wv1 + (size_t)((CH)*16 + dd_)*240 + c4_); \
        } \
    } } while(0)

    __syncthreads();
    K1B_PF(0, 0);
    CP_COMMIT();

    for (int ch = 0; ch < 48; ch++) {
        int cur = ch & 1;
        CP_WAIT0();
        __syncthreads();
        if (ch < 47) { K1B_PF(ch+1, cur^1); CP_COMMIT(); }
#pragma unroll
        for (int ks = 0; ks < 2; ks++) {
            int kb = ks*8;
            unsigned a_frag[2][4];
#pragma unroll
            for (int mf = 0; mf < 2; mf++) {
                int row0 = warp_m*32 + mf*16 + group;
                a_frag[mf][0] = __float_as_uint(As[cur][row0*20 + kb + tcol]);
                a_frag[mf][1] = __float_as_uint(As[cur][(row0+8)*20 + kb + tcol]);
                a_frag[mf][2] = __float_as_uint(As[cur][row0*20 + kb + tcol + 4]);
                a_frag[mf][3] = __float_as_uint(As[cur][(row0+8)*20 + kb + tcol + 4]);
            }
#pragma unroll
            for (int nf = 0; nf < 8; nf++) {
                int coln = warp_n*64 + nf*8 + group;
                unsigned b0 = __float_as_uint(Bs[cur][(kb + tcol)*264 + coln]);
                unsigned b1 = __float_as_uint(Bs[cur][(kb + tcol + 4)*264 + coln]);
#pragma unroll
                for (int mf = 0; mf < 2; mf++)
                    MMA_TF32(c_acc[mf][nf][0], c_acc[mf][nf][1], c_acc[mf][nf][2], c_acc[mf][nf][3],
                             a_frag[mf][0], a_frag[mf][1], a_frag[mf][2], a_frag[mf][3], b0, b1);
            }
        }
    }
#undef K1B_PF
#pragma unroll
    for (int mf = 0; mf < 2; mf++) {
#pragma unroll
        for (int nf = 0; nf < 8; nf++) {
            int c = warp_n*64 + nf*8 + tcol*2;
            if (c >= 240) continue;
            int r0 = m0 + warp_m*32 + mf*16 + group;
            g_kv[(size_t)r0*496 + 256 + c]     = c_acc[mf][nf][0];
            g_kv[(size_t)r0*496 + 256 + c + 1] = c_acc[mf][nf][1];
            g_kv[(size_t)(r0+8)*496 + 256 + c]     = c_acc[mf][nf][2];
            g_kv[(size_t)(r0+8)*496 + 256 + c + 1] = c_acc[mf][nf][3];
        }
    }
}

// ---------------- K2: Q projection (all 4 heads) + fused score -> alpha (fp32) ----------------
__global__ __launch_bounds__(256, 1) void k2_qalpha(const float* __restrict__ hx,
                          const float* __restrict__ Wq)
{
    __shared__ __align__(16) float Xs[20*68];
    __shared__ __align__(16) float Ws[20*260];
    int tid = threadIdx.x;            // 256
    int tx = tid & 31, ty = tid >> 5;
    int m0 = blockIdx.x * 64;
    int k  = blockIdx.y;

    float acc[64];
#pragma unroll
    for (int i = 0; i < 64; i++) acc[i] = 0.f;

    for (int d0 = 0; d0 < 60; d0 += 20) {
        for (int e = tid; e < 64*20; e += 256) {
            int m = e / 20, dd = e % 20;
            Xs[dd*68 + m] = hx[(size_t)(m0+m)*360 + k*60 + d0 + dd];
        }
        for (int e = tid; e < 20*256; e += 256) {
            int dd = e >> 8, n = e & 255;
            Ws[dd*260 + n] = Wq[(size_t)k*15360 + (d0+dd)*256 + n];
        }
        __syncthreads();
#pragma unroll
        for (int kk = 0; kk < 20; kk++) {
            float af[8], bf[8];
            LOAD_FRAG(af, &Xs[kk*68 + ty*8]);
            LOAD_FRAG(bf, &Ws[kk*260 + tx*8]);
            FMA8x8(acc, af, bf);
        }
        __syncthreads();
    }
    int h = tx >> 3, lane8 = tx & 7;
#pragma unroll
    for (int i = 0; i < 8; i++) {
        int gm = m0 + ty*8 + i;
        const float* kp = &g_kv[(size_t)gm*496 + h*64 + lane8*8];
        float s = 0.f;
#pragma unroll
        for (int j = 0; j < 8; j++) s += acc[i*8+j] * kp[j];
        s += __shfl_xor_sync(0xffffffffu, s, 1);
        s += __shfl_xor_sync(0xffffffffu, s, 2);
        s += __shfl_xor_sync(0xffffffffu, s, 4);
        if (lane8 == 0) g_alpha[(size_t)gm*24 + k*4 + h] = sigf(0.125f*s);
    }
}

// ---------------- K3: top-2 null mask ----------------
__global__ void k3_mask()
{
    int b = blockIdx.x*256 + threadIdx.x;
    float4 a0 = *(const float4*)&g_alpha[(size_t)b*24 + 0];
    float4 a1 = *(const float4*)&g_alpha[(size_t)b*24 + 4];
    float4 a2 = *(const float4*)&g_alpha[(size_t)b*24 + 8];
    float4 a3 = *(const float4*)&g_alpha[(size_t)b*24 + 12];
    float4 a4 = *(const float4*)&g_alpha[(size_t)b*24 + 16];
    float4 a5 = *(const float4*)&g_alpha[(size_t)b*24 + 20];
    float nul[6];
    nul[0] = 1.f - 0.25f*(a0.x+a0.y+a0.z+a0.w);
    nul[1] = 1.f - 0.25f*(a1.x+a1.y+a1.z+a1.w);
    nul[2] = 1.f - 0.25f*(a2.x+a2.y+a2.z+a2.w);
    nul[3] = 1.f - 0.25f*(a3.x+a3.y+a3.z+a3.w);
    nul[4] = 1.f - 0.25f*(a4.x+a4.y+a4.z+a4.w);
    nul[5] = 1.f - 0.25f*(a5.x+a5.y+a5.z+a5.w);
    int i1 = 0; float m1 = nul[0];
#pragma unroll
    for (int k = 1; k < 6; k++) if (nul[k] > m1) { m1 = nul[k]; i1 = k; }
    int i2 = -1; float m2 = -1e30f;
#pragma unroll
    for (int k = 0; k < 6; k++) if (k != i1 && nul[k] > m2) { m2 = nul[k]; i2 = k; }
#pragma unroll
    for (int k = 0; k < 6; k++)
        g_mask[(size_t)b*6 + k] = (k == i1 || k == i2) ? 0.f : 1.f;
}

// ---------------- K4: pipelined tf32 mma gates GEMM + LSTM pointwise + cx_out ----------------
__global__ __launch_bounds__(256, 1) void k4_gates_lstm(const float* __restrict__ hx,
                              const float* __restrict__ cx,
                              const float* __restrict__ b_ih,
                              const float* __restrict__ b_hh,
                              float* __restrict__ out_cx)
{
    __shared__ __align__(16) float As[2][64*20];
    __shared__ __align__(16) float Bs[2][16*264];
    __shared__ float sbias[240];
    __shared__ float s_alpha[256];
    int tid = threadIdx.x;
    int lane = tid & 31, warp = tid >> 5;
    int warp_m = warp >> 2, warp_n = warp & 3;
    int group = lane >> 2, tcol = lane & 3;
    int m0 = blockIdx.x * 64;
    int k  = blockIdx.y;

    if (tid < 240) {
        int c = tid, r = c >> 2, g = c & 3;
        int rowW = g*360 + k*60 + r;
        sbias[c] = b_ih[rowW] + b_hh[rowW];
    }
    s_alpha[tid] = g_alpha[(size_t)(m0 + (tid >> 2))*24 + k*4 + (tid & 3)];
    __syncthreads();

    const float* w4k = g_w4 + (size_t)k*(304*256);

#define PREFETCH_A(CH, S) do { \
    _Pragma("unroll") \
    for (int i_ = 0; i_ < 4; i_++) { \
        int e_ = tid + i_*256; \
        int m_ = e_ >> 4, dd_ = e_ & 15; \
        int d_ = (CH)*16 + dd_; \
        float v_; \
        if (d_ < 240)      v_ = s_alpha[m_*4 + d_/60] * g_kv[(size_t)(m0+m_)*496 + 256 + d_]; \
        else if (d_ < 300) v_ = hx[(size_t)(m0+m_)*360 + k*60 + (d_-240)]; \
        else               v_ = 0.f; \
        As[S][m_*20 + dd_] = v_; \
    } } while(0)

#define PREFETCH_B(CH, S) do { \
    const float* src_ = w4k + (CH)*16*256; \
    _Pragma("unroll") \
    for (int i_ = 0; i_ < 4; i_++) { \
        int e_ = tid + i_*256; \
        int dd_ = e_ >> 6, c4_ = (e_ & 63)*4; \
        unsigned dst_ = (unsigned)__cvta_generic_to_shared(&Bs[S][dd_*264 + c4_]); \
        CP_ASYNC16(dst_, src_ + dd_*256 + c4_); \
    } } while(0)

    float c_acc[2][8][4];
#pragma unroll
    for (int a = 0; a < 2; a++)
#pragma unroll
        for (int b = 0; b < 8; b++)
#pragma unroll
            for (int d = 0; d < 4; d++) c_acc[a][b][d] = 0.f;

    PREFETCH_B(0, 0);
    PREFETCH_A(0, 0);
    CP_COMMIT();

    for (int ch = 0; ch < 19; ch++) {
        int cur = ch & 1;
        CP_WAIT0();
        __syncthreads();
        if (ch < 18) {
            PREFETCH_B(ch+1, cur^1);
            PREFETCH_A(ch+1, cur^1);
            CP_COMMIT();
        }
#pragma unroll
        for (int ks = 0; ks < 2; ks++) {
            int kb = ks*8;
            unsigned a_frag[2][4];
#pragma unroll
            for (int mf = 0; mf < 2; mf++) {
                int row0 = warp_m*32 + mf*16 + group;
                a_frag[mf][0] = __float_as_uint(As[cur][row0*20 + kb + tcol]);
                a_frag[mf][1] = __float_as_uint(As[cur][(row0+8)*20 + kb + tcol]);
                a_frag[mf][2] = __float_as_uint(As[cur][row0*20 + kb + tcol + 4]);
                a_frag[mf][3] = __float_as_uint(As[cur][(row0+8)*20 + kb + tcol + 4]);
            }
#pragma unroll
            for (int nf = 0; nf < 8; nf++) {
                int coln = warp_n*64 + nf*8 + group;
                unsigned b0 = __float_as_uint(Bs[cur][(kb + tcol)*264 + coln]);
                unsigned b1 = __float_as_uint(Bs[cur][(kb + tcol + 4)*264 + coln]);
#pragma unroll
                for (int mf = 0; mf < 2; mf++)
                    MMA_TF32(c_acc[mf][nf][0], c_acc[mf][nf][1], c_acc[mf][nf][2], c_acc[mf][nf][3],
                             a_frag[mf][0], a_frag[mf][1], a_frag[mf][2], a_frag[mf][3], b0, b1);
            }
        }
    }
#undef PREFETCH_A
#undef PREFETCH_B
#pragma unroll
    for (int mf = 0; mf < 2; mf++) {
#pragma unroll
        for (int nf = 0; nf < 8; nf++) {
            float x0 = c_acc[mf][nf][0], x1 = c_acc[mf][nf][1];
            float x2 = c_acc[mf][nf][2], x3 = c_acc[mf][nf][3];
            float y0 = __shfl_xor_sync(0xffffffffu, x0, 1);
            float y1 = __shfl_xor_sync(0xffffffffu, x1, 1);
            float y2 = __shfl_xor_sync(0xffffffffu, x2, 1);
            float y3 = __shfl_xor_sync(0xffffffffu, x3, 1);
            int r = warp_n*16 + nf*2 + (tcol >> 1);
            if (r >= 60) continue;
            float gi, gf, gg, go; int rowloc;
            if ((tcol & 1) == 0) {
                gi = x0; gf = x1; gg = y0; go = y1;
                rowloc = warp_m*32 + mf*16 + group;
            } else {
                gi = y2; gf = y3; gg = x2; go = x3;
                rowloc = warp_m*32 + mf*16 + group + 8;
            }
            gi += sbias[r*4 + 0];
            gf += sbias[r*4 + 1];
            gg += sbias[r*4 + 2];
            go += sbias[r*4 + 3];
            int b = m0 + rowloc;
            float msk = g_mask[(size_t)b*6 + k];
            size_t idx = (size_t)b*360 + k*60 + r;
            float c_old = cx[idx];
            float cn = sigf(gf)*c_old + sigf(gi)*tanhf(gg);
            float hn = sigf(go)*tanhf(cn);
            g_hxn[idx] = hn;
            out_cx[idx] = msk*cn + (1.f - msk)*c_old;
        }
    }
}

// ---------------- K6: tf32 mma comm QKV  [B,64] @ [64,384] per block ----------------
// M=64, N=192 (bz 0..1), K=64 = 4 chunks. 8 warps 2Mx4N, warp 32x48 (Nf=6).
__global__ __launch_bounds__(256, 1) void k6_commqkv()
{
    __shared__ __align__(16) float As[2][64*20];
    __shared__ __align__(16) float Bs[2][16*200];
    int tid = threadIdx.x;
    int lane = tid & 31, warp = tid >> 5;
    int warp_m = warp >> 2, warp_n = warp & 3;
    int group = lane >> 2, tcol = lane & 3;
    int m0 = blockIdx.x * 64;
    int kblk = blockIdx.y;
    int bz = blockIdx.z;
    const float* wck = g_wc + (size_t)kblk*(64*384) + bz*192;

#define K6_PFA(CH, S) do { \
    _Pragma("unroll") \
    for (int i_ = 0; i_ < 4; i_++) { \
        int e_ = tid + i_*256; \
        int m_ = e_ >> 4, dd_ = e_ & 15; \
        int d_ = (CH)*16 + dd_; \
        As[S][m_*20 + dd_] = (d_ < 60) ? g_hxn[(size_t)(m0+m_)*360 + kblk*60 + d_] : 0.f; \
    } } while(0)

// B: 16 rows x 192 floats = 3072 floats = 768 x 4-float copies = 3 x 256.
#define K6_PFB(CH, S) do { \
    _Pragma("unroll") \
    for (int i_ = 0; i_ < 3; i_++) { \
        int e_ = tid + i_*256; \
        int dd_ = e_ / 48, c4_ = (e_ % 48)*4; \
        unsigned dst_ = (unsigned)__cvta_generic_to_shared(&Bs[S][dd_*200 + c4_]); \
        CP_ASYNC16(dst_, wck + (size_t)((CH)*16 + dd_)*384 + c4_); \
    } } while(0)

    float c_acc[2][6][4];
#pragma unroll
    for (int a = 0; a < 2; a++)
#pragma unroll
        for (int b = 0; b < 6; b++)
#pragma unroll
            for (int d = 0; d < 4; d++) c_acc[a][b][d] = 0.f;

    K6_PFB(0, 0);
    K6_PFA(0, 0);
    CP_COMMIT();

    for (int ch = 0; ch < 4; ch++) {
        int cur = ch & 1;
        CP_WAIT0();
        __syncthreads();
        if (ch < 3) { K6_PFB(ch+1, cur^1); K6_PFA(ch+1, cur^1); CP_COMMIT(); }
#pragma unroll
        for (int ks = 0; ks < 2; ks++) {
            int kb = ks*8;
            unsigned a_frag[2][4];
#pragma unroll
            for (int mf = 0; mf < 2; mf++) {
                int row0 = warp_m*32 + mf*16 + group;
                a_frag[mf][0] = __float_as_uint(As[cur][row0*20 + kb + tcol]);
                a_frag[mf][1] = __float_as_uint(As[cur][(row0+8)*20 + kb + tcol]);
                a_frag[mf][2] = __float_as_uint(As[cur][row0*20 + kb + tcol + 4]);
                a_frag[mf][3] = __float_as_uint(As[cur][(row0+8)*20 + kb + tcol + 4]);
            }
#pragma unroll
            for (int nf = 0; nf < 6; nf++) {
                int coln = warp_n*48 + nf*8 + group;
                unsigned b0 = __float_as_uint(Bs[cur][(kb + tcol)*200 + coln]);
                unsigned b1 = __float_as_uint(Bs[cur][(kb + tcol + 4)*200 + coln]);
#pragma unroll
                for (int mf = 0; mf < 2; mf++)
                    MMA_TF32(c_acc[mf][nf][0], c_acc[mf][nf][1], c_acc[mf][nf][2], c_acc[mf][nf][3],
                             a_frag[mf][0], a_frag[mf][1], a_frag[mf][2], a_frag[mf][3], b0, b1);
            }
        }
    }
#undef K6_PFA
#undef K6_PFB
#pragma unroll
    for (int mf = 0; mf < 2; mf++) {
#pragma unroll
        for (int nf = 0; nf < 6; nf++) {
            int c = warp_n*48 + nf*8 + tcol*2;
            int r0 = m0 + warp_m*32 + mf*16 + group;
            size_t base = (size_t)kblk*384 + bz*192 + c;
            *(float2*)&g_qkvc[(size_t)r0*2304 + base]     = make_float2(c_acc[mf][nf][0], c_acc[mf][nf][1]);
            *(float2*)&g_qkvc[(size_t)(r0+8)*2304 + base] = make_float2(c_acc[mf][nf][2], c_acc[mf][nf][3]);
        }
    }
}

// ---------------- K7: communication attention (6 tokens, 4 heads x 32) ----------------
__global__ void k7_commattn()
{
    __shared__ float sq[4][2304];
    __shared__ float ss[4][144];
    int w = threadIdx.x >> 5, lane = threadIdx.x & 31;
    int b = blockIdx.x * 4 + w;
    const float4* src = (const float4*)(g_qkvc + (size_t)b*2304);
    float4* dst = (float4*)&sq[w][0];
    for (int t = lane; t < 576; t += 32) dst[t] = src[t];
    __syncwarp();

    const float inv = 0.17677669529663687f;  // 1/sqrt(32)
    for (int p = lane; p < 144; p += 32) {
        int h = p / 36, rem = p % 36, i = rem / 6, j = rem % 6;
        const float* qv = &sq[w][i*384 + h*32];
        const float* kv = &sq[w][j*384 + 128 + h*32];
        float s = 0.f;
#pragma unroll
        for (int c = 0; c < 32; c++) s += qv[c]*kv[c];
        ss[w][p] = s * inv;
    }
    __syncwarp();
    if (lane < 24) {
        float* row = &ss[w][lane*6];
        float mx = row[0];
#pragma unroll
        for (int j = 1; j < 6; j++) mx = fmaxf(mx, row[j]);
        float ev[6]; float sum = 0.f;
#pragma unroll
        for (int j = 0; j < 6; j++) { ev[j] = expf(row[j]-mx); sum += ev[j]; }
        float is = 1.f/sum;
#pragma unroll
        for (int j = 0; j < 6; j++) row[j] = ev[j]*is;
    }
    __syncwarp();
    for (int o = lane; o < 768; o += 32) {
        int i = o >> 7, rem = o & 127, h = rem >> 5, c = rem & 31;
        const float* att = &ss[w][h*36 + i*6];
        float acc = 0.f;
#pragma unroll
        for (int j = 0; j < 6; j++) acc += att[j]*sq[w][j*384 + 256 + h*32 + c];
        g_raw[(size_t)b*768 + o] = acc;
    }
}

// ---------------- K8: tf32 mma fc/gate GEMM + final hx_out ----------------
// rows = B*6, M=64, N=128 (c=r*2+s, 120 pad), K=128 = 8 chunks. 8 warps 2Mx4N, warp 32x32 (Nf=4).
__global__ __launch_bounds__(256, 1) void k8_fcgate_out(const float* __restrict__ fc_b,
                              const float* __restrict__ gate_b,
                              const float* __restrict__ hx, float* __restrict__ out_hx)
{
    __shared__ __align__(16) float As[2][64*20];
    __shared__ __align__(16) float Bs[2][16*136];
    int tid = threadIdx.x;
    int lane = tid & 31, warp = tid >> 5;
    int warp_m = warp >> 2, warp_n = warp & 3;
    int group = lane >> 2, tcol = lane & 3;
    int m0 = blockIdx.x * 64;

#define K8_PFA(CH, S) do { \
    { int m_ = tid >> 2, seg_ = tid & 3; \
      unsigned dA_ = (unsigned)__cvta_generic_to_shared(&As[S][m_*20 + seg_*4]); \
      CP_ASYNC16(dA_, g_raw + (size_t)(m0+m_)*128 + (CH)*16 + seg_*4); } \
    } while(0)

// B: 16 rows x 128 floats = 2048 floats = 512 x 4-float copies = 2 x 256.
#define K8_PFB(CH, S) do { \
    _Pragma("unroll") \
    for (int i_ = 0; i_ < 2; i_++) { \
        int e_ = tid + i_*256; \
        int dd_ = e_ >> 5, c4_ = (e_ & 31)*4; \
        unsigned dst_ = (unsigned)__cvta_generic_to_shared(&Bs[S][dd_*136 + c4_]); \
        CP_ASYNC16(dst_, g_w8 + (size_t)((CH)*16 + dd_)*128 + c4_); \
    } } while(0)

    float c_acc[2][4][4];
#pragma unroll
    for (int a = 0; a < 2; a++)
#pragma unroll
        for (int b = 0; b < 4; b++)
#pragma unroll
            for (int d = 0; d < 4; d++) c_acc[a][b][d] = 0.f;

    K8_PFB(0, 0);
    K8_PFA(0, 0);
    CP_COMMIT();

    for (int ch = 0; ch < 8; ch++) {
        int cur = ch & 1;
        CP_WAIT0();
        __syncthreads();
        if (ch < 7) { K8_PFB(ch+1, cur^1); K8_PFA(ch+1, cur^1); CP_COMMIT(); }
#pragma unroll
        for (int ks = 0; ks < 2; ks++) {
            int kb = ks*8;
            unsigned a_frag[2][4];
#pragma unroll
            for (int mf = 0; mf < 2; mf++) {
                int row0 = warp_m*32 + mf*16 + group;
                a_frag[mf][0] = __float_as_uint(As[cur][row0*20 + kb + tcol]);
                a_frag[mf][1] = __float_as_uint(As[cur][(row0+8)*20 + kb + tcol]);
                a_frag[mf][2] = __float_as_uint(As[cur][row0*20 + kb + tcol + 4]);
                a_frag[mf][3] = __float_as_uint(As[cur][(row0+8)*20 + kb + tcol + 4]);
            }
#pragma unroll
            for (int nf = 0; nf < 4; nf++) {
                int coln = warp_n*32 + nf*8 + group;
                unsigned b0 = __float_as_uint(Bs[cur][(kb + tcol)*136 + coln]);
                unsigned b1 = __float_as_uint(Bs[cur][(kb + tcol + 4)*136 + coln]);
#pragma unroll
                for (int mf = 0; mf < 2; mf++)
                    MMA_TF32(c_acc[mf][nf][0], c_acc[mf][nf][1], c_acc[mf][nf][2], c_acc[mf][nf][3],
                             a_frag[mf][0], a_frag[mf][1], a_frag[mf][2], a_frag[mf][3], b0, b1);
            }
        }
    }
#undef K8_PFA
#undef K8_PFB
    // epilogue: each thread's (c, c+1) = (fc_r, gate_r) directly
#pragma unroll
    for (int mf = 0; mf < 2; mf++) {
#pragma unroll
        for (int nf = 0; nf < 4; nf++) {
            int c = warp_n*32 + nf*8 + tcol*2;
            int r = c >> 1;
            if (r >= 60) continue;
            float fb = fc_b[r], gb = gate_b[r];
#pragma unroll
            for (int half = 0; half < 2; half++) {
                int m = m0 + warp_m*32 + mf*16 + group + half*8;
                float fc = c_acc[mf][nf][half*2]     + fb;
                float gt = c_acc[mf][nf][half*2 + 1] + gb;
                float att = sigf(gt) * tanhf(fc);
                int b = m / 6, kb = m % 6;
                float msk = g_mask[m];
                size_t idx = (size_t)b*360 + kb*60 + r;
                float hn = g_hxn[idx];
                float ho = hx[idx];
                out_hx[idx] = msk*(hn + att) + (1.f - msk)*ho;
            }
        }
    }
}

// ---------------- launch ----------------
extern "C" void kernel_launch(void* const* d_in, const int* in_sizes, int n_in,
                              void* d_out, int out_size)
{
    const float* inp    = (const float*)d_in[0];
    const float* hx     = (const float*)d_in[1];
    const float* cx     = (const float*)d_in[2];
    const float* Wq_inp = (const float*)d_in[3];
    const float* Wk_inp = (const float*)d_in[4];
    const float* Wv_inp = (const float*)d_in[5];
    const float* Wq_c   = (const float*)d_in[6];
    const float* Wk_c   = (const float*)d_in[7];
    const float* Wv_c   = (const float*)d_in[8];
    const float* fc_w   = (const float*)d_in[9];
    const float* fc_b   = (const float*)d_in[10];
    const float* gate_w = (const float*)d_in[11];
    const float* gate_b = (const float*)d_in[12];
    const float* W_ih   = (const float*)d_in[13];
    const float* W_hh   = (const float*)d_in[14];
    const float* b_ih   = (const float*)d_in[15];
    const float* b_hh   = (const float*)d_in[16];

    float* out_hx = (float*)d_out;
    float* out_cx = (float*)d_out + (size_t)BATCH*360;

    prep_w4<<<1824, 256>>>(W_ih, W_hh);
    prep_wc<<<576, 256>>>(Wq_c, Wk_c, Wv_c);
    prep_w8<<<64, 256>>>(fc_w, gate_w);
    k1a_kproj<<<dim3(2, 128), 256>>>(inp, Wk_inp + 768*256);
    k1b_vproj<<<256, 256>>>(inp, Wv_inp + 768*240);
    k2_qalpha<<<dim3(256, 6), 256>>>(hx, Wq_inp);
    k3_mask<<<64, 256>>>();
    k4_gates_lstm<<<dim3(256, 6), 256>>>(hx, cx, b_ih, b_hh, out_cx);
    k6_commqkv<<<dim3(256, 6, 2), 256>>>();
    k7_commattn<<<BATCH/4, 128>>>();
    k8_fcgate_out<<<1536, 256>>>(fc_b, gate_b, hx, out_hx);
}

// round 13
// speedup vs baseline: 1.8113x; 1.0530x over previous
#include <cuda_runtime.h>
#include <math.h>

#define BATCH 16384
#define NINP  768
#define NHID  360
#define NBLK  6
#define BSZ   60

// ---------------- scratch ----------------
__device__ float g_kv[BATCH*496];      // [b][0:256]=Kproj (4 heads x64), [256:496]=Vproj (4 heads x60)
__device__ float g_alpha[BATCH*24];    // [b][k*4+h] = sigma(score)
__device__ float g_mask[BATCH*6];      // 0/1
__device__ float g_hxn[BATCH*360];     // LSTM hx_new (pre comm-attn)
__device__ float g_qkvc[BATCH*2304];   // [b][k*384 + {0:q,128:k,256:v}]
__device__ float g_raw[BATCH*768];     // [b][i*128 + h*32 + c]
__device__ float g_w4[6*304*256];      // LSTM weights [k][d][c], c=r*4+g
__device__ float g_wc[6*64*384];       // comm QKV weights [k][d][n], n={q|k|v}, d padded to 64
__device__ float g_w8[128*128];        // fc/gate weights [d][c], c=r*2+s (s=0 fc, 1 gate), c padded 128

__device__ __forceinline__ float sigf(float x){ return 1.f/(1.f+expf(-x)); }

#define LOAD_FRAG(f, p) do { \
    *(float4*)&f[0] = *(const float4*)(p); \
    *(float4*)&f[4] = *(const float4*)((p)+4); } while(0)

#define FMA8x8(acc, af, bf) do { \
  _Pragma("unroll") for (int i_ = 0; i_ < 8; i_++) \
    _Pragma("unroll") for (int j_ = 0; j_ < 8; j_++) \
      acc[i_*8+j_] = fmaf(af[i_], bf[j_], acc[i_*8+j_]); } while(0)

#define CP_ASYNC16(dst, src) \
    asm volatile("cp.async.ca.shared.global [%0], [%1], 16;" :: "r"(dst), "l"(src))
#define CP_COMMIT() asm volatile("cp.async.commit_group;")
#define CP_WAIT0()  asm volatile("cp.async.wait_group 0;")

#define MMA_TF32(c0,c1,c2,c3, a0,a1,a2,a3, b0,b1) \
    asm volatile( \
        "mma.sync.aligned.m16n8k8.row.col.f32.tf32.tf32.f32 " \
        "{%0,%1,%2,%3}, {%4,%5,%6,%7}, {%8,%9}, {%0,%1,%2,%3};" \
        : "+f"(c0), "+f"(c1), "+f"(c2), "+f"(c3) \
        : "r"(a0), "r"(a1), "r"(a2), "r"(a3), "r"(b0), "r"(b1))

// ---------------- prep kernels ----------------
__global__ void prep_w4(const float* __restrict__ W_ih, const float* __restrict__ W_hh)
{
    int i = blockIdx.x*256 + threadIdx.x;        // < 6*304*256
    if (i >= 6*304*256) return;
    int k = i / (304*256); int rem = i % (304*256);
    int d = rem >> 8; int c = rem & 255;
    int r = c >> 2, g = c & 3;
    float v = 0.f;
    if (r < 60) {
        int rowW = g*360 + k*60 + r;
        if (d < 240)      v = W_ih[(size_t)rowW*1440 + k*240 + d];
        else if (d < 300) v = W_hh[(size_t)rowW*360 + k*60 + (d-240)];
    }
    g_w4[i] = v;
}

__global__ void prep_wc(const float* __restrict__ Wq_c,
                        const float* __restrict__ Wk_c,
                        const float* __restrict__ Wv_c)
{
    int i = blockIdx.x*256 + threadIdx.x;        // < 6*64*384 = 147456
    if (i >= 6*64*384) return;
    int k = i / (64*384); int rem = i % (64*384);
    int d = rem / 384; int n = rem % 384;
    float v = 0.f;
    if (d < 60) {
        const float* W = (n < 128) ? Wq_c : (n < 256) ? Wk_c : Wv_c;
        v = W[(size_t)k*7680 + d*128 + (n & 127)];
    }
    g_wc[i] = v;
}

__global__ void prep_w8(const float* __restrict__ fc_w, const float* __restrict__ gate_w)
{
    int i = blockIdx.x*256 + threadIdx.x;        // < 128*128
    if (i >= 128*128) return;
    int d = i >> 7, c = i & 127;
    int r = c >> 1, s = c & 1;
    float v = 0.f;
    if (r < 60) v = s ? gate_w[(size_t)r*128 + d] : fc_w[(size_t)r*128 + d];
    g_w8[i] = v;
}

// ---------------- K1a: Kproj  [B,768] @ [768,256]  (fp32 FFMA, pipelined) ----------------
// 128x128 tile, 256 thr, 8x8 micro, K-chunk 16, 48 chunks.
// B via cp.async (contiguous), A via register-staged prefetch (transposed store).
__global__ __launch_bounds__(256, 2) void k1a_kproj(const float* __restrict__ inp,
                          const float* __restrict__ Wk1)
{
    __shared__ __align__(16) float As[2][16*132];   // [d][m]
    __shared__ __align__(16) float Bs[2][16*132];   // [d][n]
    int tid = threadIdx.x;
    int tx = tid & 15, ty = tid >> 4;
    int m0 = blockIdx.y * 128;
    int n0 = blockIdx.x * 128;
    int am = tid >> 1;                // 0..127 row for A staging
    int ad = (tid & 1) * 8;           // d-half 0 or 8

    float acc[64];
#pragma unroll
    for (int i = 0; i < 64; i++) acc[i] = 0.f;

    float a_reg[8];
#define K1A_LOAD_A(CH) do { \
    const float4* p_ = (const float4*)(inp + (size_t)(m0+am)*768 + (CH)*16 + ad); \
    float4 u0_ = p_[0], u1_ = p_[1]; \
    a_reg[0]=u0_.x; a_reg[1]=u0_.y; a_reg[2]=u0_.z; a_reg[3]=u0_.w; \
    a_reg[4]=u1_.x; a_reg[5]=u1_.y; a_reg[6]=u1_.z; a_reg[7]=u1_.w; } while(0)
#define K1A_STORE_A(S) do { \
    _Pragma("unroll") for (int j_ = 0; j_ < 8; j_++) \
        As[S][(ad+j_)*132 + am] = a_reg[j_]; } while(0)
// B: 16 rows x 128 floats = 512 x 4-float copies = 2 x 256
#define K1A_CPB(CH, S) do { \
    _Pragma("unroll") for (int i_ = 0; i_ < 2; i_++) { \
        int e_ = tid + i_*256; \
        int dd_ = e_ >> 5, c4_ = (e_ & 31)*4; \
        unsigned dst_ = (unsigned)__cvta_generic_to_shared(&Bs[S][dd_*132 + c4_]); \
        CP_ASYNC16(dst_, Wk1 + (size_t)((CH)*16 + dd_)*256 + n0 + c4_); \
    } } while(0)

    K1A_LOAD_A(0);
    K1A_CPB(0, 0);
    K1A_STORE_A(0);
    CP_COMMIT();

    for (int ch = 0; ch < 48; ch++) {
        int cur = ch & 1;
        CP_WAIT0();
        __syncthreads();
        if (ch < 47) {
            K1A_LOAD_A(ch+1);
            K1A_CPB(ch+1, cur^1);
            CP_COMMIT();
        }
#pragma unroll
        for (int kk = 0; kk < 16; kk++) {
            float af[8], bf[8];
            LOAD_FRAG(af, &As[cur][kk*132 + ty*8]);
            LOAD_FRAG(bf, &Bs[cur][kk*132 + tx*8]);
            FMA8x8(acc, af, bf);
        }
        if (ch < 47) K1A_STORE_A(cur^1);
    }
#undef K1A_LOAD_A
#undef K1A_STORE_A
#undef K1A_CPB
#pragma unroll
    for (int i = 0; i < 8; i++) {
        int m = m0 + ty*8 + i;
#pragma unroll
        for (int j = 0; j < 8; j++)
            g_kv[(size_t)m*496 + n0 + tx*8 + j] = acc[i*8+j];
    }
}

// ---------------- K2: Q projection + fused score -> alpha (fp32, W pipelined) ----------------
// X tile (64x60) fully resident; W pipelined chunk 12 x 5 via cp.async.
__global__ __launch_bounds__(256, 2) void k2_qalpha(const float* __restrict__ hx,
                          const float* __restrict__ Wq)
{
    __shared__ __align__(16) float Xs[60*68];        // [d][m]
    __shared__ __align__(16) float Ws[2][12*260];    // [d][n]
    int tid = threadIdx.x;            // 256
    int tx = tid & 31, ty = tid >> 5;
    int m0 = blockIdx.x * 64;
    int k  = blockIdx.y;
    const float* Wk = Wq + (size_t)k*15360;

    // load all of X once (transposed)
    for (int e = tid; e < 64*60; e += 256) {
        int m = e / 60, dd = e % 60;
        Xs[dd*68 + m] = hx[(size_t)(m0+m)*360 + k*60 + dd];
    }

// W: 12 rows x 256 floats = 768 x 4-float copies = 3 x 256
#define K2_CPW(CH, S) do { \
    _Pragma("unroll") for (int i_ = 0; i_ < 3; i_++) { \
        int e_ = tid + i_*256; \
        int dd_ = e_ >> 6, c4_ = (e_ & 63)*4; \
        unsigned dst_ = (unsigned)__cvta_generic_to_shared(&Ws[S][dd_*260 + c4_]); \
        CP_ASYNC16(dst_, Wk + (size_t)((CH)*12 + dd_)*256 + c4_); \
    } } while(0)

    float acc[64];
#pragma unroll
    for (int i = 0; i < 64; i++) acc[i] = 0.f;

    K2_CPW(0, 0);
    CP_COMMIT();

    for (int ch = 0; ch < 5; ch++) {
        int cur = ch & 1;
        CP_WAIT0();
        __syncthreads();
        if (ch < 4) { K2_CPW(ch+1, cur^1); CP_COMMIT(); }
#pragma unroll
        for (int kk = 0; kk < 12; kk++) {
            float af[8], bf[8];
            LOAD_FRAG(af, &Xs[(ch*12 + kk)*68 + ty*8]);
            LOAD_FRAG(bf, &Ws[cur][kk*260 + tx*8]);
            FMA8x8(acc, af, bf);
        }
    }
#undef K2_CPW
    int h = tx >> 3, lane8 = tx & 7;
#pragma unroll
    for (int i = 0; i < 8; i++) {
        int gm = m0 + ty*8 + i;
        const float* kp = &g_kv[(size_t)gm*496 + h*64 + lane8*8];
        float s = 0.f;
#pragma unroll
        for (int j = 0; j < 8; j++) s += acc[i*8+j] * kp[j];
        s += __shfl_xor_sync(0xffffffffu, s, 1);
        s += __shfl_xor_sync(0xffffffffu, s, 2);
        s += __shfl_xor_sync(0xffffffffu, s, 4);
        if (lane8 == 0) g_alpha[(size_t)gm*24 + k*4 + h] = sigf(0.125f*s);
    }
}

// ---------------- K3: top-2 null mask ----------------
__global__ void k3_mask()
{
    int b = blockIdx.x*256 + threadIdx.x;
    float4 a0 = *(const float4*)&g_alpha[(size_t)b*24 + 0];
    float4 a1 = *(const float4*)&g_alpha[(size_t)b*24 + 4];
    float4 a2 = *(const float4*)&g_alpha[(size_t)b*24 + 8];
    float4 a3 = *(const float4*)&g_alpha[(size_t)b*24 + 12];
    float4 a4 = *(const float4*)&g_alpha[(size_t)b*24 + 16];
    float4 a5 = *(const float4*)&g_alpha[(size_t)b*24 + 20];
    float nul[6];
    nul[0] = 1.f - 0.25f*(a0.x+a0.y+a0.z+a0.w);
    nul[1] = 1.f - 0.25f*(a1.x+a1.y+a1.z+a1.w);
    nul[2] = 1.f - 0.25f*(a2.x+a2.y+a2.z+a2.w);
    nul[3] = 1.f - 0.25f*(a3.x+a3.y+a3.z+a3.w);
    nul[4] = 1.f - 0.25f*(a4.x+a4.y+a4.z+a4.w);
    nul[5] = 1.f - 0.25f*(a5.x+a5.y+a5.z+a5.w);
    int i1 = 0; float m1 = nul[0];
#pragma unroll
    for (int k = 1; k < 6; k++) if (nul[k] > m1) { m1 = nul[k]; i1 = k; }
    int i2 = -1; float m2 = -1e30f;
#pragma unroll
    for (int k = 0; k < 6; k++) if (k != i1 && nul[k] > m2) { m2 = nul[k]; i2 = k; }
#pragma unroll
    for (int k = 0; k < 6; k++)
        g_mask[(size_t)b*6 + k] = (k == i1 || k == i2) ? 0.f : 1.f;
}

// ---------------- K1b: Vproj  [B,768] @ [768,240]  (tf32 mma, pipelined) ----------------
__global__ __launch_bounds__(256, 1) void k1b_vproj(const float* __restrict__ inp,
                          const float* __restrict__ Wv1)
{
    __shared__ __align__(16) float As[2][64*20];
    __shared__ __align__(16) float Bs[2][16*264];
    int tid = threadIdx.x;
    int lane = tid & 31, warp = tid >> 5;
    int warp_m = warp >> 2, warp_n = warp & 3;
    int group = lane >> 2, tcol = lane & 3;
    int m0 = blockIdx.x * 64;

    for (int s = 0; s < 2; s++)
        for (int e = tid; e < 16*24; e += 256) {
            int dd = e / 24, c = 240 + e % 24;
            Bs[s][dd*264 + c] = 0.f;
        }

    float c_acc[2][8][4];
#pragma unroll
    for (int a = 0; a < 2; a++)
#pragma unroll
        for (int b = 0; b < 8; b++)
#pragma unroll
            for (int d = 0; d < 4; d++) c_acc[a][b][d] = 0.f;

#define K1B_PF(CH, S) do { \
    { int m_ = tid >> 2, seg_ = tid & 3; \
      unsigned dA_ = (unsigned)__cvta_generic_to_shared(&As[S][m_*20 + seg_*4]); \
      CP_ASYNC16(dA_, inp + (size_t)(m0+m_)*768 + (CH)*16 + seg_*4); } \
    _Pragma("unroll") \
    for (int i_ = 0; i_ < 4; i_++) { \
        int e_ = tid + i_*256; \
        if (e_ < 960) { \
            int dd_ = e_ / 60, c4_ = (e_ % 60)*4; \
            unsigned dB_ = (unsigned)__cvta_generic_to_shared(&Bs[S][dd_*264 + c4_]); \
            CP_ASYNC16(dB_, Wv1 + (size_t)((CH)*16 + dd_)*240 + c4_); \
        } \
    } } while(0)

    __syncthreads();
    K1B_PF(0, 0);
    CP_COMMIT();

    for (int ch = 0; ch < 48; ch++) {
        int cur = ch & 1;
        CP_WAIT0();
        __syncthreads();
        if (ch < 47) { K1B_PF(ch+1, cur^1); CP_COMMIT(); }
#pragma unroll
        for (int ks = 0; ks < 2; ks++) {
            int kb = ks*8;
            unsigned a_frag[2][4];
#pragma unroll
            for (int mf = 0; mf < 2; mf++) {
                int row0 = warp_m*32 + mf*16 + group;
                a_frag[mf][0] = __float_as_uint(As[cur][row0*20 + kb + tcol]);
                a_frag[mf][1] = __float_as_uint(As[cur][(row0+8)*20 + kb + tcol]);
                a_frag[mf][2] = __float_as_uint(As[cur][row0*20 + kb + tcol + 4]);
                a_frag[mf][3] = __float_as_uint(As[cur][(row0+8)*20 + kb + tcol + 4]);
            }
#pragma unroll
            for (int nf = 0; nf < 8; nf++) {
                int coln = warp_n*64 + nf*8 + group;
                unsigned b0 = __float_as_uint(Bs[cur][(kb + tcol)*264 + coln]);
                unsigned b1 = __float_as_uint(Bs[cur][(kb + tcol + 4)*264 + coln]);
#pragma unroll
                for (int mf = 0; mf < 2; mf++)
                    MMA_TF32(c_acc[mf][nf][0], c_acc[mf][nf][1], c_acc[mf][nf][2], c_acc[mf][nf][3],
                             a_frag[mf][0], a_frag[mf][1], a_frag[mf][2], a_frag[mf][3], b0, b1);
            }
        }
    }
#undef K1B_PF
#pragma unroll
    for (int mf = 0; mf < 2; mf++) {
#pragma unroll
        for (int nf = 0; nf < 8; nf++) {
            int c = warp_n*64 + nf*8 + tcol*2;
            if (c >= 240) continue;
            int r0 = m0 + warp_m*32 + mf*16 + group;
            g_kv[(size_t)r0*496 + 256 + c]     = c_acc[mf][nf][0];
            g_kv[(size_t)r0*496 + 256 + c + 1] = c_acc[mf][nf][1];
            g_kv[(size_t)(r0+8)*496 + 256 + c]     = c_acc[mf][nf][2];
            g_kv[(size_t)(r0+8)*496 + 256 + c + 1] = c_acc[mf][nf][3];
        }
    }
}

// ---------------- K4: pipelined tf32 mma gates GEMM + LSTM pointwise + cx_out ----------------
__global__ __launch_bounds__(256, 1) void k4_gates_lstm(const float* __restrict__ hx,
                              const float* __restrict__ cx,
                              const float* __restrict__ b_ih,
                              const float* __restrict__ b_hh,
                              float* __restrict__ out_cx)
{
    __shared__ __align__(16) float As[2][64*20];
    __shared__ __align__(16) float Bs[2][16*264];
    __shared__ float sbias[240];
    __shared__ float s_alpha[256];
    int tid = threadIdx.x;
    int lane = tid & 31, warp = tid >> 5;
    int warp_m = warp >> 2, warp_n = warp & 3;
    int group = lane >> 2, tcol = lane & 3;
    int m0 = blockIdx.x * 64;
    int k  = blockIdx.y;

    if (tid < 240) {
        int c = tid, r = c >> 2, g = c & 3;
        int rowW = g*360 + k*60 + r;
        sbias[c] = b_ih[rowW] + b_hh[rowW];
    }
    s_alpha[tid] = g_alpha[(size_t)(m0 + (tid >> 2))*24 + k*4 + (tid & 3)];
    __syncthreads();

    const float* w4k = g_w4 + (size_t)k*(304*256);

#define PREFETCH_A(CH, S) do { \
    _Pragma("unroll") \
    for (int i_ = 0; i_ < 4; i_++) { \
        int e_ = tid + i_*256; \
        int m_ = e_ >> 4, dd_ = e_ & 15; \
        int d_ = (CH)*16 + dd_; \
        float v_; \
        if (d_ < 240)      v_ = s_alpha[m_*4 + d_/60] * g_kv[(size_t)(m0+m_)*496 + 256 + d_]; \
        else if (d_ < 300) v_ = hx[(size_t)(m0+m_)*360 + k*60 + (d_-240)]; \
        else               v_ = 0.f; \
        As[S][m_*20 + dd_] = v_; \
    } } while(0)

#define PREFETCH_B(CH, S) do { \
    const float* src_ = w4k + (CH)*16*256; \
    _Pragma("unroll") \
    for (int i_ = 0; i_ < 4; i_++) { \
        int e_ = tid + i_*256; \
        int dd_ = e_ >> 6, c4_ = (e_ & 63)*4; \
        unsigned dst_ = (unsigned)__cvta_generic_to_shared(&Bs[S][dd_*264 + c4_]); \
        CP_ASYNC16(dst_, src_ + dd_*256 + c4_); \
    } } while(0)

    float c_acc[2][8][4];
#pragma unroll
    for (int a = 0; a < 2; a++)
#pragma unroll
        for (int b = 0; b < 8; b++)
#pragma unroll
            for (int d = 0; d < 4; d++) c_acc[a][b][d] = 0.f;

    PREFETCH_B(0, 0);
    PREFETCH_A(0, 0);
    CP_COMMIT();

    for (int ch = 0; ch < 19; ch++) {
        int cur = ch & 1;
        CP_WAIT0();
        __syncthreads();
        if (ch < 18) {
            PREFETCH_B(ch+1, cur^1);
            PREFETCH_A(ch+1, cur^1);
            CP_COMMIT();
        }
#pragma unroll
        for (int ks = 0; ks < 2; ks++) {
            int kb = ks*8;
            unsigned a_frag[2][4];
#pragma unroll
            for (int mf = 0; mf < 2; mf++) {
                int row0 = warp_m*32 + mf*16 + group;
                a_frag[mf][0] = __float_as_uint(As[cur][row0*20 + kb + tcol]);
                a_frag[mf][1] = __float_as_uint(As[cur][(row0+8)*20 + kb + tcol]);
                a_frag[mf][2] = __float_as_uint(As[cur][row0*20 + kb + tcol + 4]);
                a_frag[mf][3] = __float_as_uint(As[cur][(row0+8)*20 + kb + tcol + 4]);
            }
#pragma unroll
            for (int nf = 0; nf < 8; nf++) {
                int coln = warp_n*64 + nf*8 + group;
                unsigned b0 = __float_as_uint(Bs[cur][(kb + tcol)*264 + coln]);
                unsigned b1 = __float_as_uint(Bs[cur][(kb + tcol + 4)*264 + coln]);
#pragma unroll
                for (int mf = 0; mf < 2; mf++)
                    MMA_TF32(c_acc[mf][nf][0], c_acc[mf][nf][1], c_acc[mf][nf][2], c_acc[mf][nf][3],
                             a_frag[mf][0], a_frag[mf][1], a_frag[mf][2], a_frag[mf][3], b0, b1);
            }
        }
    }
#undef PREFETCH_A
#undef PREFETCH_B
#pragma unroll
    for (int mf = 0; mf < 2; mf++) {
#pragma unroll
        for (int nf = 0; nf < 8; nf++) {
            float x0 = c_acc[mf][nf][0], x1 = c_acc[mf][nf][1];
            float x2 = c_acc[mf][nf][2], x3 = c_acc[mf][nf][3];
            float y0 = __shfl_xor_sync(0xffffffffu, x0, 1);
            float y1 = __shfl_xor_sync(0xffffffffu, x1, 1);
            float y2 = __shfl_xor_sync(0xffffffffu, x2, 1);
            float y3 = __shfl_xor_sync(0xffffffffu, x3, 1);
            int r = warp_n*16 + nf*2 + (tcol >> 1);
            if (r >= 60) continue;
            float gi, gf, gg, go; int rowloc;
            if ((tcol & 1) == 0) {
                gi = x0; gf = x1; gg = y0; go = y1;
                rowloc = warp_m*32 + mf*16 + group;
            } else {
                gi = y2; gf = y3; gg = x2; go = x3;
                rowloc = warp_m*32 + mf*16 + group + 8;
            }
            gi += sbias[r*4 + 0];
            gf += sbias[r*4 + 1];
            gg += sbias[r*4 + 2];
            go += sbias[r*4 + 3];
            int b = m0 + rowloc;
            float msk = g_mask[(size_t)b*6 + k];
            size_t idx = (size_t)b*360 + k*60 + r;
            float c_old = cx[idx];
            float cn = sigf(gf)*c_old + sigf(gi)*tanhf(gg);
            float hn = sigf(go)*tanhf(cn);
            g_hxn[idx] = hn;
            out_cx[idx] = msk*cn + (1.f - msk)*c_old;
        }
    }
}

// ---------------- K6: tf32 mma comm QKV  [B,64] @ [64,384] per block ----------------
__global__ __launch_bounds__(256, 1) void k6_commqkv()
{
    __shared__ __align__(16) float As[2][64*20];
    __shared__ __align__(16) float Bs[2][16*200];
    int tid = threadIdx.x;
    int lane = tid & 31, warp = tid >> 5;
    int warp_m = warp >> 2, warp_n = warp & 3;
    int group = lane >> 2, tcol = lane & 3;
    int m0 = blockIdx.x * 64;
    int kblk = blockIdx.y;
    int bz = blockIdx.z;
    const float* wck = g_wc + (size_t)kblk*(64*384) + bz*192;

#define K6_PFA(CH, S) do { \
    _Pragma("unroll") \
    for (int i_ = 0; i_ < 4; i_++) { \
        int e_ = tid + i_*256; \
        int m_ = e_ >> 4, dd_ = e_ & 15; \
        int d_ = (CH)*16 + dd_; \
        As[S][m_*20 + dd_] = (d_ < 60) ? g_hxn[(size_t)(m0+m_)*360 + kblk*60 + d_] : 0.f; \
    } } while(0)

#define K6_PFB(CH, S) do { \
    _Pragma("unroll") \
    for (int i_ = 0; i_ < 3; i_++) { \
        int e_ = tid + i_*256; \
        int dd_ = e_ / 48, c4_ = (e_ % 48)*4; \
        unsigned dst_ = (unsigned)__cvta_generic_to_shared(&Bs[S][dd_*200 + c4_]); \
        CP_ASYNC16(dst_, wck + (size_t)((CH)*16 + dd_)*384 + c4_); \
    } } while(0)

    float c_acc[2][6][4];
#pragma unroll
    for (int a = 0; a < 2; a++)
#pragma unroll
        for (int b = 0; b < 6; b++)
#pragma unroll
            for (int d = 0; d < 4; d++) c_acc[a][b][d] = 0.f;

    K6_PFB(0, 0);
    K6_PFA(0, 0);
    CP_COMMIT();

    for (int ch = 0; ch < 4; ch++) {
        int cur = ch & 1;
        CP_WAIT0();
        __syncthreads();
        if (ch < 3) { K6_PFB(ch+1, cur^1); K6_PFA(ch+1, cur^1); CP_COMMIT(); }
#pragma unroll
        for (int ks = 0; ks < 2; ks++) {
            int kb = ks*8;
            unsigned a_frag[2][4];
#pragma unroll
            for (int mf = 0; mf < 2; mf++) {
                int row0 = warp_m*32 + mf*16 + group;
                a_frag[mf][0] = __float_as_uint(As[cur][row0*20 + kb + tcol]);
                a_frag[mf][1] = __float_as_uint(As[cur][(row0+8)*20 + kb + tcol]);
                a_frag[mf][2] = __float_as_uint(As[cur][row0*20 + kb + tcol + 4]);
                a_frag[mf][3] = __float_as_uint(As[cur][(row0+8)*20 + kb + tcol + 4]);
            }
#pragma unroll
            for (int nf = 0; nf < 6; nf++) {
                int coln = warp_n*48 + nf*8 + group;
                unsigned b0 = __float_as_uint(Bs[cur][(kb + tcol)*200 + coln]);
                unsigned b1 = __float_as_uint(Bs[cur][(kb + tcol + 4)*200 + coln]);
#pragma unroll
                for (int mf = 0; mf < 2; mf++)
                    MMA_TF32(c_acc[mf][nf][0], c_acc[mf][nf][1], c_acc[mf][nf][2], c_acc[mf][nf][3],
                             a_frag[mf][0], a_frag[mf][1], a_frag[mf][2], a_frag[mf][3], b0, b1);
            }
        }
    }
#undef K6_PFA
#undef K6_PFB
#pragma unroll
    for (int mf = 0; mf < 2; mf++) {
#pragma unroll
        for (int nf = 0; nf < 6; nf++) {
            int c = warp_n*48 + nf*8 + tcol*2;
            int r0 = m0 + warp_m*32 + mf*16 + group;
            size_t base = (size_t)kblk*384 + bz*192 + c;
            *(float2*)&g_qkvc[(size_t)r0*2304 + base]     = make_float2(c_acc[mf][nf][0], c_acc[mf][nf][1]);
            *(float2*)&g_qkvc[(size_t)(r0+8)*2304 + base] = make_float2(c_acc[mf][nf][2], c_acc[mf][nf][3]);
        }
    }
}

// ---------------- K7: communication attention (6 tokens, 4 heads x 32) ----------------
__global__ void k7_commattn()
{
    __shared__ float sq[4][2304];
    __shared__ float ss[4][144];
    int w = threadIdx.x >> 5, lane = threadIdx.x & 31;
    int b = blockIdx.x * 4 + w;
    const float4* src = (const float4*)(g_qkvc + (size_t)b*2304);
    float4* dst = (float4*)&sq[w][0];
    for (int t = lane; t < 576; t += 32) dst[t] = src[t];
    __syncwarp();

    const float inv = 0.17677669529663687f;  // 1/sqrt(32)
    for (int p = lane; p < 144; p += 32) {
        int h = p / 36, rem = p % 36, i = rem / 6, j = rem % 6;
        const float* qv = &sq[w][i*384 + h*32];
        const float* kv = &sq[w][j*384 + 128 + h*32];
        float s = 0.f;
#pragma unroll
        for (int c = 0; c < 32; c++) s += qv[c]*kv[c];
        ss[w][p] = s * inv;
    }
    __syncwarp();
    if (lane < 24) {
        float* row = &ss[w][lane*6];
        float mx = row[0];
#pragma unroll
        for (int j = 1; j < 6; j++) mx = fmaxf(mx, row[j]);
        float ev[6]; float sum = 0.f;
#pragma unroll
        for (int j = 0; j < 6; j++) { ev[j] = expf(row[j]-mx); sum += ev[j]; }
        float is = 1.f/sum;
#pragma unroll
        for (int j = 0; j < 6; j++) row[j] = ev[j]*is;
    }
    __syncwarp();
    for (int o = lane; o < 768; o += 32) {
        int i = o >> 7, rem = o & 127, h = rem >> 5, c = rem & 31;
        const float* att = &ss[w][h*36 + i*6];
        float acc = 0.f;
#pragma unroll
        for (int j = 0; j < 6; j++) acc += att[j]*sq[w][j*384 + 256 + h*32 + c];
        g_raw[(size_t)b*768 + o] = acc;
    }
}

// ---------------- K8: tf32 mma fc/gate GEMM + final hx_out ----------------
__global__ __launch_bounds__(256, 1) void k8_fcgate_out(const float* __restrict__ fc_b,
                              const float* __restrict__ gate_b,
                              const float* __restrict__ hx, float* __restrict__ out_hx)
{
    __shared__ __align__(16) float As[2][64*20];
    __shared__ __align__(16) float Bs[2][16*136];
    int tid = threadIdx.x;
    int lane = tid & 31, warp = tid >> 5;
    int warp_m = warp >> 2, warp_n = warp & 3;
    int group = lane >> 2, tcol = lane & 3;
    int m0 = blockIdx.x * 64;

#define K8_PFA(CH, S) do { \
    { int m_ = tid >> 2, seg_ = tid & 3; \
      unsigned dA_ = (unsigned)__cvta_generic_to_shared(&As[S][m_*20 + seg_*4]); \
      CP_ASYNC16(dA_, g_raw + (size_t)(m0+m_)*128 + (CH)*16 + seg_*4); } \
    } while(0)

#define K8_PFB(CH, S) do { \
    _Pragma("unroll") \
    for (int i_ = 0; i_ < 2; i_++) { \
        int e_ = tid + i_*256; \
        int dd_ = e_ >> 5, c4_ = (e_ & 31)*4; \
        unsigned dst_ = (unsigned)__cvta_generic_to_shared(&Bs[S][dd_*136 + c4_]); \
        CP_ASYNC16(dst_, g_w8 + (size_t)((CH)*16 + dd_)*128 + c4_); \
    } } while(0)

    float c_acc[2][4][4];
#pragma unroll
    for (int a = 0; a < 2; a++)
#pragma unroll
        for (int b = 0; b < 4; b++)
#pragma unroll
            for (int d = 0; d < 4; d++) c_acc[a][b][d] = 0.f;

    K8_PFB(0, 0);
    K8_PFA(0, 0);
    CP_COMMIT();

    for (int ch = 0; ch < 8; ch++) {
        int cur = ch & 1;
        CP_WAIT0();
        __syncthreads();
        if (ch < 7) { K8_PFB(ch+1, cur^1); K8_PFA(ch+1, cur^1); CP_COMMIT(); }
#pragma unroll
        for (int ks = 0; ks < 2; ks++) {
            int kb = ks*8;
            unsigned a_frag[2][4];
#pragma unroll
            for (int mf = 0; mf < 2; mf++) {
                int row0 = warp_m*32 + mf*16 + group;
                a_frag[mf][0] = __float_as_uint(As[cur][row0*20 + kb + tcol]);
                a_frag[mf][1] = __float_as_uint(As[cur][(row0+8)*20 + kb + tcol]);
                a_frag[mf][2] = __float_as_uint(As[cur][row0*20 + kb + tcol + 4]);
                a_frag[mf][3] = __float_as_uint(As[cur][(row0+8)*20 + kb + tcol + 4]);
            }
#pragma unroll
            for (int nf = 0; nf < 4; nf++) {
                int coln = warp_n*32 + nf*8 + group;
                unsigned b0 = __float_as_uint(Bs[cur][(kb + tcol)*136 + coln]);
                unsigned b1 = __float_as_uint(Bs[cur][(kb + tcol + 4)*136 + coln]);
#pragma unroll
                for (int mf = 0; mf < 2; mf++)
                    MMA_TF32(c_acc[mf][nf][0], c_acc[mf][nf][1], c_acc[mf][nf][2], c_acc[mf][nf][3],
                             a_frag[mf][0], a_frag[mf][1], a_frag[mf][2], a_frag[mf][3], b0, b1);
            }
        }
    }
#undef K8_PFA
#undef K8_PFB
#pragma unroll
    for (int mf = 0; mf < 2; mf++) {
#pragma unroll
        for (int nf = 0; nf < 4; nf++) {
            int c = warp_n*32 + nf*8 + tcol*2;
            int r = c >> 1;
            if (r >= 60) continue;
            float fb = fc_b[r], gb = gate_b[r];
#pragma unroll
            for (int half = 0; half < 2; half++) {
                int m = m0 + warp_m*32 + mf*16 + group + half*8;
                float fc = c_acc[mf][nf][half*2]     + fb;
                float gt = c_acc[mf][nf][half*2 + 1] + gb;
                float att = sigf(gt) * tanhf(fc);
                int b = m / 6, kb = m % 6;
                float msk = g_mask[m];
                size_t idx = (size_t)b*360 + kb*60 + r;
                float hn = g_hxn[idx];
                float ho = hx[idx];
                out_hx[idx] = msk*(hn + att) + (1.f - msk)*ho;
            }
        }
    }
}

// ---------------- launch ----------------
extern "C" void kernel_launch(void* const* d_in, const int* in_sizes, int n_in,
                              void* d_out, int out_size)
{
    const float* inp    = (const float*)d_in[0];
    const float* hx     = (const float*)d_in[1];
    const float* cx     = (const float*)d_in[2];
    const float* Wq_inp = (const float*)d_in[3];
    const float* Wk_inp = (const float*)d_in[4];
    const float* Wv_inp = (const float*)d_in[5];
    const float* Wq_c   = (const float*)d_in[6];
    const float* Wk_c   = (const float*)d_in[7];
    const float* Wv_c   = (const float*)d_in[8];
    const float* fc_w   = (const float*)d_in[9];
    const float* fc_b   = (const float*)d_in[10];
    const float* gate_w = (const float*)d_in[11];
    const float* gate_b = (const float*)d_in[12];
    const float* W_ih   = (const float*)d_in[13];
    const float* W_hh   = (const float*)d_in[14];
    const float* b_ih   = (const float*)d_in[15];
    const float* b_hh   = (const float*)d_in[16];

    float* out_hx = (float*)d_out;
    float* out_cx = (float*)d_out + (size_t)BATCH*360;

    prep_w4<<<1824, 256>>>(W_ih, W_hh);
    prep_wc<<<576, 256>>>(Wq_c, Wk_c, Wv_c);
    prep_w8<<<64, 256>>>(fc_w, gate_w);
    k1a_kproj<<<dim3(2, 128), 256>>>(inp, Wk_inp + 768*256);
    k1b_vproj<<<256, 256>>>(inp, Wv_inp + 768*240);
    k2_qalpha<<<dim3(256, 6), 256>>>(hx, Wq_inp);
    k3_mask<<<64, 256>>>();
    k4_gates_lstm<<<dim3(256, 6), 256>>>(hx, cx, b_ih, b_hh, out_cx);
    k6_commqkv<<<dim3(256, 6, 2), 256>>>();
    k7_commattn<<<BATCH/4, 128>>>();
    k8_fcgate_out<<<1536, 256>>>(fc_b, gate_b, hx, out_hx);
}

// round 14
// speedup vs baseline: 2.2197x; 1.2255x over previous
#include <cuda_runtime.h>
#include <math.h>

#define BATCH 16384
#define NINP  768
#define NHID  360
#define NBLK  6
#define BSZ   60

// ---------------- scratch ----------------
__device__ float g_kv[BATCH*496];      // [b][0:256]=Kproj (4 heads x64), [256:496]=Vproj (4 heads x60)
__device__ float g_alpha[BATCH*24];    // [b][k*4+h] = sigma(score)
__device__ float g_mask[BATCH*6];      // 0/1
__device__ float g_hxn[BATCH*360];     // LSTM hx_new (pre comm-attn)
__device__ float g_qkvc[BATCH*2304];   // [b][k*384 + {0:q,128:k,256:v}]
__device__ float g_raw[BATCH*768];     // [b][i*128 + h*32 + c]
__device__ float g_w4[6*304*256];      // LSTM weights [k][d][c], c=r*4+g
__device__ float g_wc[6*64*384];       // comm QKV weights [k][d][n], n={q|k|v}, d padded to 64
__device__ float g_w8[128*128];        // fc/gate weights [d][c], c=r*2+s (s=0 fc, 1 gate), c padded 128

__device__ __forceinline__ float sigf(float x){ return 1.f/(1.f+expf(-x)); }

#define LOAD_FRAG(f, p) do { \
    *(float4*)&f[0] = *(const float4*)(p); \
    *(float4*)&f[4] = *(const float4*)((p)+4); } while(0)

#define FMA8x8(acc, af, bf) do { \
  _Pragma("unroll") for (int i_ = 0; i_ < 8; i_++) \
    _Pragma("unroll") for (int j_ = 0; j_ < 8; j_++) \
      acc[i_*8+j_] = fmaf(af[i_], bf[j_], acc[i_*8+j_]); } while(0)

#define CP_ASYNC16(dst, src) \
    asm volatile("cp.async.ca.shared.global [%0], [%1], 16;" :: "r"(dst), "l"(src))
#define CP_COMMIT() asm volatile("cp.async.commit_group;")
#define CP_WAIT0()  asm volatile("cp.async.wait_group 0;")

#define MMA_TF32(c0,c1,c2,c3, a0,a1,a2,a3, b0,b1) \
    asm volatile( \
        "mma.sync.aligned.m16n8k8.row.col.f32.tf32.tf32.f32 " \
        "{%0,%1,%2,%3}, {%4,%5,%6,%7}, {%8,%9}, {%0,%1,%2,%3};" \
        : "+f"(c0), "+f"(c1), "+f"(c2), "+f"(c3) \
        : "r"(a0), "r"(a1), "r"(a2), "r"(a3), "r"(b0), "r"(b1))

// ---------------- prep kernels ----------------
__global__ void prep_w4(const float* __restrict__ W_ih, const float* __restrict__ W_hh)
{
    int i = blockIdx.x*256 + threadIdx.x;        // < 6*304*256
    if (i >= 6*304*256) return;
    int k = i / (304*256); int rem = i % (304*256);
    int d = rem >> 8; int c = rem & 255;
    int r = c >> 2, g = c & 3;
    float v = 0.f;
    if (r < 60) {
        int rowW = g*360 + k*60 + r;
        if (d < 240)      v = W_ih[(size_t)rowW*1440 + k*240 + d];
        else if (d < 300) v = W_hh[(size_t)rowW*360 + k*60 + (d-240)];
    }
    g_w4[i] = v;
}

__global__ void prep_wc(const float* __restrict__ Wq_c,
                        const float* __restrict__ Wk_c,
                        const float* __restrict__ Wv_c)
{
    int i = blockIdx.x*256 + threadIdx.x;        // < 6*64*384 = 147456
    if (i >= 6*64*384) return;
    int k = i / (64*384); int rem = i % (64*384);
    int d = rem / 384; int n = rem % 384;
    float v = 0.f;
    if (d < 60) {
        const float* W = (n < 128) ? Wq_c : (n < 256) ? Wk_c : Wv_c;
        v = W[(size_t)k*7680 + d*128 + (n & 127)];
    }
    g_wc[i] = v;
}

__global__ void prep_w8(const float* __restrict__ fc_w, const float* __restrict__ gate_w)
{
    int i = blockIdx.x*256 + threadIdx.x;        // < 128*128
    if (i >= 128*128) return;
    int d = i >> 7, c = i & 127;
    int r = c >> 1, s = c & 1;
    float v = 0.f;
    if (r < 60) v = s ? gate_w[(size_t)r*128 + d] : fc_w[(size_t)r*128 + d];
    g_w8[i] = v;
}

// ---------------- K1a: Kproj  [B,768] @ [768,256]  (fp32 FFMA, pipelined) ----------------
__global__ __launch_bounds__(256, 2) void k1a_kproj(const float* __restrict__ inp,
                          const float* __restrict__ Wk1)
{
    __shared__ __align__(16) float As[2][16*132];   // [d][m]
    __shared__ __align__(16) float Bs[2][16*132];   // [d][n]
    int tid = threadIdx.x;
    int tx = tid & 15, ty = tid >> 4;
    int m0 = blockIdx.y * 128;
    int n0 = blockIdx.x * 128;
    int am = tid >> 1;
    int ad = (tid & 1) * 8;

    float acc[64];
#pragma unroll
    for (int i = 0; i < 64; i++) acc[i] = 0.f;

    float a_reg[8];
#define K1A_LOAD_A(CH) do { \
    const float4* p_ = (const float4*)(inp + (size_t)(m0+am)*768 + (CH)*16 + ad); \
    float4 u0_ = p_[0], u1_ = p_[1]; \
    a_reg[0]=u0_.x; a_reg[1]=u0_.y; a_reg[2]=u0_.z; a_reg[3]=u0_.w; \
    a_reg[4]=u1_.x; a_reg[5]=u1_.y; a_reg[6]=u1_.z; a_reg[7]=u1_.w; } while(0)
#define K1A_STORE_A(S) do { \
    _Pragma("unroll") for (int j_ = 0; j_ < 8; j_++) \
        As[S][(ad+j_)*132 + am] = a_reg[j_]; } while(0)
#define K1A_CPB(CH, S) do { \
    _Pragma("unroll") for (int i_ = 0; i_ < 2; i_++) { \
        int e_ = tid + i_*256; \
        int dd_ = e_ >> 5, c4_ = (e_ & 31)*4; \
        unsigned dst_ = (unsigned)__cvta_generic_to_shared(&Bs[S][dd_*132 + c4_]); \
        CP_ASYNC16(dst_, Wk1 + (size_t)((CH)*16 + dd_)*256 + n0 + c4_); \
    } } while(0)

    K1A_LOAD_A(0);
    K1A_CPB(0, 0);
    K1A_STORE_A(0);
    CP_COMMIT();

    for (int ch = 0; ch < 48; ch++) {
        int cur = ch & 1;
        CP_WAIT0();
        __syncthreads();
        if (ch < 47) {
            K1A_LOAD_A(ch+1);
            K1A_CPB(ch+1, cur^1);
            CP_COMMIT();
        }
#pragma unroll
        for (int kk = 0; kk < 16; kk++) {
            float af[8], bf[8];
            LOAD_FRAG(af, &As[cur][kk*132 + ty*8]);
            LOAD_FRAG(bf, &Bs[cur][kk*132 + tx*8]);
            FMA8x8(acc, af, bf);
        }
        if (ch < 47) K1A_STORE_A(cur^1);
    }
#undef K1A_LOAD_A
#undef K1A_STORE_A
#undef K1A_CPB
#pragma unroll
    for (int i = 0; i < 8; i++) {
        int m = m0 + ty*8 + i;
#pragma unroll
        for (int j = 0; j < 8; j++)
            g_kv[(size_t)m*496 + n0 + tx*8 + j] = acc[i*8+j];
    }
}

// ---------------- K2: Q projection + fused score -> alpha (fp32, W pipelined) ----------------
__global__ __launch_bounds__(256, 2) void k2_qalpha(const float* __restrict__ hx,
                          const float* __restrict__ Wq)
{
    __shared__ __align__(16) float Xs[60*68];        // [d][m]
    __shared__ __align__(16) float Ws[2][12*260];    // [d][n]
    int tid = threadIdx.x;            // 256
    int tx = tid & 31, ty = tid >> 5;
    int m0 = blockIdx.x * 64;
    int k  = blockIdx.y;
    const float* Wk = Wq + (size_t)k*15360;

    for (int e = tid; e < 64*60; e += 256) {
        int m = e / 60, dd = e % 60;
        Xs[dd*68 + m] = hx[(size_t)(m0+m)*360 + k*60 + dd];
    }

#define K2_CPW(CH, S) do { \
    _Pragma("unroll") for (int i_ = 0; i_ < 3; i_++) { \
        int e_ = tid + i_*256; \
        int dd_ = e_ >> 6, c4_ = (e_ & 63)*4; \
        unsigned dst_ = (unsigned)__cvta_generic_to_shared(&Ws[S][dd_*260 + c4_]); \
        CP_ASYNC16(dst_, Wk + (size_t)((CH)*12 + dd_)*256 + c4_); \
    } } while(0)

    float acc[64];
#pragma unroll
    for (int i = 0; i < 64; i++) acc[i] = 0.f;

    K2_CPW(0, 0);
    CP_COMMIT();

    for (int ch = 0; ch < 5; ch++) {
        int cur = ch & 1;
        CP_WAIT0();
        __syncthreads();
        if (ch < 4) { K2_CPW(ch+1, cur^1); CP_COMMIT(); }
#pragma unroll
        for (int kk = 0; kk < 12; kk++) {
            float af[8], bf[8];
            LOAD_FRAG(af, &Xs[(ch*12 + kk)*68 + ty*8]);
            LOAD_FRAG(bf, &Ws[cur][kk*260 + tx*8]);
            FMA8x8(acc, af, bf);
        }
    }
#undef K2_CPW
    int h = tx >> 3, lane8 = tx & 7;
#pragma unroll
    for (int i = 0; i < 8; i++) {
        int gm = m0 + ty*8 + i;
        const float* kp = &g_kv[(size_t)gm*496 + h*64 + lane8*8];
        float s = 0.f;
#pragma unroll
        for (int j = 0; j < 8; j++) s += acc[i*8+j] * kp[j];
        s += __shfl_xor_sync(0xffffffffu, s, 1);
        s += __shfl_xor_sync(0xffffffffu, s, 2);
        s += __shfl_xor_sync(0xffffffffu, s, 4);
        if (lane8 == 0) g_alpha[(size_t)gm*24 + k*4 + h] = sigf(0.125f*s);
    }
}

// ---------------- K3: top-2 null mask ----------------
__global__ void k3_mask()
{
    int b = blockIdx.x*256 + threadIdx.x;
    float4 a0 = *(const float4*)&g_alpha[(size_t)b*24 + 0];
    float4 a1 = *(const float4*)&g_alpha[(size_t)b*24 + 4];
    float4 a2 = *(const float4*)&g_alpha[(size_t)b*24 + 8];
    float4 a3 = *(const float4*)&g_alpha[(size_t)b*24 + 12];
    float4 a4 = *(const float4*)&g_alpha[(size_t)b*24 + 16];
    float4 a5 = *(const float4*)&g_alpha[(size_t)b*24 + 20];
    float nul[6];
    nul[0] = 1.f - 0.25f*(a0.x+a0.y+a0.z+a0.w);
    nul[1] = 1.f - 0.25f*(a1.x+a1.y+a1.z+a1.w);
    nul[2] = 1.f - 0.25f*(a2.x+a2.y+a2.z+a2.w);
    nul[3] = 1.f - 0.25f*(a3.x+a3.y+a3.z+a3.w);
    nul[4] = 1.f - 0.25f*(a4.x+a4.y+a4.z+a4.w);
    nul[5] = 1.f - 0.25f*(a5.x+a5.y+a5.z+a5.w);
    int i1 = 0; float m1 = nul[0];
#pragma unroll
    for (int k = 1; k < 6; k++) if (nul[k] > m1) { m1 = nul[k]; i1 = k; }
    int i2 = -1; float m2 = -1e30f;
#pragma unroll
    for (int k = 0; k < 6; k++) if (k != i1 && nul[k] > m2) { m2 = nul[k]; i2 = k; }
#pragma unroll
    for (int k = 0; k < 6; k++)
        g_mask[(size_t)b*6 + k] = (k == i1 || k == i2) ? 0.f : 1.f;
}

// ---------------- K1b: Vproj  [B,768] @ [768,240]  (tf32 mma, pipelined) ----------------
__global__ __launch_bounds__(256, 1) void k1b_vproj(const float* __restrict__ inp,
                          const float* __restrict__ Wv1)
{
    __shared__ __align__(16) float As[2][64*20];
    __shared__ __align__(16) float Bs[2][16*264];
    int tid = threadIdx.x;
    int lane = tid & 31, warp = tid >> 5;
    int warp_m = warp >> 2, warp_n = warp & 3;
    int group = lane >> 2, tcol = lane & 3;
    int m0 = blockIdx.x * 64;

    for (int s = 0; s < 2; s++)
        for (int e = tid; e < 16*24; e += 256) {
            int dd = e / 24, c = 240 + e % 24;
            Bs[s][dd*264 + c] = 0.f;
        }

    float c_acc[2][8][4];
#pragma unroll
    for (int a = 0; a < 2; a++)
#pragma unroll
        for (int b = 0; b < 8; b++)
#pragma unroll
            for (int d = 0; d < 4; d++) c_acc[a][b][d] = 0.f;

#define K1B_PF(CH, S) do { \
    { int m_ = tid >> 2, seg_ = tid & 3; \
      unsigned dA_ = (unsigned)__cvta_generic_to_shared(&As[S][m_*20 + seg_*4]); \
      CP_ASYNC16(dA_, inp + (size_t)(m0+m_)*768 + (CH)*16 + seg_*4); } \
    _Pragma("unroll") \
    for (int i_ = 0; i_ < 4; i_++) { \
        int e_ = tid + i_*256; \
        if (e_ < 960) { \
            int dd_ = e_ / 60, c4_ = (e_ % 60)*4; \
            unsigned dB_ = (unsigned)__cvta_generic_to_shared(&Bs[S][dd_*264 + c4_]); \
            CP_ASYNC16(dB_, Wv1 + (size_t)((CH)*16 + dd_)*240 + c4_); \
        } \
    } } while(0)

    __syncthreads();
    K1B_PF(0, 0);
    CP_COMMIT();

    for (int ch = 0; ch < 48; ch++) {
        int cur = ch & 1;
        CP_WAIT0();
        __syncthreads();
        if (ch < 47) { K1B_PF(ch+1, cur^1); CP_COMMIT(); }
#pragma unroll
        for (int ks = 0; ks < 2; ks++) {
            int kb = ks*8;
            unsigned a_frag[2][4];
#pragma unroll
            for (int mf = 0; mf < 2; mf++) {
                int row0 = warp_m*32 + mf*16 + group;
                a_frag[mf][0] = __float_as_uint(As[cur][row0*20 + kb + tcol]);
                a_frag[mf][1] = __float_as_uint(As[cur][(row0+8)*20 + kb + tcol]);
                a_frag[mf][2] = __float_as_uint(As[cur][row0*20 + kb + tcol + 4]);
                a_frag[mf][3] = __float_as_uint(As[cur][(row0+8)*20 + kb + tcol + 4]);
            }
#pragma unroll
            for (int nf = 0; nf < 8; nf++) {
                int coln = warp_n*64 + nf*8 + group;
                unsigned b0 = __float_as_uint(Bs[cur][(kb + tcol)*264 + coln]);
                unsigned b1 = __float_as_uint(Bs[cur][(kb + tcol + 4)*264 + coln]);
#pragma unroll
                for (int mf = 0; mf < 2; mf++)
                    MMA_TF32(c_acc[mf][nf][0], c_acc[mf][nf][1], c_acc[mf][nf][2], c_acc[mf][nf][3],
                             a_frag[mf][0], a_frag[mf][1], a_frag[mf][2], a_frag[mf][3], b0, b1);
            }
        }
    }
#undef K1B_PF
#pragma unroll
    for (int mf = 0; mf < 2; mf++) {
#pragma unroll
        for (int nf = 0; nf < 8; nf++) {
            int c = warp_n*64 + nf*8 + tcol*2;
            if (c >= 240) continue;
            int r0 = m0 + warp_m*32 + mf*16 + group;
            g_kv[(size_t)r0*496 + 256 + c]     = c_acc[mf][nf][0];
            g_kv[(size_t)r0*496 + 256 + c + 1] = c_acc[mf][nf][1];
            g_kv[(size_t)(r0+8)*496 + 256 + c]     = c_acc[mf][nf][2];
            g_kv[(size_t)(r0+8)*496 + 256 + c + 1] = c_acc[mf][nf][3];
        }
    }
}

// ---------------- K4: pipelined tf32 mma gates GEMM + LSTM pointwise + cx_out ----------------
// A staged RAW via cp.async (V | hx | 0); alpha applied at fragment load from s_alpha5 (idx4=1).
__global__ __launch_bounds__(256, 1) void k4_gates_lstm(const float* __restrict__ hx,
                              const float* __restrict__ cx,
                              const float* __restrict__ b_ih,
                              const float* __restrict__ b_hh,
                              float* __restrict__ out_cx)
{
    __shared__ __align__(16) float As[2][64*20];
    __shared__ __align__(16) float Bs[2][16*264];
    __shared__ float sbias[240];
    __shared__ float s_alpha5[320];   // [m][5], col 4 = 1.0 (hx region)
    int tid = threadIdx.x;
    int lane = tid & 31, warp = tid >> 5;
    int warp_m = warp >> 2, warp_n = warp & 3;
    int group = lane >> 2, tcol = lane & 3;
    int m0 = blockIdx.x * 64;
    int k  = blockIdx.y;

    if (tid < 240) {
        int c = tid, r = c >> 2, g = c & 3;
        int rowW = g*360 + k*60 + r;
        sbias[c] = b_ih[rowW] + b_hh[rowW];
    }
    for (int e = tid; e < 320; e += 256) {
        int m = e / 5, j = e % 5;
        s_alpha5[e] = (j < 4) ? g_alpha[(size_t)(m0+m)*24 + k*4 + j] : 1.f;
    }
    __syncthreads();

    const float* w4k = g_w4 + (size_t)k*(304*256);

#define PREFETCH_A(CH, S) do { \
    int m_ = tid >> 2, seg_ = tid & 3; \
    int d0_ = (CH)*16 + seg_*4; \
    unsigned dA_ = (unsigned)__cvta_generic_to_shared(&As[S][m_*20 + seg_*4]); \
    if (d0_ < 240)      { CP_ASYNC16(dA_, g_kv + (size_t)(m0+m_)*496 + 256 + d0_); } \
    else if (d0_ < 300) { CP_ASYNC16(dA_, hx + (size_t)(m0+m_)*360 + k*60 + (d0_-240)); } \
    else *(float4*)&As[S][m_*20 + seg_*4] = make_float4(0.f,0.f,0.f,0.f); \
    } while(0)

#define PREFETCH_B(CH, S) do { \
    const float* src_ = w4k + (CH)*16*256; \
    _Pragma("unroll") \
    for (int i_ = 0; i_ < 4; i_++) { \
        int e_ = tid + i_*256; \
        int dd_ = e_ >> 6, c4_ = (e_ & 63)*4; \
        unsigned dst_ = (unsigned)__cvta_generic_to_shared(&Bs[S][dd_*264 + c4_]); \
        CP_ASYNC16(dst_, src_ + dd_*256 + c4_); \
    } } while(0)

    float c_acc[2][8][4];
#pragma unroll
    for (int a = 0; a < 2; a++)
#pragma unroll
        for (int b = 0; b < 8; b++)
#pragma unroll
            for (int d = 0; d < 4; d++) c_acc[a][b][d] = 0.f;

    PREFETCH_B(0, 0);
    PREFETCH_A(0, 0);
    CP_COMMIT();

    int row0a = warp_m*32 + group;      // mf=0 base row
    for (int ch = 0; ch < 19; ch++) {
        int cur = ch & 1;
        CP_WAIT0();
        __syncthreads();
        if (ch < 18) {
            PREFETCH_B(ch+1, cur^1);
            PREFETCH_A(ch+1, cur^1);
            CP_COMMIT();
        }
#pragma unroll
        for (int ks = 0; ks < 2; ks++) {
            int kb = ks*8;
            int dlo = ch*16 + kb + tcol;
            int dhi = dlo + 4;
            int hlo = dlo/60; if (hlo > 4) hlo = 4;
            int hhi = dhi/60; if (hhi > 4) hhi = 4;
            unsigned a_frag[2][4];
#pragma unroll
            for (int mf = 0; mf < 2; mf++) {
                int row0 = row0a + mf*16;
                float m0lo = s_alpha5[row0*5 + hlo];
                float m1lo = s_alpha5[(row0+8)*5 + hlo];
                float m0hi = s_alpha5[row0*5 + hhi];
                float m1hi = s_alpha5[(row0+8)*5 + hhi];
                a_frag[mf][0] = __float_as_uint(As[cur][row0*20 + kb + tcol] * m0lo);
                a_frag[mf][1] = __float_as_uint(As[cur][(row0+8)*20 + kb + tcol] * m1lo);
                a_frag[mf][2] = __float_as_uint(As[cur][row0*20 + kb + tcol + 4] * m0hi);
                a_frag[mf][3] = __float_as_uint(As[cur][(row0+8)*20 + kb + tcol + 4] * m1hi);
            }
#pragma unroll
            for (int nf = 0; nf < 8; nf++) {
                int coln = warp_n*64 + nf*8 + group;
                unsigned b0 = __float_as_uint(Bs[cur][(kb + tcol)*264 + coln]);
                unsigned b1 = __float_as_uint(Bs[cur][(kb + tcol + 4)*264 + coln]);
#pragma unroll
                for (int mf = 0; mf < 2; mf++)
                    MMA_TF32(c_acc[mf][nf][0], c_acc[mf][nf][1], c_acc[mf][nf][2], c_acc[mf][nf][3],
                             a_frag[mf][0], a_frag[mf][1], a_frag[mf][2], a_frag[mf][3], b0, b1);
            }
        }
    }
#undef PREFETCH_A
#undef PREFETCH_B
#pragma unroll
    for (int mf = 0; mf < 2; mf++) {
#pragma unroll
        for (int nf = 0; nf < 8; nf++) {
            float x0 = c_acc[mf][nf][0], x1 = c_acc[mf][nf][1];
            float x2 = c_acc[mf][nf][2], x3 = c_acc[mf][nf][3];
            float y0 = __shfl_xor_sync(0xffffffffu, x0, 1);
            float y1 = __shfl_xor_sync(0xffffffffu, x1, 1);
            float y2 = __shfl_xor_sync(0xffffffffu, x2, 1);
            float y3 = __shfl_xor_sync(0xffffffffu, x3, 1);
            int r = warp_n*16 + nf*2 + (tcol >> 1);
            if (r >= 60) continue;
            float gi, gf, gg, go; int rowloc;
            if ((tcol & 1) == 0) {
                gi = x0; gf = x1; gg = y0; go = y1;
                rowloc = warp_m*32 + mf*16 + group;
            } else {
                gi = y2; gf = y3; gg = x2; go = x3;
                rowloc = warp_m*32 + mf*16 + group + 8;
            }
            gi += sbias[r*4 + 0];
            gf += sbias[r*4 + 1];
            gg += sbias[r*4 + 2];
            go += sbias[r*4 + 3];
            int b = m0 + rowloc;
            float msk = g_mask[(size_t)b*6 + k];
            size_t idx = (size_t)b*360 + k*60 + r;
            float c_old = cx[idx];
            float cn = sigf(gf)*c_old + sigf(gi)*tanhf(gg);
            float hn = sigf(go)*tanhf(cn);
            g_hxn[idx] = hn;
            out_cx[idx] = msk*cn + (1.f - msk)*c_old;
        }
    }
}

// ---------------- K6: tf32 mma comm QKV  [B,64] @ [64,384] per block ----------------
__global__ __launch_bounds__(256, 1) void k6_commqkv()
{
    __shared__ __align__(16) float As[2][64*20];
    __shared__ __align__(16) float Bs[2][16*200];
    int tid = threadIdx.x;
    int lane = tid & 31, warp = tid >> 5;
    int warp_m = warp >> 2, warp_n = warp & 3;
    int group = lane >> 2, tcol = lane & 3;
    int m0 = blockIdx.x * 64;
    int kblk = blockIdx.y;
    int bz = blockIdx.z;
    const float* wck = g_wc + (size_t)kblk*(64*384) + bz*192;

#define K6_PFA(CH, S) do { \
    _Pragma("unroll") \
    for (int i_ = 0; i_ < 4; i_++) { \
        int e_ = tid + i_*256; \
        int m_ = e_ >> 4, dd_ = e_ & 15; \
        int d_ = (CH)*16 + dd_; \
        As[S][m_*20 + dd_] = (d_ < 60) ? g_hxn[(size_t)(m0+m_)*360 + kblk*60 + d_] : 0.f; \
    } } while(0)

#define K6_PFB(CH, S) do { \
    _Pragma("unroll") \
    for (int i_ = 0; i_ < 3; i_++) { \
        int e_ = tid + i_*256; \
        int dd_ = e_ / 48, c4_ = (e_ % 48)*4; \
        unsigned dst_ = (unsigned)__cvta_generic_to_shared(&Bs[S][dd_*200 + c4_]); \
        CP_ASYNC16(dst_, wck + (size_t)((CH)*16 + dd_)*384 + c4_); \
    } } while(0)

    float c_acc[2][6][4];
#pragma unroll
    for (int a = 0; a < 2; a++)
#pragma unroll
        for (int b = 0; b < 6; b++)
#pragma unroll
            for (int d = 0; d < 4; d++) c_acc[a][b][d] = 0.f;

    K6_PFB(0, 0);
    K6_PFA(0, 0);
    CP_COMMIT();

    for (int ch = 0; ch < 4; ch++) {
        int cur = ch & 1;
        CP_WAIT0();
        __syncthreads();
        if (ch < 3) { K6_PFB(ch+1, cur^1); K6_PFA(ch+1, cur^1); CP_COMMIT(); }
#pragma unroll
        for (int ks = 0; ks < 2; ks++) {
            int kb = ks*8;
            unsigned a_frag[2][4];
#pragma unroll
            for (int mf = 0; mf < 2; mf++) {
                int row0 = warp_m*32 + mf*16 + group;
                a_frag[mf][0] = __float_as_uint(As[cur][row0*20 + kb + tcol]);
                a_frag[mf][1] = __float_as_uint(As[cur][(row0+8)*20 + kb + tcol]);
                a_frag[mf][2] = __float_as_uint(As[cur][row0*20 + kb + tcol + 4]);
                a_frag[mf][3] = __float_as_uint(As[cur][(row0+8)*20 + kb + tcol + 4]);
            }
#pragma unroll
            for (int nf = 0; nf < 6; nf++) {
                int coln = warp_n*48 + nf*8 + group;
                unsigned b0 = __float_as_uint(Bs[cur][(kb + tcol)*200 + coln]);
                unsigned b1 = __float_as_uint(Bs[cur][(kb + tcol + 4)*200 + coln]);
#pragma unroll
                for (int mf = 0; mf < 2; mf++)
                    MMA_TF32(c_acc[mf][nf][0], c_acc[mf][nf][1], c_acc[mf][nf][2], c_acc[mf][nf][3],
                             a_frag[mf][0], a_frag[mf][1], a_frag[mf][2], a_frag[mf][3], b0, b1);
            }
        }
    }
#undef K6_PFA
#undef K6_PFB
#pragma unroll
    for (int mf = 0; mf < 2; mf++) {
#pragma unroll
        for (int nf = 0; nf < 6; nf++) {
            int c = warp_n*48 + nf*8 + tcol*2;
            int r0 = m0 + warp_m*32 + mf*16 + group;
            size_t base = (size_t)kblk*384 + bz*192 + c;
            *(float2*)&g_qkvc[(size_t)r0*2304 + base]     = make_float2(c_acc[mf][nf][0], c_acc[mf][nf][1]);
            *(float2*)&g_qkvc[(size_t)(r0+8)*2304 + base] = make_float2(c_acc[mf][nf][2], c_acc[mf][nf][3]);
        }
    }
}

// ---------------- K7: communication attention, v in registers ----------------
// 128 thr (4 warps, 1 row each). smem: q,k only (24.6 KB) + scores.
__global__ void k7_commattn()
{
    __shared__ float sqk[4][1536];   // [w][i*256 + {0:q(128),128:k(128)}]
    __shared__ float ss[4][144];
    int w = threadIdx.x >> 5, lane = threadIdx.x & 31;
    int b = blockIdx.x * 4 + w;
    const float* src = g_qkvc + (size_t)b*2304;

    // q,k -> smem (per block i: 256 floats from i*384)
    for (int t = lane; t < 384; t += 32) {
        int i = t / 64, q4 = t % 64;           // 64 float4 per block
        *(float4*)&sqk[w][i*256 + q4*4] = *(const float4*)&src[i*384 + q4*4];
    }
    // v -> regs: v_reg[j][h] = v[j][h*32 + lane]
    float v_reg[6][4];
#pragma unroll
    for (int j = 0; j < 6; j++)
#pragma unroll
        for (int h = 0; h < 4; h++)
            v_reg[j][h] = src[j*384 + 256 + h*32 + lane];
    __syncwarp();

    const float inv = 0.17677669529663687f;  // 1/sqrt(32)
    for (int p = lane; p < 144; p += 32) {
        int h = p / 36, rem = p % 36, i = rem / 6, j = rem % 6;
        const float* qv = &sqk[w][i*256 + h*32];
        const float* kv = &sqk[w][j*256 + 128 + h*32];
        float s = 0.f;
#pragma unroll
        for (int c = 0; c < 32; c++) s += qv[c]*kv[c];
        ss[w][p] = s * inv;
    }
    __syncwarp();
    if (lane < 24) {
        float* row = &ss[w][lane*6];
        float mx = row[0];
#pragma unroll
        for (int j = 1; j < 6; j++) mx = fmaxf(mx, row[j]);
        float ev[6]; float sum = 0.f;
#pragma unroll
        for (int j = 0; j < 6; j++) { ev[j] = expf(row[j]-mx); sum += ev[j]; }
        float is = 1.f/sum;
#pragma unroll
        for (int j = 0; j < 6; j++) row[j] = ev[j]*is;
    }
    __syncwarp();
    // out[i][h][lane] = sum_j att[h][i][j] * v_reg[j][h]
#pragma unroll
    for (int i = 0; i < 6; i++) {
#pragma unroll
        for (int h = 0; h < 4; h++) {
            const float* att = &ss[w][h*36 + i*6];
            float acc = 0.f;
#pragma unroll
            for (int j = 0; j < 6; j++) acc += att[j]*v_reg[j][h];
            g_raw[(size_t)b*768 + i*128 + h*32 + lane] = acc;
        }
    }
}

// ---------------- K8: tf32 mma fc/gate GEMM + final hx_out ----------------
__global__ __launch_bounds__(256, 1) void k8_fcgate_out(const float* __restrict__ fc_b,
                              const float* __restrict__ gate_b,
                              const float* __restrict__ hx, float* __restrict__ out_hx)
{
    __shared__ __align__(16) float As[2][64*20];
    __shared__ __align__(16) float Bs[2][16*136];
    int tid = threadIdx.x;
    int lane = tid & 31, warp = tid >> 5;
    int warp_m = warp >> 2, warp_n = warp & 3;
    int group = lane >> 2, tcol = lane & 3;
    int m0 = blockIdx.x * 64;

#define K8_PFA(CH, S) do { \
    { int m_ = tid >> 2, seg_ = tid & 3; \
      unsigned dA_ = (unsigned)__cvta_generic_to_shared(&As[S][m_*20 + seg_*4]); \
      CP_ASYNC16(dA_, g_raw + (size_t)(m0+m_)*128 + (CH)*16 + seg_*4); } \
    } while(0)

#define K8_PFB(CH, S) do { \
    _Pragma("unroll") \
    for (int i_ = 0; i_ < 2; i_++) { \
        int e_ = tid + i_*256; \
        int dd_ = e_ >> 5, c4_ = (e_ & 31)*4; \
        unsigned dst_ = (unsigned)__cvta_generic_to_shared(&Bs[S][dd_*136 + c4_]); \
        CP_ASYNC16(dst_, g_w8 + (size_t)((CH)*16 + dd_)*128 + c4_); \
    } } while(0)

    float c_acc[2][4][4];
#pragma unroll
    for (int a = 0; a < 2; a++)
#pragma unroll
        for (int b = 0; b < 4; b++)
#pragma unroll
            for (int d = 0; d < 4; d++) c_acc[a][b][d] = 0.f;

    K8_PFB(0, 0);
    K8_PFA(0, 0);
    CP_COMMIT();

    for (int ch = 0; ch < 8; ch++) {
        int cur = ch & 1;
        CP_WAIT0();
        __syncthreads();
        if (ch < 7) { K8_PFB(ch+1, cur^1); K8_PFA(ch+1, cur^1); CP_COMMIT(); }
#pragma unroll
        for (int ks = 0; ks < 2; ks++) {
            int kb = ks*8;
            unsigned a_frag[2][4];
#pragma unroll
            for (int mf = 0; mf < 2; mf++) {
                int row0 = warp_m*32 + mf*16 + group;
                a_frag[mf][0] = __float_as_uint(As[cur][row0*20 + kb + tcol]);
                a_frag[mf][1] = __float_as_uint(As[cur][(row0+8)*20 + kb + tcol]);
                a_frag[mf][2] = __float_as_uint(As[cur][row0*20 + kb + tcol + 4]);
                a_frag[mf][3] = __float_as_uint(As[cur][(row0+8)*20 + kb + tcol + 4]);
            }
#pragma unroll
            for (int nf = 0; nf < 4; nf++) {
                int coln = warp_n*32 + nf*8 + group;
                unsigned b0 = __float_as_uint(Bs[cur][(kb + tcol)*136 + coln]);
                unsigned b1 = __float_as_uint(Bs[cur][(kb + tcol + 4)*136 + coln]);
#pragma unroll
                for (int mf = 0; mf < 2; mf++)
                    MMA_TF32(c_acc[mf][nf][0], c_acc[mf][nf][1], c_acc[mf][nf][2], c_acc[mf][nf][3],
                             a_frag[mf][0], a_frag[mf][1], a_frag[mf][2], a_frag[mf][3], b0, b1);
            }
        }
    }
#undef K8_PFA
#undef K8_PFB
#pragma unroll
    for (int mf = 0; mf < 2; mf++) {
#pragma unroll
        for (int nf = 0; nf < 4; nf++) {
            int c = warp_n*32 + nf*8 + tcol*2;
            int r = c >> 1;
            if (r >= 60) continue;
            float fb = fc_b[r], gb = gate_b[r];
#pragma unroll
            for (int half = 0; half < 2; half++) {
                int m = m0 + warp_m*32 + mf*16 + group + half*8;
                float fc = c_acc[mf][nf][half*2]     + fb;
                float gt = c_acc[mf][nf][half*2 + 1] + gb;
                float att = sigf(gt) * tanhf(fc);
                int b = m / 6, kb = m % 6;
                float msk = g_mask[m];
                size_t idx = (size_t)b*360 + kb*60 + r;
                float hn = g_hxn[idx];
                float ho = hx[idx];
                out_hx[idx] = msk*(hn + att) + (1.f - msk)*ho;
            }
        }
    }
}

// ---------------- launch ----------------
extern "C" void kernel_launch(void* const* d_in, const int* in_sizes, int n_in,
                              void* d_out, int out_size)
{
    const float* inp    = (const float*)d_in[0];
    const float* hx     = (const float*)d_in[1];
    const float* cx     = (const float*)d_in[2];
    const float* Wq_inp = (const float*)d_in[3];
    const float* Wk_inp = (const float*)d_in[4];
    const float* Wv_inp = (const float*)d_in[5];
    const float* Wq_c   = (const float*)d_in[6];
    const float* Wk_c   = (const float*)d_in[7];
    const float* Wv_c   = (const float*)d_in[8];
    const float* fc_w   = (const float*)d_in[9];
    const float* fc_b   = (const float*)d_in[10];
    const float* gate_w = (const float*)d_in[11];
    const float* gate_b = (const float*)d_in[12];
    const float* W_ih   = (const float*)d_in[13];
    const float* W_hh   = (const float*)d_in[14];
    const float* b_ih   = (const float*)d_in[15];
    const float* b_hh   = (const float*)d_in[16];

    float* out_hx = (float*)d_out;
    float* out_cx = (float*)d_out + (size_t)BATCH*360;

    prep_w4<<<1824, 256>>>(W_ih, W_hh);
    prep_wc<<<576, 256>>>(Wq_c, Wk_c, Wv_c);
    prep_w8<<<64, 256>>>(fc_w, gate_w);
    k1a_kproj<<<dim3(2, 128), 256>>>(inp, Wk_inp + 768*256);
    k1b_vproj<<<256, 256>>>(inp, Wv_inp + 768*240);
    k2_qalpha<<<dim3(256, 6), 256>>>(hx, Wq_inp);
    k3_mask<<<64, 256>>>();
    k4_gates_lstm<<<dim3(256, 6), 256>>>(hx, cx, b_ih, b_hh, out_cx);
    k6_commqkv<<<dim3(256, 6, 2), 256>>>();
    k7_commattn<<<BATCH/4, 128>>>();
    k8_fcgate_out<<<1536, 256>>>(fc_b, gate_b, hx, out_hx);
}

// round 16
// speedup vs baseline: 2.3361x; 1.0524x over previous
#include <cuda_runtime.h>
#include <math.h>

#define BATCH 16384
#define NINP  768
#define NHID  360
#define NBLK  6
#define BSZ   60

// ---------------- scratch ----------------
__device__ float g_kv[BATCH*496];      // [b][0:256]=Kproj (4 heads x64), [256:496]=Vproj (4 heads x60)
__device__ float g_alpha[BATCH*24];    // [b][k*4+h] = sigma(score)
__device__ float g_mask[BATCH*6];      // 0/1
__device__ float g_hxn[BATCH*360];     // LSTM hx_new (pre comm-attn)
__device__ float g_qkvc[BATCH*2304];   // [b][k*384 + {0:q,128:k,256:v}]
__device__ float g_raw[BATCH*768];     // [b][i*128 + h*32 + c]
__device__ float g_w4[6*304*256];      // LSTM weights [k][d][c], c=r*4+g
__device__ float g_wc[6*64*384];       // comm QKV weights [k][d][n], n={q|k|v}, d padded to 64
__device__ float g_w8[128*128];        // fc/gate weights [d][c], c=r*2+s (s=0 fc, 1 gate), c padded 128

__device__ __forceinline__ float sigf(float x){ return 1.f/(1.f+expf(-x)); }

__device__ __forceinline__ float tf32r(float x){
    unsigned t; asm("cvt.rna.tf32.f32 %0, %1;" : "=r"(t) : "f"(x));
    return __uint_as_float(t);
}

#define LOAD_FRAG(f, p) do { \
    *(float4*)&f[0] = *(const float4*)(p); \
    *(float4*)&f[4] = *(const float4*)((p)+4); } while(0)

#define FMA8x8(acc, af, bf) do { \
  _Pragma("unroll") for (int i_ = 0; i_ < 8; i_++) \
    _Pragma("unroll") for (int j_ = 0; j_ < 8; j_++) \
      acc[i_*8+j_] = fmaf(af[i_], bf[j_], acc[i_*8+j_]); } while(0)

#define CP_ASYNC16(dst, src) \
    asm volatile("cp.async.ca.shared.global [%0], [%1], 16;" :: "r"(dst), "l"(src))
#define CP_COMMIT() asm volatile("cp.async.commit_group;")
#define CP_WAIT0()  asm volatile("cp.async.wait_group 0;")

#define MMA_TF32(c0,c1,c2,c3, a0,a1,a2,a3, b0,b1) \
    asm volatile( \
        "mma.sync.aligned.m16n8k8.row.col.f32.tf32.tf32.f32 " \
        "{%0,%1,%2,%3}, {%4,%5,%6,%7}, {%8,%9}, {%0,%1,%2,%3};" \
        : "+f"(c0), "+f"(c1), "+f"(c2), "+f"(c3) \
        : "r"(a0), "r"(a1), "r"(a2), "r"(a3), "r"(b0), "r"(b1))

// ---------------- prep kernels ----------------
__global__ void prep_w4(const float* __restrict__ W_ih, const float* __restrict__ W_hh)
{
    int i = blockIdx.x*256 + threadIdx.x;        // < 6*304*256
    if (i >= 6*304*256) return;
    int k = i / (304*256); int rem = i % (304*256);
    int d = rem >> 8; int c = rem & 255;
    int r = c >> 2, g = c & 3;
    float v = 0.f;
    if (r < 60) {
        int rowW = g*360 + k*60 + r;
        if (d < 240)      v = W_ih[(size_t)rowW*1440 + k*240 + d];
        else if (d < 300) v = W_hh[(size_t)rowW*360 + k*60 + (d-240)];
    }
    g_w4[i] = v;
}

__global__ void prep_wc(const float* __restrict__ Wq_c,
                        const float* __restrict__ Wk_c,
                        const float* __restrict__ Wv_c)
{
    int i = blockIdx.x*256 + threadIdx.x;        // < 6*64*384 = 147456
    if (i >= 6*64*384) return;
    int k = i / (64*384); int rem = i % (64*384);
    int d = rem / 384; int n = rem % 384;
    float v = 0.f;
    if (d < 60) {
        const float* W = (n < 128) ? Wq_c : (n < 256) ? Wk_c : Wv_c;
        v = W[(size_t)k*7680 + d*128 + (n & 127)];
    }
    g_wc[i] = v;
}

__global__ void prep_w8(const float* __restrict__ fc_w, const float* __restrict__ gate_w)
{
    int i = blockIdx.x*256 + threadIdx.x;        // < 128*128
    if (i >= 128*128) return;
    int d = i >> 7, c = i & 127;
    int r = c >> 1, s = c & 1;
    float v = 0.f;
    if (r < 60) v = s ? gate_w[(size_t)r*128 + d] : fc_w[(size_t)r*128 + d];
    g_w8[i] = v;
}

// ---------------- K1a: Kproj  [B,768] @ [768,256]  (3xTF32 mma, pipelined) ----------------
// Split-precision: a*b ~= ah*bh + ah*bl + al*bh  (score error ~1e-7, safe for mask).
// M=64 tile, N=256, K=768 = 48 chunks of 16. 8 warps 2Mx4N, warp 32x64 (Nf=8).
__global__ __launch_bounds__(256, 1) void k1a_kproj(const float* __restrict__ inp,
                          const float* __restrict__ Wk1)
{
    __shared__ __align__(16) float As[2][64*20];
    __shared__ __align__(16) float Bs[2][16*264];
    int tid = threadIdx.x;
    int lane = tid & 31, warp = tid >> 5;
    int warp_m = warp >> 2, warp_n = warp & 3;
    int group = lane >> 2, tcol = lane & 3;
    int m0 = blockIdx.x * 64;

    float c_acc[2][8][4];
#pragma unroll
    for (int a = 0; a < 2; a++)
#pragma unroll
        for (int b = 0; b < 8; b++)
#pragma unroll
            for (int d = 0; d < 4; d++) c_acc[a][b][d] = 0.f;

// A: 64x16 raw via cp.async; B: 16x256 = 1024 x 4-float copies = 4 x 256
#define K1A_PF(CH, S) do { \
    { int m_ = tid >> 2, seg_ = tid & 3; \
      unsigned dA_ = (unsigned)__cvta_generic_to_shared(&As[S][m_*20 + seg_*4]); \
      CP_ASYNC16(dA_, inp + (size_t)(m0+m_)*768 + (CH)*16 + seg_*4); } \
    _Pragma("unroll") \
    for (int i_ = 0; i_ < 4; i_++) { \
        int e_ = tid + i_*256; \
        int dd_ = e_ >> 6, c4_ = (e_ & 63)*4; \
        unsigned dB_ = (unsigned)__cvta_generic_to_shared(&Bs[S][dd_*264 + c4_]); \
        CP_ASYNC16(dB_, Wk1 + (size_t)((CH)*16 + dd_)*256 + c4_); \
    } } while(0)

    K1A_PF(0, 0);
    CP_COMMIT();

    for (int ch = 0; ch < 48; ch++) {
        int cur = ch & 1;
        CP_WAIT0();
        __syncthreads();
        if (ch < 47) { K1A_PF(ch+1, cur^1); CP_COMMIT(); }
#pragma unroll
        for (int ks = 0; ks < 2; ks++) {
            int kb = ks*8;
            unsigned ah[2][4], al[2][4];
#pragma unroll
            for (int mf = 0; mf < 2; mf++) {
                int row0 = warp_m*32 + mf*16 + group;
                float r0 = As[cur][row0*20 + kb + tcol];
                float r1 = As[cur][(row0+8)*20 + kb + tcol];
                float r2 = As[cur][row0*20 + kb + tcol + 4];
                float r3 = As[cur][(row0+8)*20 + kb + tcol + 4];
                float h0 = tf32r(r0), h1 = tf32r(r1), h2 = tf32r(r2), h3 = tf32r(r3);
                ah[mf][0] = __float_as_uint(h0); al[mf][0] = __float_as_uint(r0 - h0);
                ah[mf][1] = __float_as_uint(h1); al[mf][1] = __float_as_uint(r1 - h1);
                ah[mf][2] = __float_as_uint(h2); al[mf][2] = __float_as_uint(r2 - h2);
                ah[mf][3] = __float_as_uint(h3); al[mf][3] = __float_as_uint(r3 - h3);
            }
#pragma unroll
            for (int nf = 0; nf < 8; nf++) {
                int coln = warp_n*64 + nf*8 + group;
                float b0r = Bs[cur][(kb + tcol)*264 + coln];
                float b1r = Bs[cur][(kb + tcol + 4)*264 + coln];
                float bh0f = tf32r(b0r), bh1f = tf32r(b1r);
                unsigned bh0 = __float_as_uint(bh0f);
                unsigned bh1 = __float_as_uint(bh1f);
                unsigned bl0 = __float_as_uint(b0r - bh0f);
                unsigned bl1 = __float_as_uint(b1r - bh1f);
#pragma unroll
                for (int mf = 0; mf < 2; mf++) {
                    MMA_TF32(c_acc[mf][nf][0], c_acc[mf][nf][1], c_acc[mf][nf][2], c_acc[mf][nf][3],
                             ah[mf][0], ah[mf][1], ah[mf][2], ah[mf][3], bh0, bh1);
                    MMA_TF32(c_acc[mf][nf][0], c_acc[mf][nf][1], c_acc[mf][nf][2], c_acc[mf][nf][3],
                             ah[mf][0], ah[mf][1], ah[mf][2], ah[mf][3], bl0, bl1);
                    MMA_TF32(c_acc[mf][nf][0], c_acc[mf][nf][1], c_acc[mf][nf][2], c_acc[mf][nf][3],
                             al[mf][0], al[mf][1], al[mf][2], al[mf][3], bh0, bh1);
                }
            }
        }
    }
#undef K1A_PF
#pragma unroll
    for (int mf = 0; mf < 2; mf++) {
#pragma unroll
        for (int nf = 0; nf < 8; nf++) {
            int c = warp_n*64 + nf*8 + tcol*2;
            int r0 = m0 + warp_m*32 + mf*16 + group;
            *(float2*)&g_kv[(size_t)r0*496 + c]     = make_float2(c_acc[mf][nf][0], c_acc[mf][nf][1]);
            *(float2*)&g_kv[(size_t)(r0+8)*496 + c] = make_float2(c_acc[mf][nf][2], c_acc[mf][nf][3]);
        }
    }
}

// ---------------- K2: Q projection + fused score -> alpha (fp32, W pipelined) ----------------
__global__ __launch_bounds__(256, 2) void k2_qalpha(const float* __restrict__ hx,
                          const float* __restrict__ Wq)
{
    __shared__ __align__(16) float Xs[60*68];        // [d][m]
    __shared__ __align__(16) float Ws[2][12*260];    // [d][n]
    int tid = threadIdx.x;            // 256
    int tx = tid & 31, ty = tid >> 5;
    int m0 = blockIdx.x * 64;
    int k  = blockIdx.y;
    const float* Wk = Wq + (size_t)k*15360;

    for (int e = tid; e < 64*60; e += 256) {
        int m = e / 60, dd = e % 60;
        Xs[dd*68 + m] = hx[(size_t)(m0+m)*360 + k*60 + dd];
    }

#define K2_CPW(CH, S) do { \
    _Pragma("unroll") for (int i_ = 0; i_ < 3; i_++) { \
        int e_ = tid + i_*256; \
        int dd_ = e_ >> 6, c4_ = (e_ & 63)*4; \
        unsigned dst_ = (unsigned)__cvta_generic_to_shared(&Ws[S][dd_*260 + c4_]); \
        CP_ASYNC16(dst_, Wk + (size_t)((CH)*12 + dd_)*256 + c4_); \
    } } while(0)

    float acc[64];
#pragma unroll
    for (int i = 0; i < 64; i++) acc[i] = 0.f;

    K2_CPW(0, 0);
    CP_COMMIT();

    for (int ch = 0; ch < 5; ch++) {
        int cur = ch & 1;
        CP_WAIT0();
        __syncthreads();
        if (ch < 4) { K2_CPW(ch+1, cur^1); CP_COMMIT(); }
#pragma unroll
        for (int kk = 0; kk < 12; kk++) {
            float af[8], bf[8];
            LOAD_FRAG(af, &Xs[(ch*12 + kk)*68 + ty*8]);
            LOAD_FRAG(bf, &Ws[cur][kk*260 + tx*8]);
            FMA8x8(acc, af, bf);
        }
    }
#undef K2_CPW
    int h = tx >> 3, lane8 = tx & 7;
#pragma unroll
    for (int i = 0; i < 8; i++) {
        int gm = m0 + ty*8 + i;
        const float* kp = &g_kv[(size_t)gm*496 + h*64 + lane8*8];
        float s = 0.f;
#pragma unroll
        for (int j = 0; j < 8; j++) s += acc[i*8+j] * kp[j];
        s += __shfl_xor_sync(0xffffffffu, s, 1);
        s += __shfl_xor_sync(0xffffffffu, s, 2);
        s += __shfl_xor_sync(0xffffffffu, s, 4);
        if (lane8 == 0) g_alpha[(size_t)gm*24 + k*4 + h] = sigf(0.125f*s);
    }
}

// ---------------- K3: top-2 null mask ----------------
__global__ void k3_mask()
{
    int b = blockIdx.x*256 + threadIdx.x;
    float4 a0 = *(const float4*)&g_alpha[(size_t)b*24 + 0];
    float4 a1 = *(const float4*)&g_alpha[(size_t)b*24 + 4];
    float4 a2 = *(const float4*)&g_alpha[(size_t)b*24 + 8];
    float4 a3 = *(const float4*)&g_alpha[(size_t)b*24 + 12];
    float4 a4 = *(const float4*)&g_alpha[(size_t)b*24 + 16];
    float4 a5 = *(const float4*)&g_alpha[(size_t)b*24 + 20];
    float nul[6];
    nul[0] = 1.f - 0.25f*(a0.x+a0.y+a0.z+a0.w);
    nul[1] = 1.f - 0.25f*(a1.x+a1.y+a1.z+a1.w);
    nul[2] = 1.f - 0.25f*(a2.x+a2.y+a2.z+a2.w);
    nul[3] = 1.f - 0.25f*(a3.x+a3.y+a3.z+a3.w);
    nul[4] = 1.f - 0.25f*(a4.x+a4.y+a4.z+a4.w);
    nul[5] = 1.f - 0.25f*(a5.x+a5.y+a5.z+a5.w);
    int i1 = 0; float m1 = nul[0];
#pragma unroll
    for (int k = 1; k < 6; k++) if (nul[k] > m1) { m1 = nul[k]; i1 = k; }
    int i2 = -1; float m2 = -1e30f;
#pragma unroll
    for (int k = 0; k < 6; k++) if (k != i1 && nul[k] > m2) { m2 = nul[k]; i2 = k; }
#pragma unroll
    for (int k = 0; k < 6; k++)
        g_mask[(size_t)b*6 + k] = (k == i1 || k == i2) ? 0.f : 1.f;
}

// ---------------- K1b: Vproj  [B,768] @ [768,240]  (tf32 mma, pipelined) ----------------
__global__ __launch_bounds__(256, 1) void k1b_vproj(const float* __restrict__ inp,
                          const float* __restrict__ Wv1)
{
    __shared__ __align__(16) float As[2][64*20];
    __shared__ __align__(16) float Bs[2][16*264];
    int tid = threadIdx.x;
    int lane = tid & 31, warp = tid >> 5;
    int warp_m = warp >> 2, warp_n = warp & 3;
    int group = lane >> 2, tcol = lane & 3;
    int m0 = blockIdx.x * 64;

    for (int s = 0; s < 2; s++)
        for (int e = tid; e < 16*24; e += 256) {
            int dd = e / 24, c = 240 + e % 24;
            Bs[s][dd*264 + c] = 0.f;
        }

    float c_acc[2][8][4];
#pragma unroll
    for (int a = 0; a < 2; a++)
#pragma unroll
        for (int b = 0; b < 8; b++)
#pragma unroll
            for (int d = 0; d < 4; d++) c_acc[a][b][d] = 0.f;

#define K1B_PF(CH, S) do { \
    { int m_ = tid >> 2, seg_ = tid & 3; \
      unsigned dA_ = (unsigned)__cvta_generic_to_shared(&As[S][m_*20 + seg_*4]); \
      CP_ASYNC16(dA_, inp + (size_t)(m0+m_)*768 + (CH)*16 + seg_*4); } \
    _Pragma("unroll") \
    for (int i_ = 0; i_ < 4; i_++) { \
        int e_ = tid + i_*256; \
        if (e_ < 960) { \
            int dd_ = e_ / 60, c4_ = (e_ % 60)*4; \
            unsigned dB_ = (unsigned)__cvta_generic_to_shared(&Bs[S][dd_*264 + c4_]); \
            CP_ASYNC16(dB_, Wv1 + (size_t)((CH)*16 + dd_)*240 + c4_); \
        } \
    } } while(0)

    __syncthreads();
    K1B_PF(0, 0);
    CP_COMMIT();

    for (int ch = 0; ch < 48; ch++) {
        int cur = ch & 1;
        CP_WAIT0();
        __syncthreads();
        if (ch < 47) { K1B_PF(ch+1, cur^1); CP_COMMIT(); }
#pragma unroll
        for (int ks = 0; ks < 2; ks++) {
            int kb = ks*8;
            unsigned a_frag[2][4];
#pragma unroll
            for (int mf = 0; mf < 2; mf++) {
                int row0 = warp_m*32 + mf*16 + group;
                a_frag[mf][0] = __float_as_uint(As[cur][row0*20 + kb + tcol]);
                a_frag[mf][1] = __float_as_uint(As[cur][(row0+8)*20 + kb + tcol]);
                a_frag[mf][2] = __float_as_uint(As[cur][row0*20 + kb + tcol + 4]);
                a_frag[mf][3] = __float_as_uint(As[cur][(row0+8)*20 + kb + tcol + 4]);
            }
#pragma unroll
            for (int nf = 0; nf < 8; nf++) {
                int coln = warp_n*64 + nf*8 + group;
                unsigned b0 = __float_as_uint(Bs[cur][(kb + tcol)*264 + coln]);
                unsigned b1 = __float_as_uint(Bs[cur][(kb + tcol + 4)*264 + coln]);
#pragma unroll
                for (int mf = 0; mf < 2; mf++)
                    MMA_TF32(c_acc[mf][nf][0], c_acc[mf][nf][1], c_acc[mf][nf][2], c_acc[mf][nf][3],
                             a_frag[mf][0], a_frag[mf][1], a_frag[mf][2], a_frag[mf][3], b0, b1);
            }
        }
    }
#undef K1B_PF
#pragma unroll
    for (int mf = 0; mf < 2; mf++) {
#pragma unroll
        for (int nf = 0; nf < 8; nf++) {
            int c = warp_n*64 + nf*8 + tcol*2;
            if (c >= 240) continue;
            int r0 = m0 + warp_m*32 + mf*16 + group;
            g_kv[(size_t)r0*496 + 256 + c]     = c_acc[mf][nf][0];
            g_kv[(size_t)r0*496 + 256 + c + 1] = c_acc[mf][nf][1];
            g_kv[(size_t)(r0+8)*496 + 256 + c]     = c_acc[mf][nf][2];
            g_kv[(size_t)(r0+8)*496 + 256 + c + 1] = c_acc[mf][nf][3];
        }
    }
}

// ---------------- K4: pipelined tf32 mma gates GEMM + LSTM pointwise + cx_out ----------------
__global__ __launch_bounds__(256, 1) void k4_gates_lstm(const float* __restrict__ hx,
                              const float* __restrict__ cx,
                              const float* __restrict__ b_ih,
                              const float* __restrict__ b_hh,
                              float* __restrict__ out_cx)
{
    __shared__ __align__(16) float As[2][64*20];
    __shared__ __align__(16) float Bs[2][16*264];
    __shared__ float sbias[240];
    __shared__ float s_alpha5[320];   // [m][5], col 4 = 1.0 (hx region)
    int tid = threadIdx.x;
    int lane = tid & 31, warp = tid >> 5;
    int warp_m = warp >> 2, warp_n = warp & 3;
    int group = lane >> 2, tcol = lane & 3;
    int m0 = blockIdx.x * 64;
    int k  = blockIdx.y;

    if (tid < 240) {
        int c = tid, r = c >> 2, g = c & 3;
        int rowW = g*360 + k*60 + r;
        sbias[c] = b_ih[rowW] + b_hh[rowW];
    }
    for (int e = tid; e < 320; e += 256) {
        int m = e / 5, j = e % 5;
        s_alpha5[e] = (j < 4) ? g_alpha[(size_t)(m0+m)*24 + k*4 + j] : 1.f;
    }
    __syncthreads();

    const float* w4k = g_w4 + (size_t)k*(304*256);

#define PREFETCH_A(CH, S) do { \
    int m_ = tid >> 2, seg_ = tid & 3; \
    int d0_ = (CH)*16 + seg_*4; \
    unsigned dA_ = (unsigned)__cvta_generic_to_shared(&As[S][m_*20 + seg_*4]); \
    if (d0_ < 240)      { CP_ASYNC16(dA_, g_kv + (size_t)(m0+m_)*496 + 256 + d0_); } \
    else if (d0_ < 300) { CP_ASYNC16(dA_, hx + (size_t)(m0+m_)*360 + k*60 + (d0_-240)); } \
    else *(float4*)&As[S][m_*20 + seg_*4] = make_float4(0.f,0.f,0.f,0.f); \
    } while(0)

#define PREFETCH_B(CH, S) do { \
    const float* src_ = w4k + (CH)*16*256; \
    _Pragma("unroll") \
    for (int i_ = 0; i_ < 4; i_++) { \
        int e_ = tid + i_*256; \
        int dd_ = e_ >> 6, c4_ = (e_ & 63)*4; \
        unsigned dst_ = (unsigned)__cvta_generic_to_shared(&Bs[S][dd_*264 + c4_]); \
        CP_ASYNC16(dst_, src_ + dd_*256 + c4_); \
    } } while(0)

    float c_acc[2][8][4];
#pragma unroll
    for (int a = 0; a < 2; a++)
#pragma unroll
        for (int b = 0; b < 8; b++)
#pragma unroll
            for (int d = 0; d < 4; d++) c_acc[a][b][d] = 0.f;

    PREFETCH_B(0, 0);
    PREFETCH_A(0, 0);
    CP_COMMIT();

    int row0a = warp_m*32 + group;
    for (int ch = 0; ch < 19; ch++) {
        int cur = ch & 1;
        CP_WAIT0();
        __syncthreads();
        if (ch < 18) {
            PREFETCH_B(ch+1, cur^1);
            PREFETCH_A(ch+1, cur^1);
            CP_COMMIT();
        }
#pragma unroll
        for (int ks = 0; ks < 2; ks++) {
            int kb = ks*8;
            int dlo = ch*16 + kb + tcol;
            int dhi = dlo + 4;
            int hlo = dlo/60; if (hlo > 4) hlo = 4;
            int hhi = dhi/60; if (hhi > 4) hhi = 4;
            unsigned a_frag[2][4];
#pragma unroll
            for (int mf = 0; mf < 2; mf++) {
                int row0 = row0a + mf*16;
                float m0lo = s_alpha5[row0*5 + hlo];
                float m1lo = s_alpha5[(row0+8)*5 + hlo];
                float m0hi = s_alpha5[row0*5 + hhi];
                float m1hi = s_alpha5[(row0+8)*5 + hhi];
                a_frag[mf][0] = __float_as_uint(As[cur][row0*20 + kb + tcol] * m0lo);
                a_frag[mf][1] = __float_as_uint(As[cur][(row0+8)*20 + kb + tcol] * m1lo);
                a_frag[mf][2] = __float_as_uint(As[cur][row0*20 + kb + tcol + 4] * m0hi);
                a_frag[mf][3] = __float_as_uint(As[cur][(row0+8)*20 + kb + tcol + 4] * m1hi);
            }
#pragma unroll
            for (int nf = 0; nf < 8; nf++) {
                int coln = warp_n*64 + nf*8 + group;
                unsigned b0 = __float_as_uint(Bs[cur][(kb + tcol)*264 + coln]);
                unsigned b1 = __float_as_uint(Bs[cur][(kb + tcol + 4)*264 + coln]);
#pragma unroll
                for (int mf = 0; mf < 2; mf++)
                    MMA_TF32(c_acc[mf][nf][0], c_acc[mf][nf][1], c_acc[mf][nf][2], c_acc[mf][nf][3],
                             a_frag[mf][0], a_frag[mf][1], a_frag[mf][2], a_frag[mf][3], b0, b1);
            }
        }
    }
#undef PREFETCH_A
#undef PREFETCH_B
#pragma unroll
    for (int mf = 0; mf < 2; mf++) {
#pragma unroll
        for (int nf = 0; nf < 8; nf++) {
            float x0 = c_acc[mf][nf][0], x1 = c_acc[mf][nf][1];
            float x2 = c_acc[mf][nf][2], x3 = c_acc[mf][nf][3];
            float y0 = __shfl_xor_sync(0xffffffffu, x0, 1);
            float y1 = __shfl_xor_sync(0xffffffffu, x1, 1);
            float y2 = __shfl_xor_sync(0xffffffffu, x2, 1);
            float y3 = __shfl_xor_sync(0xffffffffu, x3, 1);
            int r = warp_n*16 + nf*2 + (tcol >> 1);
            if (r >= 60) continue;
            float gi, gf, gg, go; int rowloc;
            if ((tcol & 1) == 0) {
                gi = x0; gf = x1; gg = y0; go = y1;
                rowloc = warp_m*32 + mf*16 + group;
            } else {
                gi = y2; gf = y3; gg = x2; go = x3;
                rowloc = warp_m*32 + mf*16 + group + 8;
            }
            gi += sbias[r*4 + 0];
            gf += sbias[r*4 + 1];
            gg += sbias[r*4 + 2];
            go += sbias[r*4 + 3];
            int b = m0 + rowloc;
            float msk = g_mask[(size_t)b*6 + k];
            size_t idx = (size_t)b*360 + k*60 + r;
            float c_old = cx[idx];
            float cn = sigf(gf)*c_old + sigf(gi)*tanhf(gg);
            float hn = sigf(go)*tanhf(cn);
            g_hxn[idx] = hn;
            out_cx[idx] = msk*cn + (1.f - msk)*c_old;
        }
    }
}

// ---------------- K6: tf32 mma comm QKV  [B,64] @ [64,384] per block ----------------
__global__ __launch_bounds__(256, 1) void k6_commqkv()
{
    __shared__ __align__(16) float As[2][64*20];
    __shared__ __align__(16) float Bs[2][16*200];
    int tid = threadIdx.x;
    int lane = tid & 31, warp = tid >> 5;
    int warp_m = warp >> 2, warp_n = warp & 3;
    int group = lane >> 2, tcol = lane & 3;
    int m0 = blockIdx.x * 64;
    int kblk = blockIdx.y;
    int bz = blockIdx.z;
    const float* wck = g_wc + (size_t)kblk*(64*384) + bz*192;

#define K6_PFA(CH, S) do { \
    _Pragma("unroll") \
    for (int i_ = 0; i_ < 4; i_++) { \
        int e_ = tid + i_*256; \
        int m_ = e_ >> 4, dd_ = e_ & 15; \
        int d_ = (CH)*16 + dd_; \
        As[S][m_*20 + dd_] = (d_ < 60) ? g_hxn[(size_t)(m0+m_)*360 + kblk*60 + d_] : 0.f; \
    } } while(0)

#define K6_PFB(CH, S) do { \
    _Pragma("unroll") \
    for (int i_ = 0; i_ < 3; i_++) { \
        int e_ = tid + i_*256; \
        int dd_ = e_ / 48, c4_ = (e_ % 48)*4; \
        unsigned dst_ = (unsigned)__cvta_generic_to_shared(&Bs[S][dd_*200 + c4_]); \
        CP_ASYNC16(dst_, wck + (size_t)((CH)*16 + dd_)*384 + c4_); \
    } } while(0)

    float c_acc[2][6][4];
#pragma unroll
    for (int a = 0; a < 2; a++)
#pragma unroll
        for (int b = 0; b < 6; b++)
#pragma unroll
            for (int d = 0; d < 4; d++) c_acc[a][b][d] = 0.f;

    K6_PFB(0, 0);
    K6_PFA(0, 0);
    CP_COMMIT();

    for (int ch = 0; ch < 4; ch++) {
        int cur = ch & 1;
        CP_WAIT0();
        __syncthreads();
        if (ch < 3) { K6_PFB(ch+1, cur^1); K6_PFA(ch+1, cur^1); CP_COMMIT(); }
#pragma unroll
        for (int ks = 0; ks < 2; ks++) {
            int kb = ks*8;
            unsigned a_frag[2][4];
#pragma unroll
            for (int mf = 0; mf < 2; mf++) {
                int row0 = warp_m*32 + mf*16 + group;
                a_frag[mf][0] = __float_as_uint(As[cur][row0*20 + kb + tcol]);
                a_frag[mf][1] = __float_as_uint(As[cur][(row0+8)*20 + kb + tcol]);
                a_frag[mf][2] = __float_as_uint(As[cur][row0*20 + kb + tcol + 4]);
                a_frag[mf][3] = __float_as_uint(As[cur][(row0+8)*20 + kb + tcol + 4]);
            }
#pragma unroll
            for (int nf = 0; nf < 6; nf++) {
                int coln = warp_n*48 + nf*8 + group;
                unsigned b0 = __float_as_uint(Bs[cur][(kb + tcol)*200 + coln]);
                unsigned b1 = __float_as_uint(Bs[cur][(kb + tcol + 4)*200 + coln]);
#pragma unroll
                for (int mf = 0; mf < 2; mf++)
                    MMA_TF32(c_acc[mf][nf][0], c_acc[mf][nf][1], c_acc[mf][nf][2], c_acc[mf][nf][3],
                             a_frag[mf][0], a_frag[mf][1], a_frag[mf][2], a_frag[mf][3], b0, b1);
            }
        }
    }
#undef K6_PFA
#undef K6_PFB
#pragma unroll
    for (int mf = 0; mf < 2; mf++) {
#pragma unroll
        for (int nf = 0; nf < 6; nf++) {
            int c = warp_n*48 + nf*8 + tcol*2;
            int r0 = m0 + warp_m*32 + mf*16 + group;
            size_t base = (size_t)kblk*384 + bz*192 + c;
            *(float2*)&g_qkvc[(size_t)r0*2304 + base]     = make_float2(c_acc[mf][nf][0], c_acc[mf][nf][1]);
            *(float2*)&g_qkvc[(size_t)(r0+8)*2304 + base] = make_float2(c_acc[mf][nf][2], c_acc[mf][nf][3]);
        }
    }
}

// ---------------- K7: communication attention, v in registers ----------------
__global__ void k7_commattn()
{
    __shared__ float sqk[4][1536];   // [w][i*256 + {0:q(128),128:k(128)}]
    __shared__ float ss[4][144];
    int w = threadIdx.x >> 5, lane = threadIdx.x & 31;
    int b = blockIdx.x * 4 + w;
    const float* src = g_qkvc + (size_t)b*2304;

    for (int t = lane; t < 384; t += 32) {
        int i = t / 64, q4 = t % 64;
        *(float4*)&sqk[w][i*256 + q4*4] = *(const float4*)&src[i*384 + q4*4];
    }
    float v_reg[6][4];
#pragma unroll
    for (int j = 0; j < 6; j++)
#pragma unroll
        for (int h = 0; h < 4; h++)
            v_reg[j][h] = src[j*384 + 256 + h*32 + lane];
    __syncwarp();

    const float inv = 0.17677669529663687f;  // 1/sqrt(32)
    for (int p = lane; p < 144; p += 32) {
        int h = p / 36, rem = p % 36, i = rem / 6, j = rem % 6;
        const float* qv = &sqk[w][i*256 + h*32];
        const float* kv = &sqk[w][j*256 + 128 + h*32];
        float s = 0.f;
#pragma unroll
        for (int c = 0; c < 32; c++) s += qv[c]*kv[c];
        ss[w][p] = s * inv;
    }
    __syncwarp();
    if (lane < 24) {
        float* row = &ss[w][lane*6];
        float mx = row[0];
#pragma unroll
        for (int j = 1; j < 6; j++) mx = fmaxf(mx, row[j]);
        float ev[6]; float sum = 0.f;
#pragma unroll
        for (int j = 0; j < 6; j++) { ev[j] = expf(row[j]-mx); sum += ev[j]; }
        float is = 1.f/sum;
#pragma unroll
        for (int j = 0; j < 6; j++) row[j] = ev[j]*is;
    }
    __syncwarp();
#pragma unroll
    for (int i = 0; i < 6; i++) {
#pragma unroll
        for (int h = 0; h < 4; h++) {
            const float* att = &ss[w][h*36 + i*6];
            float acc = 0.f;
#pragma unroll
            for (int j = 0; j < 6; j++) acc += att[j]*v_reg[j][h];
            g_raw[(size_t)b*768 + i*128 + h*32 + lane] = acc;
        }
    }
}

// ---------------- K8: tf32 mma fc/gate GEMM + final hx_out ----------------
__global__ __launch_bounds__(256, 1) void k8_fcgate_out(const float* __restrict__ fc_b,
                              const float* __restrict__ gate_b,
                              const float* __restrict__ hx, float* __restrict__ out_hx)
{
    __shared__ __align__(16) float As[2][64*20];
    __shared__ __align__(16) float Bs[2][16*136];
    int tid = threadIdx.x;
    int lane = tid & 31, warp = tid >> 5;
    int warp_m = warp >> 2, warp_n = warp & 3;
    int group = lane >> 2, tcol = lane & 3;
    int m0 = blockIdx.x * 64;

#define K8_PFA(CH, S) do { \
    { int m_ = tid >> 2, seg_ = tid & 3; \
      unsigned dA_ = (unsigned)__cvta_generic_to_shared(&As[S][m_*20 + seg_*4]); \
      CP_ASYNC16(dA_, g_raw + (size_t)(m0+m_)*128 + (CH)*16 + seg_*4); } \
    } while(0)

#define K8_PFB(CH, S) do { \
    _Pragma("unroll") \
    for (int i_ = 0; i_ < 2; i_++) { \
        int e_ = tid + i_*256; \
        int dd_ = e_ >> 5, c4_ = (e_ & 31)*4; \
        unsigned dst_ = (unsigned)__cvta_generic_to_shared(&Bs[S][dd_*136 + c4_]); \
        CP_ASYNC16(dst_, g_w8 + (size_t)((CH)*16 + dd_)*128 + c4_); \
    } } while(0)

    float c_acc[2][4][4];
#pragma unroll
    for (int a = 0; a < 2; a++)
#pragma unroll
        for (int b = 0; b < 4; b++)
#pragma unroll
            for (int d = 0; d < 4; d++) c_acc[a][b][d] = 0.f;

    K8_PFB(0, 0);
    K8_PFA(0, 0);
    CP_COMMIT();

    for (int ch = 0; ch < 8; ch++) {
        int cur = ch & 1;
        CP_WAIT0();
        __syncthreads();
        if (ch < 7) { K8_PFB(ch+1, cur^1); K8_PFA(ch+1, cur^1); CP_COMMIT(); }
#pragma unroll
        for (int ks = 0; ks < 2; ks++) {
            int kb = ks*8;
            unsigned a_frag[2][4];
#pragma unroll
            for (int mf = 0; mf < 2; mf++) {
                int row0 = warp_m*32 + mf*16 + group;
                a_frag[mf][0] = __float_as_uint(As[cur][row0*20 + kb + tcol]);
                a_frag[mf][1] = __float_as_uint(As[cur][(row0+8)*20 + kb + tcol]);
                a_frag[mf][2] = __float_as_uint(As[cur][row0*20 + kb + tcol + 4]);
                a_frag[mf][3] = __float_as_uint(As[cur][(row0+8)*20 + kb + tcol + 4]);
            }
#pragma unroll
            for (int nf = 0; nf < 4; nf++) {
                int coln = warp_n*32 + nf*8 + group;
                unsigned b0 = __float_as_uint(Bs[cur][(kb + tcol)*136 + coln]);
                unsigned b1 = __float_as_uint(Bs[cur][(kb + tcol + 4)*136 + coln]);
#pragma unroll
                for (int mf = 0; mf < 2; mf++)
                    MMA_TF32(c_acc[mf][nf][0], c_acc[mf][nf][1], c_acc[mf][nf][2], c_acc[mf][nf][3],
                             a_frag[mf][0], a_frag[mf][1], a_frag[mf][2], a_frag[mf][3], b0, b1);
            }
        }
    }
#undef K8_PFA
#undef K8_PFB
#pragma unroll
    for (int mf = 0; mf < 2; mf++) {
#pragma unroll
        for (int nf = 0; nf < 4; nf++) {
            int c = warp_n*32 + nf*8 + tcol*2;
            int r = c >> 1;
            if (r >= 60) continue;
            float fb = fc_b[r], gb = gate_b[r];
#pragma unroll
            for (int half = 0; half < 2; half++) {
                int m = m0 + warp_m*32 + mf*16 + group + half*8;
                float fc = c_acc[mf][nf][half*2]     + fb;
                float gt = c_acc[mf][nf][half*2 + 1] + gb;
                float att = sigf(gt) * tanhf(fc);
                int b = m / 6, kb = m % 6;
                float msk = g_mask[m];
                size_t idx = (size_t)b*360 + kb*60 + r;
                float hn = g_hxn[idx];
                float ho = hx[idx];
                out_hx[idx] = msk*(hn + att) + (1.f - msk)*ho;
            }
        }
    }
}

// ---------------- launch ----------------
extern "C" void kernel_launch(void* const* d_in, const int* in_sizes, int n_in,
                              void* d_out, int out_size)
{
    const float* inp    = (const float*)d_in[0];
    const float* hx     = (const float*)d_in[1];
    const float* cx     = (const float*)d_in[2];
    const float* Wq_inp = (const float*)d_in[3];
    const float* Wk_inp = (const float*)d_in[4];
    const float* Wv_inp = (const float*)d_in[5];
    const float* Wq_c   = (const float*)d_in[6];
    const float* Wk_c   = (const float*)d_in[7];
    const float* Wv_c   = (const float*)d_in[8];
    const float* fc_w   = (const float*)d_in[9];
    const float* fc_b   = (const float*)d_in[10];
    const float* gate_w = (const float*)d_in[11];
    const float* gate_b = (const float*)d_in[12];
    const float* W_ih   = (const float*)d_in[13];
    const float* W_hh   = (const float*)d_in[14];
    const float* b_ih   = (const float*)d_in[15];
    const float* b_hh   = (const float*)d_in[16];

    float* out_hx = (float*)d_out;
    float* out_cx = (float*)d_out + (size_t)BATCH*360;

    prep_w4<<<1824, 256>>>(W_ih, W_hh);
    prep_wc<<<576, 256>>>(Wq_c, Wk_c, Wv_c);
    prep_w8<<<64, 256>>>(fc_w, gate_w);
    k1a_kproj<<<256, 256>>>(inp, Wk_inp + 768*256);
    k1b_vproj<<<256, 256>>>(inp, Wv_inp + 768*240);
    k2_qalpha<<<dim3(256, 6), 256>>>(hx, Wq_inp);
    k3_mask<<<64, 256>>>();
    k4_gates_lstm<<<dim3(256, 6), 256>>>(hx, cx, b_ih, b_hh, out_cx);
    k6_commqkv<<<dim3(256, 6, 2), 256>>>();
    k7_commattn<<<BATCH/4, 128>>>();
    k8_fcgate_out<<<1536, 256>>>(fc_b, gate_b, hx, out_hx);
}

// round 17
// speedup vs baseline: 2.3519x; 1.0068x over previous
#include <cuda_runtime.h>
#include <math.h>

#define BATCH 16384
#define NINP  768
#define NHID  360
#define NBLK  6
#define BSZ   60

// ---------------- scratch ----------------
__device__ float g_kv[BATCH*496];      // [b][0:256]=Kproj (4 heads x64), [256:496]=Vproj (4 heads x60)
__device__ float g_alpha[BATCH*24];    // [b][k*4+h] = sigma(score)
__device__ float g_mask[BATCH*6];      // 0/1
__device__ float g_hxn[BATCH*360];     // LSTM hx_new (pre comm-attn)
__device__ float g_qkvc[BATCH*2304];   // [b][k*384 + {0:q,128:k,256:v}]
__device__ float g_raw[BATCH*768];     // [b][i*128 + h*32 + c]
__device__ float g_w4[6*304*256];      // LSTM weights [k][d][c], c=r*4+g
__device__ float g_wc[6*64*384];       // comm QKV weights [k][d][n], n={q|k|v}, d padded to 64
__device__ float g_w8[128*128];        // fc/gate weights [d][c], c=r*2+s (s=0 fc, 1 gate), c padded 128

__device__ __forceinline__ float sigf(float x){ return 1.f/(1.f+expf(-x)); }

__device__ __forceinline__ float tf32r(float x){
    unsigned t; asm("cvt.rna.tf32.f32 %0, %1;" : "=r"(t) : "f"(x));
    return __uint_as_float(t);
}

#define LOAD_FRAG(f, p) do { \
    *(float4*)&f[0] = *(const float4*)(p); \
    *(float4*)&f[4] = *(const float4*)((p)+4); } while(0)

#define FMA8x8(acc, af, bf) do { \
  _Pragma("unroll") for (int i_ = 0; i_ < 8; i_++) \
    _Pragma("unroll") for (int j_ = 0; j_ < 8; j_++) \
      acc[i_*8+j_] = fmaf(af[i_], bf[j_], acc[i_*8+j_]); } while(0)

#define CP_ASYNC16(dst, src) \
    asm volatile("cp.async.ca.shared.global [%0], [%1], 16;" :: "r"(dst), "l"(src))
#define CP_COMMIT() asm volatile("cp.async.commit_group;")
#define CP_WAIT0()  asm volatile("cp.async.wait_group 0;")

#define MMA_TF32(c0,c1,c2,c3, a0,a1,a2,a3, b0,b1) \
    asm volatile( \
        "mma.sync.aligned.m16n8k8.row.col.f32.tf32.tf32.f32 " \
        "{%0,%1,%2,%3}, {%4,%5,%6,%7}, {%8,%9}, {%0,%1,%2,%3};" \
        : "+f"(c0), "+f"(c1), "+f"(c2), "+f"(c3) \
        : "r"(a0), "r"(a1), "r"(a2), "r"(a3), "r"(b0), "r"(b1))

// ---------------- prep kernels ----------------
__global__ void prep_w4(const float* __restrict__ W_ih, const float* __restrict__ W_hh)
{
    int i = blockIdx.x*256 + threadIdx.x;        // < 6*304*256
    if (i >= 6*304*256) return;
    int k = i / (304*256); int rem = i % (304*256);
    int d = rem >> 8; int c = rem & 255;
    int r = c >> 2, g = c & 3;
    float v = 0.f;
    if (r < 60) {
        int rowW = g*360 + k*60 + r;
        if (d < 240)      v = W_ih[(size_t)rowW*1440 + k*240 + d];
        else if (d < 300) v = W_hh[(size_t)rowW*360 + k*60 + (d-240)];
    }
    g_w4[i] = v;
}

__global__ void prep_wc(const float* __restrict__ Wq_c,
                        const float* __restrict__ Wk_c,
                        const float* __restrict__ Wv_c)
{
    int i = blockIdx.x*256 + threadIdx.x;        // < 6*64*384 = 147456
    if (i >= 6*64*384) return;
    int k = i / (64*384); int rem = i % (64*384);
    int d = rem / 384; int n = rem % 384;
    float v = 0.f;
    if (d < 60) {
        const float* W = (n < 128) ? Wq_c : (n < 256) ? Wk_c : Wv_c;
        v = W[(size_t)k*7680 + d*128 + (n & 127)];
    }
    g_wc[i] = v;
}

__global__ void prep_w8(const float* __restrict__ fc_w, const float* __restrict__ gate_w)
{
    int i = blockIdx.x*256 + threadIdx.x;        // < 128*128
    if (i >= 128*128) return;
    int d = i >> 7, c = i & 127;
    int r = c >> 1, s = c & 1;
    float v = 0.f;
    if (r < 60) v = s ? gate_w[(size_t)r*128 + d] : fc_w[(size_t)r*128 + d];
    g_w8[i] = v;
}

// ---------------- K1a: Kproj  [B,768] @ [768,256]  (3xTF32 mma, pipelined) ----------------
// Split-precision: a*b ~= ah*bh + ah*bl + al*bh  (score error ~1e-7, safe for mask).
// M=64 tile, N=256, K=768 = 48 chunks of 16. 8 warps 2Mx4N, warp 32x64 (Nf=8).
__global__ __launch_bounds__(256, 1) void k1a_kproj(const float* __restrict__ inp,
                          const float* __restrict__ Wk1)
{
    __shared__ __align__(16) float As[2][64*20];
    __shared__ __align__(16) float Bs[2][16*264];
    int tid = threadIdx.x;
    int lane = tid & 31, warp = tid >> 5;
    int warp_m = warp >> 2, warp_n = warp & 3;
    int group = lane >> 2, tcol = lane & 3;
    int m0 = blockIdx.x * 64;

    float c_acc[2][8][4];
#pragma unroll
    for (int a = 0; a < 2; a++)
#pragma unroll
        for (int b = 0; b < 8; b++)
#pragma unroll
            for (int d = 0; d < 4; d++) c_acc[a][b][d] = 0.f;

// A: 64x16 raw via cp.async; B: 16x256 = 1024 x 4-float copies = 4 x 256
#define K1A_PF(CH, S) do { \
    { int m_ = tid >> 2, seg_ = tid & 3; \
      unsigned dA_ = (unsigned)__cvta_generic_to_shared(&As[S][m_*20 + seg_*4]); \
      CP_ASYNC16(dA_, inp + (size_t)(m0+m_)*768 + (CH)*16 + seg_*4); } \
    _Pragma("unroll") \
    for (int i_ = 0; i_ < 4; i_++) { \
        int e_ = tid + i_*256; \
        int dd_ = e_ >> 6, c4_ = (e_ & 63)*4; \
        unsigned dB_ = (unsigned)__cvta_generic_to_shared(&Bs[S][dd_*264 + c4_]); \
        CP_ASYNC16(dB_, Wk1 + (size_t)((CH)*16 + dd_)*256 + c4_); \
    } } while(0)

    K1A_PF(0, 0);
    CP_COMMIT();

    for (int ch = 0; ch < 48; ch++) {
        int cur = ch & 1;
        CP_WAIT0();
        __syncthreads();
        if (ch < 47) { K1A_PF(ch+1, cur^1); CP_COMMIT(); }
#pragma unroll
        for (int ks = 0; ks < 2; ks++) {
            int kb = ks*8;
            unsigned ah[2][4], al[2][4];
#pragma unroll
            for (int mf = 0; mf < 2; mf++) {
                int row0 = warp_m*32 + mf*16 + group;
                float r0 = As[cur][row0*20 + kb + tcol];
                float r1 = As[cur][(row0+8)*20 + kb + tcol];
                float r2 = As[cur][row0*20 + kb + tcol + 4];
                float r3 = As[cur][(row0+8)*20 + kb + tcol + 4];
                float h0 = tf32r(r0), h1 = tf32r(r1), h2 = tf32r(r2), h3 = tf32r(r3);
                ah[mf][0] = __float_as_uint(h0); al[mf][0] = __float_as_uint(r0 - h0);
                ah[mf][1] = __float_as_uint(h1); al[mf][1] = __float_as_uint(r1 - h1);
                ah[mf][2] = __float_as_uint(h2); al[mf][2] = __float_as_uint(r2 - h2);
                ah[mf][3] = __float_as_uint(h3); al[mf][3] = __float_as_uint(r3 - h3);
            }
#pragma unroll
            for (int nf = 0; nf < 8; nf++) {
                int coln = warp_n*64 + nf*8 + group;
                float b0r = Bs[cur][(kb + tcol)*264 + coln];
                float b1r = Bs[cur][(kb + tcol + 4)*264 + coln];
                float bh0f = tf32r(b0r), bh1f = tf32r(b1r);
                unsigned bh0 = __float_as_uint(bh0f);
                unsigned bh1 = __float_as_uint(bh1f);
                unsigned bl0 = __float_as_uint(b0r - bh0f);
                unsigned bl1 = __float_as_uint(b1r - bh1f);
#pragma unroll
                for (int mf = 0; mf < 2; mf++) {
                    MMA_TF32(c_acc[mf][nf][0], c_acc[mf][nf][1], c_acc[mf][nf][2], c_acc[mf][nf][3],
                             ah[mf][0], ah[mf][1], ah[mf][2], ah[mf][3], bh0, bh1);
                    MMA_TF32(c_acc[mf][nf][0], c_acc[mf][nf][1], c_acc[mf][nf][2], c_acc[mf][nf][3],
                             ah[mf][0], ah[mf][1], ah[mf][2], ah[mf][3], bl0, bl1);
                    MMA_TF32(c_acc[mf][nf][0], c_acc[mf][nf][1], c_acc[mf][nf][2], c_acc[mf][nf][3],
                             al[mf][0], al[mf][1], al[mf][2], al[mf][3], bh0, bh1);
                }
            }
        }
    }
#undef K1A_PF
#pragma unroll
    for (int mf = 0; mf < 2; mf++) {
#pragma unroll
        for (int nf = 0; nf < 8; nf++) {
            int c = warp_n*64 + nf*8 + tcol*2;
            int r0 = m0 + warp_m*32 + mf*16 + group;
            *(float2*)&g_kv[(size_t)r0*496 + c]     = make_float2(c_acc[mf][nf][0], c_acc[mf][nf][1]);
            *(float2*)&g_kv[(size_t)(r0+8)*496 + c] = make_float2(c_acc[mf][nf][2], c_acc[mf][nf][3]);
        }
    }
}

// ---------------- K2: Q projection + fused score -> alpha (fp32, W pipelined) ----------------
__global__ __launch_bounds__(256, 2) void k2_qalpha(const float* __restrict__ hx,
                          const float* __restrict__ Wq)
{
    __shared__ __align__(16) float Xs[60*68];        // [d][m]
    __shared__ __align__(16) float Ws[2][12*260];    // [d][n]
    int tid = threadIdx.x;            // 256
    int tx = tid & 31, ty = tid >> 5;
    int m0 = blockIdx.x * 64;
    int k  = blockIdx.y;
    const float* Wk = Wq + (size_t)k*15360;

    for (int e = tid; e < 64*60; e += 256) {
        int m = e / 60, dd = e % 60;
        Xs[dd*68 + m] = hx[(size_t)(m0+m)*360 + k*60 + dd];
    }

#define K2_CPW(CH, S) do { \
    _Pragma("unroll") for (int i_ = 0; i_ < 3; i_++) { \
        int e_ = tid + i_*256; \
        int dd_ = e_ >> 6, c4_ = (e_ & 63)*4; \
        unsigned dst_ = (unsigned)__cvta_generic_to_shared(&Ws[S][dd_*260 + c4_]); \
        CP_ASYNC16(dst_, Wk + (size_t)((CH)*12 + dd_)*256 + c4_); \
    } } while(0)

    float acc[64];
#pragma unroll
    for (int i = 0; i < 64; i++) acc[i] = 0.f;

    K2_CPW(0, 0);
    CP_COMMIT();

    for (int ch = 0; ch < 5; ch++) {
        int cur = ch & 1;
        CP_WAIT0();
        __syncthreads();
        if (ch < 4) { K2_CPW(ch+1, cur^1); CP_COMMIT(); }
#pragma unroll
        for (int kk = 0; kk < 12; kk++) {
            float af[8], bf[8];
            LOAD_FRAG(af, &Xs[(ch*12 + kk)*68 + ty*8]);
            LOAD_FRAG(bf, &Ws[cur][kk*260 + tx*8]);
            FMA8x8(acc, af, bf);
        }
    }
#undef K2_CPW
    int h = tx >> 3, lane8 = tx & 7;
#pragma unroll
    for (int i = 0; i < 8; i++) {
        int gm = m0 + ty*8 + i;
        const float* kp = &g_kv[(size_t)gm*496 + h*64 + lane8*8];
        float s = 0.f;
#pragma unroll
        for (int j = 0; j < 8; j++) s += acc[i*8+j] * kp[j];
        s += __shfl_xor_sync(0xffffffffu, s, 1);
        s += __shfl_xor_sync(0xffffffffu, s, 2);
        s += __shfl_xor_sync(0xffffffffu, s, 4);
        if (lane8 == 0) g_alpha[(size_t)gm*24 + k*4 + h] = sigf(0.125f*s);
    }
}

// ---------------- K3: top-2 null mask ----------------
__global__ void k3_mask()
{
    int b = blockIdx.x*256 + threadIdx.x;
    float4 a0 = *(const float4*)&g_alpha[(size_t)b*24 + 0];
    float4 a1 = *(const float4*)&g_alpha[(size_t)b*24 + 4];
    float4 a2 = *(const float4*)&g_alpha[(size_t)b*24 + 8];
    float4 a3 = *(const float4*)&g_alpha[(size_t)b*24 + 12];
    float4 a4 = *(const float4*)&g_alpha[(size_t)b*24 + 16];
    float4 a5 = *(const float4*)&g_alpha[(size_t)b*24 + 20];
    float nul[6];
    nul[0] = 1.f - 0.25f*(a0.x+a0.y+a0.z+a0.w);
    nul[1] = 1.f - 0.25f*(a1.x+a1.y+a1.z+a1.w);
    nul[2] = 1.f - 0.25f*(a2.x+a2.y+a2.z+a2.w);
    nul[3] = 1.f - 0.25f*(a3.x+a3.y+a3.z+a3.w);
    nul[4] = 1.f - 0.25f*(a4.x+a4.y+a4.z+a4.w);
    nul[5] = 1.f - 0.25f*(a5.x+a5.y+a5.z+a5.w);
    int i1 = 0; float m1 = nul[0];
#pragma unroll
    for (int k = 1; k < 6; k++) if (nul[k] > m1) { m1 = nul[k]; i1 = k; }
    int i2 = -1; float m2 = -1e30f;
#pragma unroll
    for (int k = 0; k < 6; k++) if (k != i1 && nul[k] > m2) { m2 = nul[k]; i2 = k; }
#pragma unroll
    for (int k = 0; k < 6; k++)
        g_mask[(size_t)b*6 + k] = (k == i1 || k == i2) ? 0.f : 1.f;
}

// ---------------- K1b: Vproj  [B,768] @ [768,240]  (tf32 mma, pipelined) ----------------
__global__ __launch_bounds__(256, 1) void k1b_vproj(const float* __restrict__ inp,
                          const float* __restrict__ Wv1)
{
    __shared__ __align__(16) float As[2][64*20];
    __shared__ __align__(16) float Bs[2][16*264];
    int tid = threadIdx.x;
    int lane = tid & 31, warp = tid >> 5;
    int warp_m = warp >> 2, warp_n = warp & 3;
    int group = lane >> 2, tcol = lane & 3;
    int m0 = blockIdx.x * 64;

    for (int s = 0; s < 2; s++)
        for (int e = tid; e < 16*24; e += 256) {
            int dd = e / 24, c = 240 + e % 24;
            Bs[s][dd*264 + c] = 0.f;
        }

    float c_acc[2][8][4];
#pragma unroll
    for (int a = 0; a < 2; a++)
#pragma unroll
        for (int b = 0; b < 8; b++)
#pragma unroll
            for (int d = 0; d < 4; d++) c_acc[a][b][d] = 0.f;

#define K1B_PF(CH, S) do { \
    { int m_ = tid >> 2, seg_ = tid & 3; \
      unsigned dA_ = (unsigned)__cvta_generic_to_shared(&As[S][m_*20 + seg_*4]); \
      CP_ASYNC16(dA_, inp + (size_t)(m0+m_)*768 + (CH)*16 + seg_*4); } \
    _Pragma("unroll") \
    for (int i_ = 0; i_ < 4; i_++) { \
        int e_ = tid + i_*256; \
        if (e_ < 960) { \
            int dd_ = e_ / 60, c4_ = (e_ % 60)*4; \
            unsigned dB_ = (unsigned)__cvta_generic_to_shared(&Bs[S][dd_*264 + c4_]); \
            CP_ASYNC16(dB_, Wv1 + (size_t)((CH)*16 + dd_)*240 + c4_); \
        } \
    } } while(0)

    __syncthreads();
    K1B_PF(0, 0);
    CP_COMMIT();

    for (int ch = 0; ch < 48; ch++) {
        int cur = ch & 1;
        CP_WAIT0();
        __syncthreads();
        if (ch < 47) { K1B_PF(ch+1, cur^1); CP_COMMIT(); }
#pragma unroll
        for (int ks = 0; ks < 2; ks++) {
            int kb = ks*8;
            unsigned a_frag[2][4];
#pragma unroll
            for (int mf = 0; mf < 2; mf++) {
                int row0 = warp_m*32 + mf*16 + group;
                a_frag[mf][0] = __float_as_uint(As[cur][row0*20 + kb + tcol]);
                a_frag[mf][1] = __float_as_uint(As[cur][(row0+8)*20 + kb + tcol]);
                a_frag[mf][2] = __float_as_uint(As[cur][row0*20 + kb + tcol + 4]);
                a_frag[mf][3] = __float_as_uint(As[cur][(row0+8)*20 + kb + tcol + 4]);
            }
#pragma unroll
            for (int nf = 0; nf < 8; nf++) {
                int coln = warp_n*64 + nf*8 + group;
                unsigned b0 = __float_as_uint(Bs[cur][(kb + tcol)*264 + coln]);
                unsigned b1 = __float_as_uint(Bs[cur][(kb + tcol + 4)*264 + coln]);
#pragma unroll
                for (int mf = 0; mf < 2; mf++)
                    MMA_TF32(c_acc[mf][nf][0], c_acc[mf][nf][1], c_acc[mf][nf][2], c_acc[mf][nf][3],
                             a_frag[mf][0], a_frag[mf][1], a_frag[mf][2], a_frag[mf][3], b0, b1);
            }
        }
    }
#undef K1B_PF
#pragma unroll
    for (int mf = 0; mf < 2; mf++) {
#pragma unroll
        for (int nf = 0; nf < 8; nf++) {
            int c = warp_n*64 + nf*8 + tcol*2;
            if (c >= 240) continue;
            int r0 = m0 + warp_m*32 + mf*16 + group;
            g_kv[(size_t)r0*496 + 256 + c]     = c_acc[mf][nf][0];
            g_kv[(size_t)r0*496 + 256 + c + 1] = c_acc[mf][nf][1];
            g_kv[(size_t)(r0+8)*496 + 256 + c]     = c_acc[mf][nf][2];
            g_kv[(size_t)(r0+8)*496 + 256 + c + 1] = c_acc[mf][nf][3];
        }
    }
}

// ---------------- K4: pipelined tf32 mma gates GEMM + LSTM pointwise + cx_out ----------------
__global__ __launch_bounds__(256, 1) void k4_gates_lstm(const float* __restrict__ hx,
                              const float* __restrict__ cx,
                              const float* __restrict__ b_ih,
                              const float* __restrict__ b_hh,
                              float* __restrict__ out_cx)
{
    __shared__ __align__(16) float As[2][64*20];
    __shared__ __align__(16) float Bs[2][16*264];
    __shared__ float sbias[240];
    __shared__ float s_alpha5[320];   // [m][5], col 4 = 1.0 (hx region)
    int tid = threadIdx.x;
    int lane = tid & 31, warp = tid >> 5;
    int warp_m = warp >> 2, warp_n = warp & 3;
    int group = lane >> 2, tcol = lane & 3;
    int m0 = blockIdx.x * 64;
    int k  = blockIdx.y;

    if (tid < 240) {
        int c = tid, r = c >> 2, g = c & 3;
        int rowW = g*360 + k*60 + r;
        sbias[c] = b_ih[rowW] + b_hh[rowW];
    }
    for (int e = tid; e < 320; e += 256) {
        int m = e / 5, j = e % 5;
        s_alpha5[e] = (j < 4) ? g_alpha[(size_t)(m0+m)*24 + k*4 + j] : 1.f;
    }
    __syncthreads();

    const float* w4k = g_w4 + (size_t)k*(304*256);

#define PREFETCH_A(CH, S) do { \
    int m_ = tid >> 2, seg_ = tid & 3; \
    int d0_ = (CH)*16 + seg_*4; \
    unsigned dA_ = (unsigned)__cvta_generic_to_shared(&As[S][m_*20 + seg_*4]); \
    if (d0_ < 240)      { CP_ASYNC16(dA_, g_kv + (size_t)(m0+m_)*496 + 256 + d0_); } \
    else if (d0_ < 300) { CP_ASYNC16(dA_, hx + (size_t)(m0+m_)*360 + k*60 + (d0_-240)); } \
    else *(float4*)&As[S][m_*20 + seg_*4] = make_float4(0.f,0.f,0.f,0.f); \
    } while(0)

#define PREFETCH_B(CH, S) do { \
    const float* src_ = w4k + (CH)*16*256; \
    _Pragma("unroll") \
    for (int i_ = 0; i_ < 4; i_++) { \
        int e_ = tid + i_*256; \
        int dd_ = e_ >> 6, c4_ = (e_ & 63)*4; \
        unsigned dst_ = (unsigned)__cvta_generic_to_shared(&Bs[S][dd_*264 + c4_]); \
        CP_ASYNC16(dst_, src_ + dd_*256 + c4_); \
    } } while(0)

    float c_acc[2][8][4];
#pragma unroll
    for (int a = 0; a < 2; a++)
#pragma unroll
        for (int b = 0; b < 8; b++)
#pragma unroll
            for (int d = 0; d < 4; d++) c_acc[a][b][d] = 0.f;

    PREFETCH_B(0, 0);
    PREFETCH_A(0, 0);
    CP_COMMIT();

    int row0a = warp_m*32 + group;
    for (int ch = 0; ch < 19; ch++) {
        int cur = ch & 1;
        CP_WAIT0();
        __syncthreads();
        if (ch < 18) {
            PREFETCH_B(ch+1, cur^1);
            PREFETCH_A(ch+1, cur^1);
            CP_COMMIT();
        }
#pragma unroll
        for (int ks = 0; ks < 2; ks++) {
            int kb = ks*8;
            int dlo = ch*16 + kb + tcol;
            int dhi = dlo + 4;
            int hlo = dlo/60; if (hlo > 4) hlo = 4;
            int hhi = dhi/60; if (hhi > 4) hhi = 4;
            unsigned a_frag[2][4];
#pragma unroll
            for (int mf = 0; mf < 2; mf++) {
                int row0 = row0a + mf*16;
                float m0lo = s_alpha5[row0*5 + hlo];
                float m1lo = s_alpha5[(row0+8)*5 + hlo];
                float m0hi = s_alpha5[row0*5 + hhi];
                float m1hi = s_alpha5[(row0+8)*5 + hhi];
                a_frag[mf][0] = __float_as_uint(As[cur][row0*20 + kb + tcol] * m0lo);
                a_frag[mf][1] = __float_as_uint(As[cur][(row0+8)*20 + kb + tcol] * m1lo);
                a_frag[mf][2] = __float_as_uint(As[cur][row0*20 + kb + tcol + 4] * m0hi);
                a_frag[mf][3] = __float_as_uint(As[cur][(row0+8)*20 + kb + tcol + 4] * m1hi);
            }
#pragma unroll
            for (int nf = 0; nf < 8; nf++) {
                int coln = warp_n*64 + nf*8 + group;
                unsigned b0 = __float_as_uint(Bs[cur][(kb + tcol)*264 + coln]);
                unsigned b1 = __float_as_uint(Bs[cur][(kb + tcol + 4)*264 + coln]);
#pragma unroll
                for (int mf = 0; mf < 2; mf++)
                    MMA_TF32(c_acc[mf][nf][0], c_acc[mf][nf][1], c_acc[mf][nf][2], c_acc[mf][nf][3],
                             a_frag[mf][0], a_frag[mf][1], a_frag[mf][2], a_frag[mf][3], b0, b1);
            }
        }
    }
#undef PREFETCH_A
#undef PREFETCH_B
#pragma unroll
    for (int mf = 0; mf < 2; mf++) {
#pragma unroll
        for (int nf = 0; nf < 8; nf++) {
            float x0 = c_acc[mf][nf][0], x1 = c_acc[mf][nf][1];
            float x2 = c_acc[mf][nf][2], x3 = c_acc[mf][nf][3];
            float y0 = __shfl_xor_sync(0xffffffffu, x0, 1);
            float y1 = __shfl_xor_sync(0xffffffffu, x1, 1);
            float y2 = __shfl_xor_sync(0xffffffffu, x2, 1);
            float y3 = __shfl_xor_sync(0xffffffffu, x3, 1);
            int r = warp_n*16 + nf*2 + (tcol >> 1);
            if (r >= 60) continue;
            float gi, gf, gg, go; int rowloc;
            if ((tcol & 1) == 0) {
                gi = x0; gf = x1; gg = y0; go = y1;
                rowloc = warp_m*32 + mf*16 + group;
            } else {
                gi = y2; gf = y3; gg = x2; go = x3;
                rowloc = warp_m*32 + mf*16 + group + 8;
            }
            gi += sbias[r*4 + 0];
            gf += sbias[r*4 + 1];
            gg += sbias[r*4 + 2];
            go += sbias[r*4 + 3];
            int b = m0 + rowloc;
            float msk = g_mask[(size_t)b*6 + k];
            size_t idx = (size_t)b*360 + k*60 + r;
            float c_old = cx[idx];
            float cn = sigf(gf)*c_old + sigf(gi)*tanhf(gg);
            float hn = sigf(go)*tanhf(cn);
            g_hxn[idx] = hn;
            out_cx[idx] = msk*cn + (1.f - msk)*c_old;
        }
    }
}

// ---------------- K6: tf32 mma comm QKV  [B,64] @ [64,384] per block ----------------
__global__ __launch_bounds__(256, 1) void k6_commqkv()
{
    __shared__ __align__(16) float As[2][64*20];
    __shared__ __align__(16) float Bs[2][16*200];
    int tid = threadIdx.x;
    int lane = tid & 31, warp = tid >> 5;
    int warp_m = warp >> 2, warp_n = warp & 3;
    int group = lane >> 2, tcol = lane & 3;
    int m0 = blockIdx.x * 64;
    int kblk = blockIdx.y;
    int bz = blockIdx.z;
    const float* wck = g_wc + (size_t)kblk*(64*384) + bz*192;

#define K6_PFA(CH, S) do { \
    _Pragma("unroll") \
    for (int i_ = 0; i_ < 4; i_++) { \
        int e_ = tid + i_*256; \
        int m_ = e_ >> 4, dd_ = e_ & 15; \
        int d_ = (CH)*16 + dd_; \
        As[S][m_*20 + dd_] = (d_ < 60) ? g_hxn[(size_t)(m0+m_)*360 + kblk*60 + d_] : 0.f; \
    } } while(0)

#define K6_PFB(CH, S) do { \
    _Pragma("unroll") \
    for (int i_ = 0; i_ < 3; i_++) { \
        int e_ = tid + i_*256; \
        int dd_ = e_ / 48, c4_ = (e_ % 48)*4; \
        unsigned dst_ = (unsigned)__cvta_generic_to_shared(&Bs[S][dd_*200 + c4_]); \
        CP_ASYNC16(dst_, wck + (size_t)((CH)*16 + dd_)*384 + c4_); \
    } } while(0)

    float c_acc[2][6][4];
#pragma unroll
    for (int a = 0; a < 2; a++)
#pragma unroll
        for (int b = 0; b < 6; b++)
#pragma unroll
            for (int d = 0; d < 4; d++) c_acc[a][b][d] = 0.f;

    K6_PFB(0, 0);
    K6_PFA(0, 0);
    CP_COMMIT();

    for (int ch = 0; ch < 4; ch++) {
        int cur = ch & 1;
        CP_WAIT0();
        __syncthreads();
        if (ch < 3) { K6_PFB(ch+1, cur^1); K6_PFA(ch+1, cur^1); CP_COMMIT(); }
#pragma unroll
        for (int ks = 0; ks < 2; ks++) {
            int kb = ks*8;
            unsigned a_frag[2][4];
#pragma unroll
            for (int mf = 0; mf < 2; mf++) {
                int row0 = warp_m*32 + mf*16 + group;
                a_frag[mf][0] = __float_as_uint(As[cur][row0*20 + kb + tcol]);
                a_frag[mf][1] = __float_as_uint(As[cur][(row0+8)*20 + kb + tcol]);
                a_frag[mf][2] = __float_as_uint(As[cur][row0*20 + kb + tcol + 4]);
                a_frag[mf][3] = __float_as_uint(As[cur][(row0+8)*20 + kb + tcol + 4]);
            }
#pragma unroll
            for (int nf = 0; nf < 6; nf++) {
                int coln = warp_n*48 + nf*8 + group;
                unsigned b0 = __float_as_uint(Bs[cur][(kb + tcol)*200 + coln]);
                unsigned b1 = __float_as_uint(Bs[cur][(kb + tcol + 4)*200 + coln]);
#pragma unroll
                for (int mf = 0; mf < 2; mf++)
                    MMA_TF32(c_acc[mf][nf][0], c_acc[mf][nf][1], c_acc[mf][nf][2], c_acc[mf][nf][3],
                             a_frag[mf][0], a_frag[mf][1], a_frag[mf][2], a_frag[mf][3], b0, b1);
            }
        }
    }
#undef K6_PFA
#undef K6_PFB
#pragma unroll
    for (int mf = 0; mf < 2; mf++) {
#pragma unroll
        for (int nf = 0; nf < 6; nf++) {
            int c = warp_n*48 + nf*8 + tcol*2;
            int r0 = m0 + warp_m*32 + mf*16 + group;
            size_t base = (size_t)kblk*384 + bz*192 + c;
            *(float2*)&g_qkvc[(size_t)r0*2304 + base]     = make_float2(c_acc[mf][nf][0], c_acc[mf][nf][1]);
            *(float2*)&g_qkvc[(size_t)(r0+8)*2304 + base] = make_float2(c_acc[mf][nf][2], c_acc[mf][nf][3]);
        }
    }
}

// ---------------- K7: communication attention, v in registers ----------------
__global__ void k7_commattn()
{
    __shared__ float sqk[4][1536];   // [w][i*256 + {0:q(128),128:k(128)}]
    __shared__ float ss[4][144];
    int w = threadIdx.x >> 5, lane = threadIdx.x & 31;
    int b = blockIdx.x * 4 + w;
    const float* src = g_qkvc + (size_t)b*2304;

    for (int t = lane; t < 384; t += 32) {
        int i = t / 64, q4 = t % 64;
        *(float4*)&sqk[w][i*256 + q4*4] = *(const float4*)&src[i*384 + q4*4];
    }
    float v_reg[6][4];
#pragma unroll
    for (int j = 0; j < 6; j++)
#pragma unroll
        for (int h = 0; h < 4; h++)
            v_reg[j][h] = src[j*384 + 256 + h*32 + lane];
    __syncwarp();

    const float inv = 0.17677669529663687f;  // 1/sqrt(32)
    for (int p = lane; p < 144; p += 32) {
        int h = p / 36, rem = p % 36, i = rem / 6, j = rem % 6;
        const float* qv = &sqk[w][i*256 + h*32];
        const float* kv = &sqk[w][j*256 + 128 + h*32];
        float s = 0.f;
#pragma unroll
        for (int c = 0; c < 32; c++) s += qv[c]*kv[c];
        ss[w][p] = s * inv;
    }
    __syncwarp();
    if (lane < 24) {
        float* row = &ss[w][lane*6];
        float mx = row[0];
#pragma unroll
        for (int j = 1; j < 6; j++) mx = fmaxf(mx, row[j]);
        float ev[6]; float sum = 0.f;
#pragma unroll
        for (int j = 0; j < 6; j++) { ev[j] = expf(row[j]-mx); sum += ev[j]; }
        float is = 1.f/sum;
#pragma unroll
        for (int j = 0; j < 6; j++) row[j] = ev[j]*is;
    }
    __syncwarp();
#pragma unroll
    for (int i = 0; i < 6; i++) {
#pragma unroll
        for (int h = 0; h < 4; h++) {
            const float* att = &ss[w][h*36 + i*6];
            float acc = 0.f;
#pragma unroll
            for (int j = 0; j < 6; j++) acc += att[j]*v_reg[j][h];
            g_raw[(size_t)b*768 + i*128 + h*32 + lane] = acc;
        }
    }
}

// ---------------- K8: tf32 mma fc/gate GEMM + final hx_out ----------------
__global__ __launch_bounds__(256, 1) void k8_fcgate_out(const float* __restrict__ fc_b,
                              const float* __restrict__ gate_b,
                              const float* __restrict__ hx, float* __restrict__ out_hx)
{
    __shared__ __align__(16) float As[2][64*20];
    __shared__ __align__(16) float Bs[2][16*136];
    int tid = threadIdx.x;
    int lane = tid & 31, warp = tid >> 5;
    int warp_m = warp >> 2, warp_n = warp & 3;
    int group = lane >> 2, tcol = lane & 3;
    int m0 = blockIdx.x * 64;

#define K8_PFA(CH, S) do { \
    { int m_ = tid >> 2, seg_ = tid & 3; \
      unsigned dA_ = (unsigned)__cvta_generic_to_shared(&As[S][m_*20 + seg_*4]); \
      CP_ASYNC16(dA_, g_raw + (size_t)(m0+m_)*128 + (CH)*16 + seg_*4); } \
    } while(0)

#define K8_PFB(CH, S) do { \
    _Pragma("unroll") \
    for (int i_ = 0; i_ < 2; i_++) { \
        int e_ = tid + i_*256; \
        int dd_ = e_ >> 5, c4_ = (e_ & 31)*4; \
        unsigned dst_ = (unsigned)__cvta_generic_to_shared(&Bs[S][dd_*136 + c4_]); \
        CP_ASYNC16(dst_, g_w8 + (size_t)((CH)*16 + dd_)*128 + c4_); \
    } } while(0)

    float c_acc[2][4][4];
#pragma unroll
    for (int a = 0; a < 2; a++)
#pragma unroll
        for (int b = 0; b < 4; b++)
#pragma unroll
            for (int d = 0; d < 4; d++) c_acc[a][b][d] = 0.f;

    K8_PFB(0, 0);
    K8_PFA(0, 0);
    CP_COMMIT();

    for (int ch = 0; ch < 8; ch++) {
        int cur = ch & 1;
        CP_WAIT0();
        __syncthreads();
        if (ch < 7) { K8_PFB(ch+1, cur^1); K8_PFA(ch+1, cur^1); CP_COMMIT(); }
#pragma unroll
        for (int ks = 0; ks < 2; ks++) {
            int kb = ks*8;
            unsigned a_frag[2][4];
#pragma unroll
            for (int mf = 0; mf < 2; mf++) {
                int row0 = warp_m*32 + mf*16 + group;
                a_frag[mf][0] = __float_as_uint(As[cur][row0*20 + kb + tcol]);
                a_frag[mf][1] = __float_as_uint(As[cur][(row0+8)*20 + kb + tcol]);
                a_frag[mf][2] = __float_as_uint(As[cur][row0*20 + kb + tcol + 4]);
                a_frag[mf][3] = __float_as_uint(As[cur][(row0+8)*20 + kb + tcol + 4]);
            }
#pragma unroll
            for (int nf = 0; nf < 4; nf++) {
                int coln = warp_n*32 + nf*8 + group;
                unsigned b0 = __float_as_uint(Bs[cur][(kb + tcol)*136 + coln]);
                unsigned b1 = __float_as_uint(Bs[cur][(kb + tcol + 4)*136 + coln]);
#pragma unroll
                for (int mf = 0; mf < 2; mf++)
                    MMA_TF32(c_acc[mf][nf][0], c_acc[mf][nf][1], c_acc[mf][nf][2], c_acc[mf][nf][3],
                             a_frag[mf][0], a_frag[mf][1], a_frag[mf][2], a_frag[mf][3], b0, b1);
            }
        }
    }
#undef K8_PFA
#undef K8_PFB
#pragma unroll
    for (int mf = 0; mf < 2; mf++) {
#pragma unroll
        for (int nf = 0; nf < 4; nf++) {
            int c = warp_n*32 + nf*8 + tcol*2;
            int r = c >> 1;
            if (r >= 60) continue;
            float fb = fc_b[r], gb = gate_b[r];
#pragma unroll
            for (int half = 0; half < 2; half++) {
                int m = m0 + warp_m*32 + mf*16 + group + half*8;
                float fc = c_acc[mf][nf][half*2]     + fb;
                float gt = c_acc[mf][nf][half*2 + 1] + gb;
                float att = sigf(gt) * tanhf(fc);
                int b = m / 6, kb = m % 6;
                float msk = g_mask[m];
                size_t idx = (size_t)b*360 + kb*60 + r;
                float hn = g_hxn[idx];
                float ho = hx[idx];
                out_hx[idx] = msk*(hn + att) + (1.f - msk)*ho;
            }
        }
    }
}

// ---------------- launch ----------------
extern "C" void kernel_launch(void* const* d_in, const int* in_sizes, int n_in,
                              void* d_out, int out_size)
{
    const float* inp    = (const float*)d_in[0];
    const float* hx     = (const float*)d_in[1];
    const float* cx     = (const float*)d_in[2];
    const float* Wq_inp = (const float*)d_in[3];
    const float* Wk_inp = (const float*)d_in[4];
    const float* Wv_inp = (const float*)d_in[5];
    const float* Wq_c   = (const float*)d_in[6];
    const float* Wk_c   = (const float*)d_in[7];
    const float* Wv_c   = (const float*)d_in[8];
    const float* fc_w   = (const float*)d_in[9];
    const float* fc_b   = (const float*)d_in[10];
    const float* gate_w = (const float*)d_in[11];
    const float* gate_b = (const float*)d_in[12];
    const float* W_ih   = (const float*)d_in[13];
    const float* W_hh   = (const float*)d_in[14];
    const float* b_ih   = (const float*)d_in[15];
    const float* b_hh   = (const float*)d_in[16];

    float* out_hx = (float*)d_out;
    float* out_cx = (float*)d_out + (size_t)BATCH*360;

    prep_w4<<<1824, 256>>>(W_ih, W_hh);
    prep_wc<<<576, 256>>>(Wq_c, Wk_c, Wv_c);
    prep_w8<<<64, 256>>>(fc_w, gate_w);
    k1a_kproj<<<256, 256>>>(inp, Wk_inp + 768*256);
    k1b_vproj<<<256, 256>>>(inp, Wv_inp + 768*240);
    k2_qalpha<<<dim3(256, 6), 256>>>(hx, Wq_inp);
    k3_mask<<<64, 256>>>();
    k4_gates_lstm<<<dim3(256, 6), 256>>>(hx, cx, b_ih, b_hh, out_cx);
    k6_commqkv<<<dim3(256, 6, 2), 256>>>();
    k7_commattn<<<BATCH/4, 128>>>();
    k8_fcgate_out<<<1536, 256>>>(fc_b, gate_b, hx, out_hx);
}